// round 1
// baseline (speedup 1.0000x reference)
#include <cuda_runtime.h>
#include <cstddef>

#define BATCH 32
#define HEADS 8
#define NTOK 1024
#define DH 64
#define ML 256          // landmarks
#define CDIM 512
#define BHN (BATCH*HEADS)   // 256
#define KSZ 33

// ---------------- device scratch ----------------
__device__ float g_q [BHN*NTOK*DH];
__device__ float g_k [BHN*NTOK*DH];
__device__ float g_v [BHN*NTOK*DH];
__device__ float g_ql[BHN*ML*DH];
__device__ float g_kl[BHN*ML*DH];
__device__ float g_attn1[(size_t)BHN*NTOK*ML];   // (bh,1024,256)
__device__ float g_attn3[(size_t)BHN*ML*NTOK];   // (bh,256,1024)
__device__ float g_attn2[BHN*ML*ML];
__device__ float g_zA[BHN*ML*ML];
__device__ float g_zB[BHN*ML*ML];
__device__ float g_xz[BHN*ML*ML];
__device__ float g_t1[BHN*ML*ML];
__device__ float g_t2[BHN*ML*ML];
__device__ float g_av[BHN*ML*DH];
__device__ float g_bv[BHN*ML*DH];
__device__ float g_outf[(size_t)BATCH*NTOK*CDIM]; // (b, n, 512)
__device__ unsigned g_colmax;
__device__ unsigned g_rowmax;

// ---------------- QKV GEMM ----------------
// M=32768 (b*n), N=1536, K=512.  A(row,k) = x[(b*512+k)*1024 + i], B = w_qkv[512,1536]
// Writes q,k,v in (b,h,n,d) layout. q scaled by d^-0.5 = 0.125.
__global__ void qkv_gemm_kernel(const float* __restrict__ x, const float* __restrict__ w) {
    __shared__ float As[16][64];
    __shared__ float Bs[16][64];
    int tid = threadIdx.x;
    int row0 = blockIdx.y * 64;
    int col0 = blockIdx.x * 64;
    int b  = row0 >> 10;
    int i0 = row0 & 1023;
    int which = col0 >> 9;            // 0=q 1=k 2=v (tile never crosses)
    int h = (col0 & 511) >> 6;        // head (tile never crosses)
    float* dst = (which == 0) ? g_q : ((which == 1) ? g_k : g_v);
    float scale = (which == 0) ? 0.125f : 1.0f;
    int ty = tid >> 4, tx = tid & 15;
    float acc[4][4] = {};
    const float* xb = x + (size_t)b * CDIM * NTOK;
    for (int k0 = 0; k0 < CDIM; k0 += 16) {
        #pragma unroll
        for (int e = 0; e < 4; e++) {
            int idx = e * 256 + tid;
            int kk = idx >> 6, r = idx & 63;
            As[kk][r] = xb[(size_t)(k0 + kk) * NTOK + i0 + r];
            Bs[kk][r] = w[(size_t)(k0 + kk) * 1536 + col0 + r];
        }
        __syncthreads();
        #pragma unroll
        for (int kk = 0; kk < 16; kk++) {
            float a[4], bb[4];
            #pragma unroll
            for (int u = 0; u < 4; u++) { a[u] = As[kk][ty*4+u]; bb[u] = Bs[kk][tx*4+u]; }
            #pragma unroll
            for (int u = 0; u < 4; u++)
                #pragma unroll
                for (int v2 = 0; v2 < 4; v2++) acc[u][v2] += a[u] * bb[v2];
        }
        __syncthreads();
    }
    #pragma unroll
    for (int u = 0; u < 4; u++) {
        int i = i0 + ty*4 + u;
        float4 val = make_float4(acc[u][0]*scale, acc[u][1]*scale, acc[u][2]*scale, acc[u][3]*scale);
        float* p = dst + ((size_t)((b*HEADS + h)*NTOK + i)) * DH + tx*4;
        *reinterpret_cast<float4*>(p) = val;
    }
}

// ---------------- landmark means ----------------
__global__ void land_kernel() {
    int idx = blockIdx.x * blockDim.x + threadIdx.x;     // over BHN*ML*DH = 4.19M
    if (idx >= BHN*ML*DH) return;
    int d  = idx & 63;
    int j  = (idx >> 6) & 255;
    int bh = idx >> 14;
    size_t base = ((size_t)bh * NTOK + j*4) * DH + d;
    g_ql[idx] = 0.25f * (g_q[base] + g_q[base+64] + g_q[base+128] + g_q[base+192]);
    g_kl[idx] = 0.25f * (g_k[base] + g_k[base+64] + g_k[base+128] + g_k[base+192]);
}

// ---------------- Q @ K^T (both row-major [rows, 64]) ----------------
// C[bh][i][j] = sum_d A[bh][i][d] * B[bh][j][d].  grid (N/64, M/64, BHN)
__global__ void qkt_kernel(const float* __restrict__ A, const float* __restrict__ B,
                           float* __restrict__ C, int M, int N) {
    __shared__ float As[64][65];
    __shared__ float Bs[64][65];
    int bh = blockIdx.z;
    A += (size_t)bh * M * DH;
    B += (size_t)bh * N * DH;
    C += (size_t)bh * M * N;
    int i0 = blockIdx.y * 64, j0 = blockIdx.x * 64;
    int tid = threadIdx.x, ty = tid >> 4, tx = tid & 15;
    #pragma unroll
    for (int e = 0; e < 16; e++) {
        int idx = e * 256 + tid;
        int r = idx >> 6, kk = idx & 63;
        As[r][kk] = A[(size_t)(i0 + r) * DH + kk];
        Bs[r][kk] = B[(size_t)(j0 + r) * DH + kk];
    }
    __syncthreads();
    float acc[4][4] = {};
    #pragma unroll 16
    for (int kk = 0; kk < 64; kk++) {
        float a[4], bb[4];
        #pragma unroll
        for (int u = 0; u < 4; u++) { a[u] = As[ty*4+u][kk]; bb[u] = Bs[tx*4+u][kk]; }
        #pragma unroll
        for (int u = 0; u < 4; u++)
            #pragma unroll
            for (int v2 = 0; v2 < 4; v2++) acc[u][v2] += a[u] * bb[v2];
    }
    #pragma unroll
    for (int u = 0; u < 4; u++) {
        float4 val = make_float4(acc[u][0], acc[u][1], acc[u][2], acc[u][3]);
        *reinterpret_cast<float4*>(&C[(size_t)(i0 + ty*4 + u) * N + j0 + tx*4]) = val;
    }
}

// ---------------- row softmax ----------------
template<int W>
__global__ void softmax_kernel(float* __restrict__ data) {
    __shared__ float red[256];
    float* row = data + (size_t)blockIdx.x * W;
    int t = threadIdx.x;
    constexpr int PE = W / 256;
    float vals[PE];
    float mx = -1e30f;
    #pragma unroll
    for (int e = 0; e < PE; e++) { vals[e] = row[t + e*256]; mx = fmaxf(mx, vals[e]); }
    red[t] = mx; __syncthreads();
    #pragma unroll
    for (int s = 128; s > 0; s >>= 1) { if (t < s) red[t] = fmaxf(red[t], red[t+s]); __syncthreads(); }
    mx = red[0];
    __syncthreads();
    float sum = 0.f;
    #pragma unroll
    for (int e = 0; e < PE; e++) { vals[e] = expf(vals[e] - mx); sum += vals[e]; }
    red[t] = sum; __syncthreads();
    #pragma unroll
    for (int s = 128; s > 0; s >>= 1) { if (t < s) red[t] += red[t+s]; __syncthreads(); }
    float inv = 1.0f / red[0];
    #pragma unroll
    for (int e = 0; e < PE; e++) row[t + e*256] = vals[e] * inv;
}

// ---------------- pinv scale reductions ----------------
__global__ void reset_max_kernel() { if (threadIdx.x == 0) { g_colmax = 0u; g_rowmax = 0u; } }

__global__ void colmax_kernel() {   // one warp per (bh,i): row abs-sum, global max
    int gw = (blockIdx.x * blockDim.x + threadIdx.x) >> 5;
    int lane = threadIdx.x & 31;
    if (gw >= BHN * ML) return;
    const float* row = g_attn2 + (size_t)gw * ML;
    float s = 0.f;
    #pragma unroll
    for (int j = lane; j < ML; j += 32) s += fabsf(row[j]);
    #pragma unroll
    for (int o = 16; o > 0; o >>= 1) s += __shfl_down_sync(0xffffffffu, s, o);
    if (lane == 0) atomicMax(&g_colmax, __float_as_uint(s));
}

__global__ void rowmax_kernel() {   // one thread per (bh,j): column abs-sum, global max
    int idx = blockIdx.x * blockDim.x + threadIdx.x;
    if (idx >= BHN * ML) return;
    int bh = idx >> 8, j = idx & 255;
    const float* base = g_attn2 + (size_t)bh * ML * ML + j;
    float s = 0.f;
    for (int i = 0; i < ML; i++) s += fabsf(base[(size_t)i * ML]);
    atomicMax(&g_rowmax, __float_as_uint(s));
}

__global__ void zinit_kernel() {    // z = x^T / (colmax*rowmax)
    float inv = 1.0f / (__uint_as_float(g_colmax) * __uint_as_float(g_rowmax));
    size_t idx = (size_t)blockIdx.x * 256 + threadIdx.x;  // BHN*ML*ML
    int j  = idx & 255;
    int i  = (idx >> 8) & 255;
    size_t bh = idx >> 16;
    g_zA[idx] = g_attn2[(bh << 16) + ((size_t)j << 8) + i] * inv;
}

// ---------------- pinv batched GEMM: D = c1*U + c2*(A@B), 256x256 per batch ----------------
__global__ void pinv_gemm_kernel(const float* __restrict__ A, const float* __restrict__ B,
                                 const float* __restrict__ U, float* __restrict__ D,
                                 float c1, float c2) {
    __shared__ float As[64][17];
    __shared__ float Bs[16][64];
    size_t off = (size_t)blockIdx.z * ML * ML;
    A += off; B += off; D += off;
    if (U) U += off;
    int i0 = blockIdx.y * 64, j0 = blockIdx.x * 64;
    int tid = threadIdx.x, ty = tid >> 4, tx = tid & 15;
    float acc[4][4] = {};
    for (int k0 = 0; k0 < ML; k0 += 16) {
        #pragma unroll
        for (int e = 0; e < 4; e++) {
            int idx = e * 256 + tid;
            { int r = idx >> 4, kk = idx & 15; As[r][kk] = A[(size_t)(i0 + r) * ML + k0 + kk]; }
            { int kk = idx >> 6, cc = idx & 63; Bs[kk][cc] = B[(size_t)(k0 + kk) * ML + j0 + cc]; }
        }
        __syncthreads();
        #pragma unroll
        for (int kk = 0; kk < 16; kk++) {
            float a[4], bb[4];
            #pragma unroll
            for (int u = 0; u < 4; u++) { a[u] = As[ty*4+u][kk]; bb[u] = Bs[kk][tx*4+u]; }
            #pragma unroll
            for (int u = 0; u < 4; u++)
                #pragma unroll
                for (int v2 = 0; v2 < 4; v2++) acc[u][v2] += a[u] * bb[v2];
        }
        __syncthreads();
    }
    #pragma unroll
    for (int u = 0; u < 4; u++) {
        size_t o = (size_t)(i0 + ty*4 + u) * ML + j0 + tx*4;
        float4 uv = make_float4(0.f, 0.f, 0.f, 0.f);
        if (U) uv = *reinterpret_cast<const float4*>(&U[o]);
        float4 r;
        r.x = c1*uv.x + c2*acc[u][0];
        r.y = c1*uv.y + c2*acc[u][1];
        r.z = c1*uv.z + c2*acc[u][2];
        r.w = c1*uv.w + c2*acc[u][3];
        *reinterpret_cast<float4*>(&D[o]) = r;
    }
}

// ---------------- A[M,K] @ B[K,64] batched over bh ----------------
// store_flat=0: C[bh][M][64].  store_flat=1: g_outf[(b*1024+i)*512 + h*64 + d]
__global__ void ab_kernel(const float* __restrict__ A, const float* __restrict__ B,
                          float* __restrict__ C, int M, int K, int store_flat) {
    __shared__ float As[64][17];
    __shared__ float Bs[16][64];
    int bh = blockIdx.y;
    A += (size_t)bh * M * K;
    B += (size_t)bh * K * 64;
    int i0 = blockIdx.x * 64;
    int tid = threadIdx.x, ty = tid >> 4, tx = tid & 15;
    float acc[4][4] = {};
    for (int k0 = 0; k0 < K; k0 += 16) {
        #pragma unroll
        for (int e = 0; e < 4; e++) {
            int idx = e * 256 + tid;
            { int r = idx >> 4, kk = idx & 15; As[r][kk] = A[(size_t)(i0 + r) * K + k0 + kk]; }
            { int kk = idx >> 6, cc = idx & 63; Bs[kk][cc] = B[(size_t)(k0 + kk) * 64 + cc]; }
        }
        __syncthreads();
        #pragma unroll
        for (int kk = 0; kk < 16; kk++) {
            float a[4], bb[4];
            #pragma unroll
            for (int u = 0; u < 4; u++) { a[u] = As[ty*4+u][kk]; bb[u] = Bs[kk][tx*4+u]; }
            #pragma unroll
            for (int u = 0; u < 4; u++)
                #pragma unroll
                for (int v2 = 0; v2 < 4; v2++) acc[u][v2] += a[u] * bb[v2];
        }
        __syncthreads();
    }
    #pragma unroll
    for (int u = 0; u < 4; u++) {
        int i = i0 + ty*4 + u;
        float4 val = make_float4(acc[u][0], acc[u][1], acc[u][2], acc[u][3]);
        if (store_flat) {
            int b = bh >> 3, h = bh & 7;
            *reinterpret_cast<float4*>(&g_outf[((size_t)(b*NTOK + i)) * CDIM + h*64 + tx*4]) = val;
        } else {
            *reinterpret_cast<float4*>(&C[((size_t)bh * M + i) * 64 + tx*4]) = val;
        }
    }
}

// ---------------- depthwise 33-tap conv residual (adds into g_outf) ----------------
__global__ void res_add_kernel(const float* __restrict__ rk) {
    __shared__ float ker[KSZ];
    int blk = blockIdx.x;               // BHN * 256 blocks
    int bh = blk >> 8;
    int ichunk = blk & 255;
    int h = bh & 7, b = bh >> 3;
    if (threadIdx.x < KSZ) ker[threadIdx.x] = rk[h*KSZ + threadIdx.x];
    __syncthreads();
    int d = threadIdx.x & 63;
    int i = ichunk * 4 + (threadIdx.x >> 6);
    const float* vb = g_v + (size_t)bh * NTOK * DH;
    float s = 0.f;
    #pragma unroll
    for (int t = 0; t < KSZ; t++) {
        int ii = i + t - (KSZ/2);
        if (ii >= 0 && ii < NTOK) s += ker[t] * vb[(size_t)ii * DH + d];
    }
    g_outf[((size_t)(b*NTOK + i)) * CDIM + h*64 + d] += s;
}

// ---------------- final GEMM: out = outf @ w_out + b_out, transposed store ----------------
__global__ void final_gemm_kernel(const float* __restrict__ w, const float* __restrict__ bias,
                                  float* __restrict__ out) {
    __shared__ float As[64][17];
    __shared__ float Bs[16][64];
    __shared__ float Cs[64][65];
    int row0 = blockIdx.y * 64, col0 = blockIdx.x * 64;
    int b = row0 >> 10, i0 = row0 & 1023;
    int tid = threadIdx.x, ty = tid >> 4, tx = tid & 15;
    float acc[4][4] = {};
    for (int k0 = 0; k0 < CDIM; k0 += 16) {
        #pragma unroll
        for (int e = 0; e < 4; e++) {
            int idx = e * 256 + tid;
            { int r = idx >> 4, kk = idx & 15; As[r][kk] = g_outf[(size_t)(row0 + r) * CDIM + k0 + kk]; }
            { int kk = idx >> 6, cc = idx & 63; Bs[kk][cc] = w[(size_t)(k0 + kk) * CDIM + col0 + cc]; }
        }
        __syncthreads();
        #pragma unroll
        for (int kk = 0; kk < 16; kk++) {
            float a[4], bb[4];
            #pragma unroll
            for (int u = 0; u < 4; u++) { a[u] = As[ty*4+u][kk]; bb[u] = Bs[kk][tx*4+u]; }
            #pragma unroll
            for (int u = 0; u < 4; u++)
                #pragma unroll
                for (int v2 = 0; v2 < 4; v2++) acc[u][v2] += a[u] * bb[v2];
        }
        __syncthreads();
    }
    #pragma unroll
    for (int u = 0; u < 4; u++)
        #pragma unroll
        for (int v2 = 0; v2 < 4; v2++)
            Cs[ty*4+u][tx*4+v2] = acc[u][v2] + bias[col0 + tx*4 + v2];
    __syncthreads();
    #pragma unroll
    for (int e = 0; e < 16; e++) {
        int idx = e * 256 + tid;
        int c = idx >> 6, r = idx & 63;
        out[((size_t)(b*CDIM + col0 + c)) * NTOK + i0 + r] = Cs[r][c];
    }
}

// ---------------- host ----------------
extern "C" void kernel_launch(void* const* d_in, const int* in_sizes, int n_in,
                              void* d_out, int out_size) {
    const float* x     = (const float*)d_in[0];
    const float* w_qkv = (const float*)d_in[1];
    const float* w_out = (const float*)d_in[2];
    const float* b_out = (const float*)d_in[3];
    const float* rk    = (const float*)d_in[4];
    float* out = (float*)d_out;

    float *q, *k, *v, *ql, *kl, *a1, *a3, *a2, *zA, *zB, *xz, *t1, *t2, *av, *bv;
    cudaGetSymbolAddress((void**)&q,  g_q);
    cudaGetSymbolAddress((void**)&k,  g_k);
    cudaGetSymbolAddress((void**)&v,  g_v);
    cudaGetSymbolAddress((void**)&ql, g_ql);
    cudaGetSymbolAddress((void**)&kl, g_kl);
    cudaGetSymbolAddress((void**)&a1, g_attn1);
    cudaGetSymbolAddress((void**)&a3, g_attn3);
    cudaGetSymbolAddress((void**)&a2, g_attn2);
    cudaGetSymbolAddress((void**)&zA, g_zA);
    cudaGetSymbolAddress((void**)&zB, g_zB);
    cudaGetSymbolAddress((void**)&xz, g_xz);
    cudaGetSymbolAddress((void**)&t1, g_t1);
    cudaGetSymbolAddress((void**)&t2, g_t2);
    cudaGetSymbolAddress((void**)&av, g_av);
    cudaGetSymbolAddress((void**)&bv, g_bv);

    // 1) QKV projection, head split, q scaling
    qkv_gemm_kernel<<<dim3(24, 512), 256>>>(x, w_qkv);
    // 2) landmarks
    land_kernel<<<(BHN*ML*DH + 255)/256, 256>>>();
    // 3) similarity GEMMs
    qkt_kernel<<<dim3(ML/64,  NTOK/64, BHN), 256>>>(q,  kl, a1, NTOK, ML);   // sim1 (1024x256)
    qkt_kernel<<<dim3(ML/64,  ML/64,   BHN), 256>>>(ql, kl, a2, ML,   ML);   // sim2 (256x256)
    qkt_kernel<<<dim3(NTOK/64, ML/64,  BHN), 256>>>(ql, k,  a3, ML,   NTOK); // sim3 (256x1024)
    // 4) softmaxes
    softmax_kernel<256> <<<BHN*NTOK, 256>>>(a1);
    softmax_kernel<256> <<<BHN*ML,   256>>>(a2);
    softmax_kernel<1024><<<BHN*ML,   256>>>(a3);
    // 5) pinv init
    reset_max_kernel<<<1, 32>>>();
    colmax_kernel<<<(BHN*ML*32)/256, 256>>>();
    rowmax_kernel<<<(BHN*ML)/256, 256>>>();
    zinit_kernel<<<(BHN*ML*ML)/256, 256>>>();
    // 6) 6 Newton–Schulz iterations
    float* zin = zA; float* zout = zB;
    dim3 pg(ML/64, ML/64, BHN);
    for (int it = 0; it < 6; it++) {
        pinv_gemm_kernel<<<pg, 256>>>(a2,  zin, nullptr, xz,  0.0f,  1.0f);   // xz = x@z
        pinv_gemm_kernel<<<pg, 256>>>(xz,  xz,  xz,      t1,  7.0f, -1.0f);   // t1 = 7xz - xz@xz
        pinv_gemm_kernel<<<pg, 256>>>(xz,  t1,  xz,      t2, 15.0f, -1.0f);   // t2 = 15xz - xz@t1
        pinv_gemm_kernel<<<pg, 256>>>(zin, t2,  zin,     zout, 3.25f, -0.25f);// z = 3.25z - 0.25 z@t2
        float* tmp = zin; zin = zout; zout = tmp;
    }
    // 7) output chain: av = attn3@v ; bv = z@av ; outf = attn1@bv (flat layout)
    ab_kernel<<<dim3(ML/64,   BHN), 256>>>(a3,  v,  av, ML,   NTOK, 0);
    ab_kernel<<<dim3(ML/64,   BHN), 256>>>(zin, av, bv, ML,   ML,   0);
    ab_kernel<<<dim3(NTOK/64, BHN), 256>>>(a1,  bv, nullptr, NTOK, ML, 1);
    // 8) depthwise conv residual
    res_add_kernel<<<BHN*256, 256>>>(rk);
    // 9) output projection + transpose to (b, c, H, W)
    final_gemm_kernel<<<dim3(CDIM/64, (BATCH*NTOK)/64), 256>>>(w_out, b_out, out);
}

// round 4
// speedup vs baseline: 1.5771x; 1.5771x over previous
#include <cuda_runtime.h>
#include <cstdint>
#include <cstddef>

#define BATCH 32
#define HEADS 8
#define NTOK 1024
#define DH 64
#define ML 256          // landmarks
#define CDIM 512
#define BHN (BATCH*HEADS)   // 256
#define KSZ 33

// ---------------- device scratch ----------------
__device__ float g_q [BHN*NTOK*DH];
__device__ float g_k [BHN*NTOK*DH];
__device__ float g_v [BHN*NTOK*DH];
__device__ float g_ql[BHN*ML*DH];
__device__ float g_kl[BHN*ML*DH];
__device__ float g_attn1[(size_t)BHN*NTOK*ML];   // (bh,1024,256)
__device__ float g_attn3[(size_t)BHN*ML*NTOK];   // (bh,256,1024)
__device__ float g_attn2[BHN*ML*ML];
__device__ float g_zA[BHN*ML*ML];
__device__ float g_zB[BHN*ML*ML];
__device__ float g_zsA[BHN*ML*ML];   // transposed z
__device__ float g_zsB[BHN*ML*ML];
__device__ float g_xz[BHN*ML*ML];
__device__ float g_xzs[BHN*ML*ML];   // transposed xz
__device__ float g_t1[BHN*ML*ML];    // holds t1^T
__device__ float g_t2[BHN*ML*ML];
__device__ float g_t2s[BHN*ML*ML];   // transposed t2
__device__ float g_av[BHN*ML*DH];
__device__ float g_bv[BHN*ML*DH];
__device__ float g_outf[(size_t)BATCH*NTOK*CDIM]; // (b, n, 512)
__device__ unsigned g_colmax;
__device__ unsigned g_rowmax;

// ================= tf32 mma.sync helpers (valid on base compute_103) =================
__device__ __forceinline__ float cvt_tf32(float x) {
    uint32_t u;
    asm("cvt.rna.tf32.f32 %0, %1;" : "=r"(u) : "f"(x));
    return __uint_as_float(u);
}
__device__ __forceinline__ void mma_tf32_16x8x8(float c[4],
    uint32_t a0, uint32_t a1, uint32_t a2, uint32_t a3, uint32_t b0, uint32_t b1) {
    asm volatile(
        "mma.sync.aligned.m16n8k8.row.col.f32.tf32.tf32.f32 "
        "{%0,%1,%2,%3},{%4,%5,%6,%7},{%8,%9},{%0,%1,%2,%3};"
        : "+f"(c[0]), "+f"(c[1]), "+f"(c[2]), "+f"(c[3])
        : "r"(a0), "r"(a1), "r"(a2), "r"(a3), "r"(b0), "r"(b1));
}

// ================= pinv batched GEMM on tensor cores =================
// D[128,128] tile of: Cn = c1*U + c2*(P @ Q^T)  (per batch 256x256x256)
// P row-major [256,256], Q row-major (Q^T's K-major form), U row-major in Cn
// orientation. Ct (optional) = Cn^T stored directly.
#define PKC 32
#define PPITCH 36
#define PSTAGE (128*PPITCH)
#define PINV_SMEM_BYTES (4*PSTAGE*4)   // A(2 stages) + B(2 stages) = 73728

__global__ void __launch_bounds__(256, 1) pinv_mma_kernel(
    const float* __restrict__ P, const float* __restrict__ Q,
    const float* __restrict__ U, float* __restrict__ Cn, float* __restrict__ Ct,
    float c1, float c2)
{
    extern __shared__ float sm[];
    float* As = sm;                // [2][128][PPITCH]
    float* Bs = sm + 2*PSTAGE;     // [2][128][PPITCH]
    const int tid = threadIdx.x;
    const int wid = tid >> 5, lane = tid & 31;
    const int wm = wid >> 2, wn = wid & 3;      // warp grid 2x4
    const int gr = lane >> 2, gc = lane & 3;
    const int tile = blockIdx.x;                // 1024 tiles
    const int batch = tile >> 2;
    const int m0 = ((tile >> 1) & 1) << 7;
    const int n0 = (tile & 1) << 7;
    const size_t boff = (size_t)batch << 16;
    P += boff + (size_t)m0 * ML;
    Q += boff + (size_t)n0 * ML;
    if (U) U += boff;
    Cn += boff;
    if (Ct) Ct += boff;

    // per-thread gmem->smem mapping: 4 float4 per matrix per chunk
    int rrow[4], rc4[4];
    #pragma unroll
    for (int e = 0; e < 4; e++) {
        int f4 = e * 256 + tid;
        rrow[e] = f4 >> 3;
        rc4[e] = (f4 & 7) << 2;
    }

    float acc[4][4][4];
    #pragma unroll
    for (int mi = 0; mi < 4; mi++)
        #pragma unroll
        for (int ni = 0; ni < 4; ni++)
            #pragma unroll
            for (int e = 0; e < 4; e++) acc[mi][ni][e] = 0.f;

    float4 ra[4], rb[4];
    // prologue: chunk 0
    #pragma unroll
    for (int e = 0; e < 4; e++) {
        ra[e] = *reinterpret_cast<const float4*>(&P[(size_t)rrow[e] * ML + rc4[e]]);
        rb[e] = *reinterpret_cast<const float4*>(&Q[(size_t)rrow[e] * ML + rc4[e]]);
    }
    #pragma unroll
    for (int e = 0; e < 4; e++) {
        float* pa = &As[rrow[e]*PPITCH + rc4[e]];
        pa[0] = cvt_tf32(ra[e].x); pa[1] = cvt_tf32(ra[e].y);
        pa[2] = cvt_tf32(ra[e].z); pa[3] = cvt_tf32(ra[e].w);
        float* pb = &Bs[rrow[e]*PPITCH + rc4[e]];
        pb[0] = cvt_tf32(rb[e].x); pb[1] = cvt_tf32(rb[e].y);
        pb[2] = cvt_tf32(rb[e].z); pb[3] = cvt_tf32(rb[e].w);
    }
    __syncthreads();

    for (int c = 0; c < 8; c++) {
        const int st = c & 1;
        if (c < 7) {   // issue next chunk's global loads early (overlap with mma)
            const int k0 = (c + 1) * PKC;
            #pragma unroll
            for (int e = 0; e < 4; e++) {
                ra[e] = *reinterpret_cast<const float4*>(&P[(size_t)rrow[e] * ML + k0 + rc4[e]]);
                rb[e] = *reinterpret_cast<const float4*>(&Q[(size_t)rrow[e] * ML + k0 + rc4[e]]);
            }
        }
        const float* Ab = &As[st*PSTAGE];
        const float* Bb = &Bs[st*PSTAGE];
        #pragma unroll
        for (int ks = 0; ks < 4; ks++) {
            uint32_t af[4][4];
            #pragma unroll
            for (int mi = 0; mi < 4; mi++) {
                int base = (wm*64 + mi*16 + gr)*PPITCH + ks*8 + gc;
                af[mi][0] = __float_as_uint(Ab[base]);
                af[mi][1] = __float_as_uint(Ab[base + 8*PPITCH]);
                af[mi][2] = __float_as_uint(Ab[base + 4]);
                af[mi][3] = __float_as_uint(Ab[base + 8*PPITCH + 4]);
            }
            uint32_t bf[4][2];
            #pragma unroll
            for (int ni = 0; ni < 4; ni++) {
                int base = (wn*32 + ni*8 + gr)*PPITCH + ks*8 + gc;
                bf[ni][0] = __float_as_uint(Bb[base]);
                bf[ni][1] = __float_as_uint(Bb[base + 4]);
            }
            #pragma unroll
            for (int mi = 0; mi < 4; mi++)
                #pragma unroll
                for (int ni = 0; ni < 4; ni++)
                    mma_tf32_16x8x8(acc[mi][ni],
                        af[mi][0], af[mi][1], af[mi][2], af[mi][3],
                        bf[ni][0], bf[ni][1]);
        }
        if (c < 7) {
            const int nst = st ^ 1;
            #pragma unroll
            for (int e = 0; e < 4; e++) {
                float* pa = &As[nst*PSTAGE + rrow[e]*PPITCH + rc4[e]];
                pa[0] = cvt_tf32(ra[e].x); pa[1] = cvt_tf32(ra[e].y);
                pa[2] = cvt_tf32(ra[e].z); pa[3] = cvt_tf32(ra[e].w);
                float* pb = &Bs[nst*PSTAGE + rrow[e]*PPITCH + rc4[e]];
                pb[0] = cvt_tf32(rb[e].x); pb[1] = cvt_tf32(rb[e].y);
                pb[2] = cvt_tf32(rb[e].z); pb[3] = cvt_tf32(rb[e].w);
            }
        }
        __syncthreads();
    }

    // epilogue
    #pragma unroll
    for (int mi = 0; mi < 4; mi++) {
        #pragma unroll
        for (int ni = 0; ni < 4; ni++) {
            int lr = wm*64 + mi*16 + gr;
            int lc = wn*32 + ni*8 + gc*2;
            int grow = m0 + lr, gcol = n0 + lc;
            const float* a = acc[mi][ni];
            float d0, d1, d2, d3;
            if (U) {
                float2 u0 = *reinterpret_cast<const float2*>(&U[(size_t)grow * ML + gcol]);
                float2 u1 = *reinterpret_cast<const float2*>(&U[(size_t)(grow+8) * ML + gcol]);
                d0 = c1*u0.x + c2*a[0]; d1 = c1*u0.y + c2*a[1];
                d2 = c1*u1.x + c2*a[2]; d3 = c1*u1.y + c2*a[3];
            } else {
                d0 = c2*a[0]; d1 = c2*a[1]; d2 = c2*a[2]; d3 = c2*a[3];
            }
            *reinterpret_cast<float2*>(&Cn[(size_t)grow * ML + gcol]) = make_float2(d0, d1);
            *reinterpret_cast<float2*>(&Cn[(size_t)(grow+8) * ML + gcol]) = make_float2(d2, d3);
            if (Ct) {
                Ct[(size_t)gcol * ML + grow]       = d0;
                Ct[(size_t)(gcol+1) * ML + grow]   = d1;
                Ct[(size_t)gcol * ML + grow+8]     = d2;
                Ct[(size_t)(gcol+1) * ML + grow+8] = d3;
            }
        }
    }
}

// ---------------- QKV GEMM ----------------
__global__ void qkv_gemm_kernel(const float* __restrict__ x, const float* __restrict__ w) {
    __shared__ float As[16][64];
    __shared__ float Bs[16][64];
    int tid = threadIdx.x;
    int row0 = blockIdx.y * 64;
    int col0 = blockIdx.x * 64;
    int b  = row0 >> 10;
    int i0 = row0 & 1023;
    int which = col0 >> 9;
    int h = (col0 & 511) >> 6;
    float* dst = (which == 0) ? g_q : ((which == 1) ? g_k : g_v);
    float scale = (which == 0) ? 0.125f : 1.0f;
    int ty = tid >> 4, tx = tid & 15;
    float acc[4][4] = {};
    const float* xb = x + (size_t)b * CDIM * NTOK;
    for (int k0 = 0; k0 < CDIM; k0 += 16) {
        #pragma unroll
        for (int e = 0; e < 4; e++) {
            int idx = e * 256 + tid;
            int kk = idx >> 6, r = idx & 63;
            As[kk][r] = xb[(size_t)(k0 + kk) * NTOK + i0 + r];
            Bs[kk][r] = w[(size_t)(k0 + kk) * 1536 + col0 + r];
        }
        __syncthreads();
        #pragma unroll
        for (int kk = 0; kk < 16; kk++) {
            float a[4], bb[4];
            #pragma unroll
            for (int u = 0; u < 4; u++) { a[u] = As[kk][ty*4+u]; bb[u] = Bs[kk][tx*4+u]; }
            #pragma unroll
            for (int u = 0; u < 4; u++)
                #pragma unroll
                for (int v2 = 0; v2 < 4; v2++) acc[u][v2] += a[u] * bb[v2];
        }
        __syncthreads();
    }
    #pragma unroll
    for (int u = 0; u < 4; u++) {
        int i = i0 + ty*4 + u;
        float4 val = make_float4(acc[u][0]*scale, acc[u][1]*scale, acc[u][2]*scale, acc[u][3]*scale);
        float* p = dst + ((size_t)((b*HEADS + h)*NTOK + i)) * DH + tx*4;
        *reinterpret_cast<float4*>(p) = val;
    }
}

// ---------------- landmark means ----------------
__global__ void land_kernel() {
    int idx = blockIdx.x * blockDim.x + threadIdx.x;
    if (idx >= BHN*ML*DH) return;
    int d  = idx & 63;
    int j  = (idx >> 6) & 255;
    int bh = idx >> 14;
    size_t base = ((size_t)bh * NTOK + j*4) * DH + d;
    g_ql[idx] = 0.25f * (g_q[base] + g_q[base+64] + g_q[base+128] + g_q[base+192]);
    g_kl[idx] = 0.25f * (g_k[base] + g_k[base+64] + g_k[base+128] + g_k[base+192]);
}

// ---------------- Q @ K^T (vectorized smem layout) ----------------
__global__ void qkt_kernel(const float* __restrict__ A, const float* __restrict__ B,
                           float* __restrict__ C, int M, int N) {
    __shared__ float As[64][68];
    __shared__ float Bs[64][68];
    int bh = blockIdx.z;
    A += (size_t)bh * M * DH;
    B += (size_t)bh * N * DH;
    C += (size_t)bh * M * N;
    int i0 = blockIdx.y * 64, j0 = blockIdx.x * 64;
    int tid = threadIdx.x, ty = tid >> 4, tx = tid & 15;
    #pragma unroll
    for (int e = 0; e < 4; e++) {
        int f4 = e * 256 + tid;     // 1024 float4 per matrix
        int r = f4 >> 4;
        int c4 = (f4 & 15) << 2;
        float4 va = *reinterpret_cast<const float4*>(&A[(size_t)(i0 + r) * DH + c4]);
        As[c4+0][r] = va.x; As[c4+1][r] = va.y; As[c4+2][r] = va.z; As[c4+3][r] = va.w;
        float4 vb = *reinterpret_cast<const float4*>(&B[(size_t)(j0 + r) * DH + c4]);
        Bs[c4+0][r] = vb.x; Bs[c4+1][r] = vb.y; Bs[c4+2][r] = vb.z; Bs[c4+3][r] = vb.w;
    }
    __syncthreads();
    float acc[4][4] = {};
    #pragma unroll 16
    for (int kk = 0; kk < 64; kk++) {
        float4 a4 = *reinterpret_cast<const float4*>(&As[kk][ty*4]);
        float4 b4 = *reinterpret_cast<const float4*>(&Bs[kk][tx*4]);
        float a[4] = {a4.x, a4.y, a4.z, a4.w};
        float bb[4] = {b4.x, b4.y, b4.z, b4.w};
        #pragma unroll
        for (int u = 0; u < 4; u++)
            #pragma unroll
            for (int v2 = 0; v2 < 4; v2++) acc[u][v2] += a[u] * bb[v2];
    }
    #pragma unroll
    for (int u = 0; u < 4; u++) {
        float4 val = make_float4(acc[u][0], acc[u][1], acc[u][2], acc[u][3]);
        *reinterpret_cast<float4*>(&C[(size_t)(i0 + ty*4 + u) * N + j0 + tx*4]) = val;
    }
}

// ---------------- row softmax ----------------
template<int W>
__global__ void softmax_kernel(float* __restrict__ data) {
    __shared__ float red[256];
    float* row = data + (size_t)blockIdx.x * W;
    int t = threadIdx.x;
    constexpr int PE = W / 256;
    float vals[PE];
    float mx = -1e30f;
    #pragma unroll
    for (int e = 0; e < PE; e++) { vals[e] = row[t + e*256]; mx = fmaxf(mx, vals[e]); }
    red[t] = mx; __syncthreads();
    #pragma unroll
    for (int s = 128; s > 0; s >>= 1) { if (t < s) red[t] = fmaxf(red[t], red[t+s]); __syncthreads(); }
    mx = red[0];
    __syncthreads();
    float sum = 0.f;
    #pragma unroll
    for (int e = 0; e < PE; e++) { vals[e] = expf(vals[e] - mx); sum += vals[e]; }
    red[t] = sum; __syncthreads();
    #pragma unroll
    for (int s = 128; s > 0; s >>= 1) { if (t < s) red[t] += red[t+s]; __syncthreads(); }
    float inv = 1.0f / red[0];
    #pragma unroll
    for (int e = 0; e < PE; e++) row[t + e*256] = vals[e] * inv;
}

// ---------------- pinv scale reductions ----------------
__global__ void reset_max_kernel() { if (threadIdx.x == 0) { g_colmax = 0u; g_rowmax = 0u; } }

__global__ void colmax_kernel() {
    int gw = (blockIdx.x * blockDim.x + threadIdx.x) >> 5;
    int lane = threadIdx.x & 31;
    if (gw >= BHN * ML) return;
    const float* row = g_attn2 + (size_t)gw * ML;
    float s = 0.f;
    #pragma unroll
    for (int j = lane; j < ML; j += 32) s += fabsf(row[j]);
    #pragma unroll
    for (int o = 16; o > 0; o >>= 1) s += __shfl_down_sync(0xffffffffu, s, o);
    if (lane == 0) atomicMax(&g_colmax, __float_as_uint(s));
}

__global__ void rowmax_kernel() {
    int idx = blockIdx.x * blockDim.x + threadIdx.x;
    if (idx >= BHN * ML) return;
    int bh = idx >> 8, j = idx & 255;
    const float* base = g_attn2 + (size_t)bh * ML * ML + j;
    float s = 0.f;
    for (int i = 0; i < ML; i++) s += fabsf(base[(size_t)i * ML]);
    atomicMax(&g_rowmax, __float_as_uint(s));
}

__global__ void zinit_kernel() {    // z = x^T * inv ; zs = x * inv
    float inv = 1.0f / (__uint_as_float(g_colmax) * __uint_as_float(g_rowmax));
    size_t idx = (size_t)blockIdx.x * 256 + threadIdx.x;
    int j  = idx & 255;
    int i  = (idx >> 8) & 255;
    size_t bh = idx >> 16;
    g_zA[idx]  = g_attn2[(bh << 16) + ((size_t)j << 8) + i] * inv;
    g_zsA[idx] = g_attn2[idx] * inv;
}

// ---------------- A[M,K] @ B[K,64] batched over bh ----------------
__global__ void ab_kernel(const float* __restrict__ A, const float* __restrict__ B,
                          float* __restrict__ C, int M, int K, int store_flat) {
    __shared__ float As[64][17];
    __shared__ float Bs[16][64];
    int bh = blockIdx.y;
    A += (size_t)bh * M * K;
    B += (size_t)bh * K * 64;
    int i0 = blockIdx.x * 64;
    int tid = threadIdx.x, ty = tid >> 4, tx = tid & 15;
    float acc[4][4] = {};
    for (int k0 = 0; k0 < K; k0 += 16) {
        #pragma unroll
        for (int e = 0; e < 4; e++) {
            int idx = e * 256 + tid;
            { int r = idx >> 4, kk = idx & 15; As[r][kk] = A[(size_t)(i0 + r) * K + k0 + kk]; }
            { int kk = idx >> 6, cc = idx & 63; Bs[kk][cc] = B[(size_t)(k0 + kk) * 64 + cc]; }
        }
        __syncthreads();
        #pragma unroll
        for (int kk = 0; kk < 16; kk++) {
            float a[4], bb[4];
            #pragma unroll
            for (int u = 0; u < 4; u++) { a[u] = As[ty*4+u][kk]; bb[u] = Bs[kk][tx*4+u]; }
            #pragma unroll
            for (int u = 0; u < 4; u++)
                #pragma unroll
                for (int v2 = 0; v2 < 4; v2++) acc[u][v2] += a[u] * bb[v2];
        }
        __syncthreads();
    }
    #pragma unroll
    for (int u = 0; u < 4; u++) {
        int i = i0 + ty*4 + u;
        float4 val = make_float4(acc[u][0], acc[u][1], acc[u][2], acc[u][3]);
        if (store_flat) {
            int b = bh >> 3, h = bh & 7;
            *reinterpret_cast<float4*>(&g_outf[((size_t)(b*NTOK + i)) * CDIM + h*64 + tx*4]) = val;
        } else {
            *reinterpret_cast<float4*>(&C[((size_t)bh * M + i) * 64 + tx*4]) = val;
        }
    }
}

// ---------------- depthwise 33-tap conv residual ----------------
__global__ void res_add_kernel(const float* __restrict__ rk) {
    __shared__ float ker[KSZ];
    int blk = blockIdx.x;
    int bh = blk >> 8;
    int ichunk = blk & 255;
    int h = bh & 7, b = bh >> 3;
    if (threadIdx.x < KSZ) ker[threadIdx.x] = rk[h*KSZ + threadIdx.x];
    __syncthreads();
    int d = threadIdx.x & 63;
    int i = ichunk * 4 + (threadIdx.x >> 6);
    const float* vb = g_v + (size_t)bh * NTOK * DH;
    float s = 0.f;
    #pragma unroll
    for (int t = 0; t < KSZ; t++) {
        int ii = i + t - (KSZ/2);
        if (ii >= 0 && ii < NTOK) s += ker[t] * vb[(size_t)ii * DH + d];
    }
    g_outf[((size_t)(b*NTOK + i)) * CDIM + h*64 + d] += s;
}

// ---------------- final GEMM: out = outf @ w_out + b_out, transposed store ----------------
__global__ void final_gemm_kernel(const float* __restrict__ w, const float* __restrict__ bias,
                                  float* __restrict__ out) {
    __shared__ float As[64][17];
    __shared__ float Bs[16][64];
    __shared__ float Cs[64][65];
    int row0 = blockIdx.y * 64, col0 = blockIdx.x * 64;
    int b = row0 >> 10, i0 = row0 & 1023;
    int tid = threadIdx.x, ty = tid >> 4, tx = tid & 15;
    float acc[4][4] = {};
    for (int k0 = 0; k0 < CDIM; k0 += 16) {
        #pragma unroll
        for (int e = 0; e < 4; e++) {
            int idx = e * 256 + tid;
            { int r = idx >> 4, kk = idx & 15; As[r][kk] = g_outf[(size_t)(row0 + r) * CDIM + k0 + kk]; }
            { int kk = idx >> 6, cc = idx & 63; Bs[kk][cc] = w[(size_t)(k0 + kk) * CDIM + col0 + cc]; }
        }
        __syncthreads();
        #pragma unroll
        for (int kk = 0; kk < 16; kk++) {
            float a[4], bb[4];
            #pragma unroll
            for (int u = 0; u < 4; u++) { a[u] = As[ty*4+u][kk]; bb[u] = Bs[kk][tx*4+u]; }
            #pragma unroll
            for (int u = 0; u < 4; u++)
                #pragma unroll
                for (int v2 = 0; v2 < 4; v2++) acc[u][v2] += a[u] * bb[v2];
        }
        __syncthreads();
    }
    #pragma unroll
    for (int u = 0; u < 4; u++)
        #pragma unroll
        for (int v2 = 0; v2 < 4; v2++)
            Cs[ty*4+u][tx*4+v2] = acc[u][v2] + bias[col0 + tx*4 + v2];
    __syncthreads();
    #pragma unroll
    for (int e = 0; e < 16; e++) {
        int idx = e * 256 + tid;
        int c = idx >> 6, r = idx & 63;
        out[((size_t)(b*CDIM + col0 + c)) * NTOK + i0 + r] = Cs[r][c];
    }
}

// ---------------- host ----------------
extern "C" void kernel_launch(void* const* d_in, const int* in_sizes, int n_in,
                              void* d_out, int out_size) {
    const float* x     = (const float*)d_in[0];
    const float* w_qkv = (const float*)d_in[1];
    const float* w_out = (const float*)d_in[2];
    const float* b_out = (const float*)d_in[3];
    const float* rk    = (const float*)d_in[4];
    float* out = (float*)d_out;

    float *q, *k, *v, *ql, *kl, *a1, *a3, *a2;
    float *zA, *zB, *zsA, *zsB, *xz, *xzs, *t1, *t2, *t2s, *av, *bv;
    cudaGetSymbolAddress((void**)&q,  g_q);
    cudaGetSymbolAddress((void**)&k,  g_k);
    cudaGetSymbolAddress((void**)&v,  g_v);
    cudaGetSymbolAddress((void**)&ql, g_ql);
    cudaGetSymbolAddress((void**)&kl, g_kl);
    cudaGetSymbolAddress((void**)&a1, g_attn1);
    cudaGetSymbolAddress((void**)&a3, g_attn3);
    cudaGetSymbolAddress((void**)&a2, g_attn2);
    cudaGetSymbolAddress((void**)&zA, g_zA);
    cudaGetSymbolAddress((void**)&zB, g_zB);
    cudaGetSymbolAddress((void**)&zsA, g_zsA);
    cudaGetSymbolAddress((void**)&zsB, g_zsB);
    cudaGetSymbolAddress((void**)&xz, g_xz);
    cudaGetSymbolAddress((void**)&xzs, g_xzs);
    cudaGetSymbolAddress((void**)&t1, g_t1);
    cudaGetSymbolAddress((void**)&t2, g_t2);
    cudaGetSymbolAddress((void**)&t2s, g_t2s);
    cudaGetSymbolAddress((void**)&av, g_av);
    cudaGetSymbolAddress((void**)&bv, g_bv);

    cudaFuncSetAttribute(pinv_mma_kernel, cudaFuncAttributeMaxDynamicSharedMemorySize,
                         PINV_SMEM_BYTES);

    // 1) QKV projection
    qkv_gemm_kernel<<<dim3(24, 512), 256>>>(x, w_qkv);
    // 2) landmarks
    land_kernel<<<(BHN*ML*DH + 255)/256, 256>>>();
    // 3) similarity GEMMs
    qkt_kernel<<<dim3(ML/64,  NTOK/64, BHN), 256>>>(q,  kl, a1, NTOK, ML);   // sim1
    qkt_kernel<<<dim3(ML/64,  ML/64,   BHN), 256>>>(ql, kl, a2, ML,   ML);   // sim2
    qkt_kernel<<<dim3(NTOK/64, ML/64,  BHN), 256>>>(ql, k,  a3, ML,   NTOK); // sim3
    // 4) softmaxes
    softmax_kernel<256> <<<BHN*NTOK, 256>>>(a1);
    softmax_kernel<256> <<<BHN*ML,   256>>>(a2);
    softmax_kernel<1024><<<BHN*ML,   256>>>(a3);
    // 5) pinv init (z and z^T)
    reset_max_kernel<<<1, 32>>>();
    colmax_kernel<<<(BHN*ML*32)/256, 256>>>();
    rowmax_kernel<<<(BHN*ML)/256, 256>>>();
    zinit_kernel<<<(BHN*ML*ML)/256, 256>>>();
    // 6) 6 Newton–Schulz iterations on tf32 mma.sync tensor cores.
    //    Each GEMM computes P @ Q^T (both operands K-major). We keep row-major
    //    and transposed copies so every operand/epilogue term has the right
    //    orientation. U is always row-major in the OUTPUT's orientation.
    float *zin = zA, *zout = zB, *zsin = zsA, *zsout = zsB;
    for (int it = 0; it < 6; it++) {
        // xz = x @ z           : P=x(a2), Q=z^T(zs). dual-store xz, xzs
        pinv_mma_kernel<<<1024, 256, PINV_SMEM_BYTES>>>(a2, zsin, nullptr, xz, xzs, 0.0f, 1.0f);
        // t1^T = 7*xz^T - xz^T @ xz^T : P=xzs, Q=xz, U=xzs. store t1 (holds t1^T)
        pinv_mma_kernel<<<1024, 256, PINV_SMEM_BYTES>>>(xzs, xz, xzs, t1, nullptr, 7.0f, -1.0f);
        // t2 = 15*xz - xz @ t1 : P=xz, Q=t1^T(=t1 buffer), U=xz. dual-store
        pinv_mma_kernel<<<1024, 256, PINV_SMEM_BYTES>>>(xz, t1, xz, t2, t2s, 15.0f, -1.0f);
        // z' = 3.25*z - 0.25*z@t2 : P=z, Q=t2^T(t2s), U=z. dual-store
        pinv_mma_kernel<<<1024, 256, PINV_SMEM_BYTES>>>(zin, t2s, zin, zout, zsout, 3.25f, -0.25f);
        float* tmp;
        tmp = zin;  zin  = zout;  zout  = tmp;
        tmp = zsin; zsin = zsout; zsout = tmp;
    }
    // 7) output chain
    ab_kernel<<<dim3(ML/64,   BHN), 256>>>(a3,  v,  av, ML,   NTOK, 0);
    ab_kernel<<<dim3(ML/64,   BHN), 256>>>(zin, av, bv, ML,   ML,   0);
    ab_kernel<<<dim3(NTOK/64, BHN), 256>>>(a1,  bv, nullptr, NTOK, ML, 1);
    // 8) depthwise conv residual
    res_add_kernel<<<BHN*256, 256>>>(rk);
    // 9) output projection + transpose
    final_gemm_kernel<<<dim3(CDIM/64, (BATCH*NTOK)/64), 256>>>(w_out, b_out, out);
}

// round 5
// speedup vs baseline: 2.2506x; 1.4270x over previous
#include <cuda_runtime.h>
#include <cstdint>
#include <cstddef>

#define BATCH 32
#define HEADS 8
#define NTOK 1024
#define DH 64
#define ML 256          // landmarks
#define CDIM 512
#define BHN (BATCH*HEADS)   // 256
#define KSZ 33

// ---------------- device scratch ----------------
__device__ float g_xt[(size_t)BATCH*NTOK*CDIM];     // x transposed: (b, n, c)
__device__ float g_wqkvT[3*CDIM*CDIM];              // (1536, 512)
__device__ float g_woutT[CDIM*CDIM];                // (512, 512)
__device__ float g_q [BHN*NTOK*DH];
__device__ float g_k [BHN*NTOK*DH];
__device__ float g_v [BHN*NTOK*DH];
__device__ float g_vt[BHN*DH*NTOK];                 // v transposed per bh: (d, n)
__device__ float g_ql[BHN*ML*DH];
__device__ float g_kl[BHN*ML*DH];
__device__ float g_attn1[(size_t)BHN*NTOK*ML];      // (bh,1024,256)
__device__ float g_attn3[(size_t)BHN*ML*NTOK];      // (bh,256,1024)
__device__ float g_attn2[BHN*ML*ML];
__device__ float g_zA[BHN*ML*ML];
__device__ float g_zB[BHN*ML*ML];
__device__ float g_zsA[BHN*ML*ML];   // transposed z
__device__ float g_zsB[BHN*ML*ML];
__device__ float g_xz[BHN*ML*ML];
__device__ float g_xzs[BHN*ML*ML];   // transposed xz
__device__ float g_t1[BHN*ML*ML];    // holds t1^T
__device__ float g_t2[BHN*ML*ML];
__device__ float g_t2s[BHN*ML*ML];   // transposed t2
__device__ float g_av[BHN*ML*DH];
__device__ float g_avt[BHN*DH*ML];
__device__ float g_bv[BHN*ML*DH];
__device__ float g_bvt[BHN*DH*ML];
__device__ float g_outf[(size_t)BATCH*NTOK*CDIM];   // (b, n, 512)
__device__ unsigned g_colmax;
__device__ unsigned g_rowmax;

// ================= tf32 mma.sync helpers =================
__device__ __forceinline__ float cvt_tf32(float x) {
    uint32_t u;
    asm("cvt.rna.tf32.f32 %0, %1;" : "=r"(u) : "f"(x));
    return __uint_as_float(u);
}
__device__ __forceinline__ void mma_tf32_16x8x8(float c[4],
    uint32_t a0, uint32_t a1, uint32_t a2, uint32_t a3, uint32_t b0, uint32_t b1) {
    asm volatile(
        "mma.sync.aligned.m16n8k8.row.col.f32.tf32.tf32.f32 "
        "{%0,%1,%2,%3},{%4,%5,%6,%7},{%8,%9},{%0,%1,%2,%3};"
        : "+f"(c[0]), "+f"(c[1]), "+f"(c[2]), "+f"(c[3])
        : "r"(a0), "r"(a1), "r"(a2), "r"(a3), "r"(b0), "r"(b1));
}

#define PPITCH 36
#define PSTAGE (128*PPITCH)
#define G128_SMEM (4*PSTAGE*4)                    // 73728
#define B64STAGE (64*PPITCH)
#define G64_SMEM ((2*PSTAGE + 2*B64STAGE)*4)      // 55296

// ============ shared 128x128 tf32 mainloop (256 thr, warps 2x4, warp 64x32) ============
// A row-major [>=128 rows][lda], B row-major [>=128 rows][ldb]; computes A @ B^T for the
// 128x128 tile starting at the passed pointers. kch = K/32 chunks.
__device__ __forceinline__ void mainloop128x128(
    const float* __restrict__ A, const float* __restrict__ B,
    int lda, int ldb, int kch, float* sm, int tid, float acc[4][4][4])
{
    float* As = sm;
    float* Bs = sm + 2*PSTAGE;
    const int wid = tid >> 5, lane = tid & 31;
    const int gr = lane >> 2, gc = lane & 3;
    const int wm = wid >> 2, wn = wid & 3;
    int rrow[4], rc4[4];
    #pragma unroll
    for (int e = 0; e < 4; e++) {
        int f4 = e * 256 + tid;
        rrow[e] = f4 >> 3;
        rc4[e] = (f4 & 7) << 2;
    }
    float4 ra[4], rb[4];
    #pragma unroll
    for (int e = 0; e < 4; e++) {
        ra[e] = *reinterpret_cast<const float4*>(&A[(size_t)rrow[e] * lda + rc4[e]]);
        rb[e] = *reinterpret_cast<const float4*>(&B[(size_t)rrow[e] * ldb + rc4[e]]);
    }
    #pragma unroll
    for (int e = 0; e < 4; e++) {
        float* pa = &As[rrow[e]*PPITCH + rc4[e]];
        pa[0] = cvt_tf32(ra[e].x); pa[1] = cvt_tf32(ra[e].y);
        pa[2] = cvt_tf32(ra[e].z); pa[3] = cvt_tf32(ra[e].w);
        float* pb = &Bs[rrow[e]*PPITCH + rc4[e]];
        pb[0] = cvt_tf32(rb[e].x); pb[1] = cvt_tf32(rb[e].y);
        pb[2] = cvt_tf32(rb[e].z); pb[3] = cvt_tf32(rb[e].w);
    }
    __syncthreads();
    for (int c = 0; c < kch; c++) {
        const int st = c & 1;
        if (c < kch - 1) {
            const int k0 = (c + 1) * 32;
            #pragma unroll
            for (int e = 0; e < 4; e++) {
                ra[e] = *reinterpret_cast<const float4*>(&A[(size_t)rrow[e] * lda + k0 + rc4[e]]);
                rb[e] = *reinterpret_cast<const float4*>(&B[(size_t)rrow[e] * ldb + k0 + rc4[e]]);
            }
        }
        const float* Ab = &As[st*PSTAGE];
        const float* Bb = &Bs[st*PSTAGE];
        #pragma unroll
        for (int ks = 0; ks < 4; ks++) {
            uint32_t af[4][4];
            #pragma unroll
            for (int mi = 0; mi < 4; mi++) {
                int base = (wm*64 + mi*16 + gr)*PPITCH + ks*8 + gc;
                af[mi][0] = __float_as_uint(Ab[base]);
                af[mi][1] = __float_as_uint(Ab[base + 8*PPITCH]);
                af[mi][2] = __float_as_uint(Ab[base + 4]);
                af[mi][3] = __float_as_uint(Ab[base + 8*PPITCH + 4]);
            }
            uint32_t bf[4][2];
            #pragma unroll
            for (int ni = 0; ni < 4; ni++) {
                int base = (wn*32 + ni*8 + gr)*PPITCH + ks*8 + gc;
                bf[ni][0] = __float_as_uint(Bb[base]);
                bf[ni][1] = __float_as_uint(Bb[base + 4]);
            }
            #pragma unroll
            for (int mi = 0; mi < 4; mi++)
                #pragma unroll
                for (int ni = 0; ni < 4; ni++)
                    mma_tf32_16x8x8(acc[mi][ni],
                        af[mi][0], af[mi][1], af[mi][2], af[mi][3],
                        bf[ni][0], bf[ni][1]);
        }
        if (c < kch - 1) {
            const int nst = st ^ 1;
            #pragma unroll
            for (int e = 0; e < 4; e++) {
                float* pa = &As[nst*PSTAGE + rrow[e]*PPITCH + rc4[e]];
                pa[0] = cvt_tf32(ra[e].x); pa[1] = cvt_tf32(ra[e].y);
                pa[2] = cvt_tf32(ra[e].z); pa[3] = cvt_tf32(ra[e].w);
                float* pb = &Bs[nst*PSTAGE + rrow[e]*PPITCH + rc4[e]];
                pb[0] = cvt_tf32(rb[e].x); pb[1] = cvt_tf32(rb[e].y);
                pb[2] = cvt_tf32(rb[e].z); pb[3] = cvt_tf32(rb[e].w);
            }
        }
        __syncthreads();
    }
}

// ============ plain batched GEMM: C[z] = A[z] @ B[z]^T (128x128 tiles) ============
__global__ void __launch_bounds__(256, 1) gemm_tc_kernel(
    const float* __restrict__ A, const float* __restrict__ B, float* __restrict__ C,
    int lda, int ldb, int ldc, int kch,
    size_t sA, size_t sB, size_t sC)
{
    extern __shared__ float sm[];
    const int tid = threadIdx.x;
    const int z = blockIdx.z;
    const int m0 = blockIdx.y * 128, n0 = blockIdx.x * 128;
    A += (size_t)z * sA + (size_t)m0 * lda;
    B += (size_t)z * sB + (size_t)n0 * ldb;
    C += (size_t)z * sC;
    float acc[4][4][4];
    #pragma unroll
    for (int mi = 0; mi < 4; mi++)
        #pragma unroll
        for (int ni = 0; ni < 4; ni++)
            #pragma unroll
            for (int e = 0; e < 4; e++) acc[mi][ni][e] = 0.f;
    mainloop128x128(A, B, lda, ldb, kch, sm, tid, acc);
    const int wid = tid >> 5, lane = tid & 31;
    const int gr = lane >> 2, gc = lane & 3;
    const int wm = wid >> 2, wn = wid & 3;
    #pragma unroll
    for (int mi = 0; mi < 4; mi++) {
        #pragma unroll
        for (int ni = 0; ni < 4; ni++) {
            int lr = m0 + wm*64 + mi*16 + gr;
            int lc = n0 + wn*32 + ni*8 + gc*2;
            const float* a = acc[mi][ni];
            *reinterpret_cast<float2*>(&C[(size_t)lr * ldc + lc]) = make_float2(a[0], a[1]);
            *reinterpret_cast<float2*>(&C[(size_t)(lr+8) * ldc + lc]) = make_float2(a[2], a[3]);
        }
    }
}

// ============ QKV GEMM with scatter epilogue ============
__global__ void __launch_bounds__(256, 1) qkv_tc_kernel(void) {
    extern __shared__ float sm[];
    const int tid = threadIdx.x;
    const int m0 = blockIdx.y * 128;        // over 32768 (b*1024+i)
    const int n0 = blockIdx.x * 128;        // over 1536
    const float* A = g_xt + (size_t)m0 * CDIM;
    const float* B = g_wqkvT + (size_t)n0 * CDIM;
    float acc[4][4][4];
    #pragma unroll
    for (int mi = 0; mi < 4; mi++)
        #pragma unroll
        for (int ni = 0; ni < 4; ni++)
            #pragma unroll
            for (int e = 0; e < 4; e++) acc[mi][ni][e] = 0.f;
    mainloop128x128(A, B, CDIM, CDIM, CDIM/32, sm, tid, acc);
    const int wid = tid >> 5, lane = tid & 31;
    const int gr = lane >> 2, gc = lane & 3;
    const int wm = wid >> 2, wn = wid & 3;
    #pragma unroll
    for (int mi = 0; mi < 4; mi++) {
        int m = m0 + wm*64 + mi*16 + gr;
        int b = m >> 10, i = m & 1023;
        #pragma unroll
        for (int ni = 0; ni < 4; ni++) {
            int n = n0 + wn*32 + ni*8 + gc*2;
            int which = n >> 9;
            int h = (n >> 6) & 7;
            int d = n & 63;
            int bh = b*8 + h;
            float* dst = (which == 0) ? g_q : ((which == 1) ? g_k : g_v);
            float sc = (which == 0) ? 0.125f : 1.0f;
            const float* a = acc[mi][ni];
            *reinterpret_cast<float2*>(&dst[((size_t)(bh*NTOK + i))*DH + d]) =
                make_float2(a[0]*sc, a[1]*sc);
            *reinterpret_cast<float2*>(&dst[((size_t)(bh*NTOK + i + 8))*DH + d]) =
                make_float2(a[2]*sc, a[3]*sc);
            if (which == 2) {
                g_vt[((size_t)(bh*DH + d))*NTOK + i]       = a[0];
                g_vt[((size_t)(bh*DH + d + 1))*NTOK + i]   = a[1];
                g_vt[((size_t)(bh*DH + d))*NTOK + i + 8]   = a[2];
                g_vt[((size_t)(bh*DH + d + 1))*NTOK + i + 8] = a[3];
            }
        }
    }
}

// ============ final GEMM: out = outf @ woutT^T + bias, transposed store ============
__global__ void __launch_bounds__(256, 1) final_tc_kernel(
    const float* __restrict__ bias, float* __restrict__ out)
{
    extern __shared__ float sm[];
    const int tid = threadIdx.x;
    const int m0 = blockIdx.y * 128;        // over 32768
    const int n0 = blockIdx.x * 128;        // over 512
    const float* A = g_outf + (size_t)m0 * CDIM;
    const float* B = g_woutT + (size_t)n0 * CDIM;
    float acc[4][4][4];
    #pragma unroll
    for (int mi = 0; mi < 4; mi++)
        #pragma unroll
        for (int ni = 0; ni < 4; ni++)
            #pragma unroll
            for (int e = 0; e < 4; e++) acc[mi][ni][e] = 0.f;
    mainloop128x128(A, B, CDIM, CDIM, CDIM/32, sm, tid, acc);
    const int wid = tid >> 5, lane = tid & 31;
    const int gr = lane >> 2, gc = lane & 3;
    const int wm = wid >> 2, wn = wid & 3;
    #pragma unroll
    for (int mi = 0; mi < 4; mi++) {
        int m = m0 + wm*64 + mi*16 + gr;
        int b = m >> 10, i = m & 1023;
        #pragma unroll
        for (int ni = 0; ni < 4; ni++) {
            int n = n0 + wn*32 + ni*8 + gc*2;
            const float* a = acc[mi][ni];
            float b0 = bias[n], b1 = bias[n+1];
            out[((size_t)(b*CDIM + n))*NTOK + i]       = a[0] + b0;
            out[((size_t)(b*CDIM + n + 1))*NTOK + i]   = a[1] + b1;
            out[((size_t)(b*CDIM + n))*NTOK + i + 8]   = a[2] + b0;
            out[((size_t)(b*CDIM + n + 1))*NTOK + i + 8] = a[3] + b1;
        }
    }
}

// ============ 128x64 batched GEMM (N=64): C = A @ B^T, optional C^T output ============
// warps 4x2 (warp tile 32x32), 256 threads.
__global__ void __launch_bounds__(256, 1) gemm64_tc_kernel(
    const float* __restrict__ A, const float* __restrict__ B,
    float* __restrict__ C, float* __restrict__ Ct,
    int lda, int ldb, int ldc, int ldct, int kch,
    size_t sA, size_t sB, size_t sC, size_t sCt, int flatC)
{
    extern __shared__ float sm[];
    float* As = sm;                    // 2 x 128 x 36
    float* Bs = sm + 2*PSTAGE;         // 2 x 64 x 36
    const int tid = threadIdx.x;
    const int wid = tid >> 5, lane = tid & 31;
    const int gr = lane >> 2, gc = lane & 3;
    const int wm = wid >> 1, wn = wid & 1;
    const int z = blockIdx.z;
    const int m0 = blockIdx.x * 128;
    A += (size_t)z * sA + (size_t)m0 * lda;
    B += (size_t)z * sB;
    if (flatC) C += (size_t)(z >> 3) * (NTOK*CDIM) + (size_t)(z & 7) * DH;
    else       C += (size_t)z * sC;
    if (Ct) Ct += (size_t)z * sCt;

    int arow[4], ac4[4], brow[2], bc4[2];
    #pragma unroll
    for (int e = 0; e < 4; e++) {
        int f4 = e * 256 + tid;
        arow[e] = f4 >> 3; ac4[e] = (f4 & 7) << 2;
    }
    #pragma unroll
    for (int e = 0; e < 2; e++) {
        int f4 = e * 256 + tid;
        brow[e] = f4 >> 3; bc4[e] = (f4 & 7) << 2;
    }

    float acc[2][4][4];
    #pragma unroll
    for (int mi = 0; mi < 2; mi++)
        #pragma unroll
        for (int ni = 0; ni < 4; ni++)
            #pragma unroll
            for (int e = 0; e < 4; e++) acc[mi][ni][e] = 0.f;

    float4 ra[4], rb[2];
    #pragma unroll
    for (int e = 0; e < 4; e++)
        ra[e] = *reinterpret_cast<const float4*>(&A[(size_t)arow[e] * lda + ac4[e]]);
    #pragma unroll
    for (int e = 0; e < 2; e++)
        rb[e] = *reinterpret_cast<const float4*>(&B[(size_t)brow[e] * ldb + bc4[e]]);
    #pragma unroll
    for (int e = 0; e < 4; e++) {
        float* pa = &As[arow[e]*PPITCH + ac4[e]];
        pa[0] = cvt_tf32(ra[e].x); pa[1] = cvt_tf32(ra[e].y);
        pa[2] = cvt_tf32(ra[e].z); pa[3] = cvt_tf32(ra[e].w);
    }
    #pragma unroll
    for (int e = 0; e < 2; e++) {
        float* pb = &Bs[brow[e]*PPITCH + bc4[e]];
        pb[0] = cvt_tf32(rb[e].x); pb[1] = cvt_tf32(rb[e].y);
        pb[2] = cvt_tf32(rb[e].z); pb[3] = cvt_tf32(rb[e].w);
    }
    __syncthreads();

    for (int c = 0; c < kch; c++) {
        const int st = c & 1;
        if (c < kch - 1) {
            const int k0 = (c + 1) * 32;
            #pragma unroll
            for (int e = 0; e < 4; e++)
                ra[e] = *reinterpret_cast<const float4*>(&A[(size_t)arow[e] * lda + k0 + ac4[e]]);
            #pragma unroll
            for (int e = 0; e < 2; e++)
                rb[e] = *reinterpret_cast<const float4*>(&B[(size_t)brow[e] * ldb + k0 + bc4[e]]);
        }
        const float* Ab = &As[st*PSTAGE];
        const float* Bb = &Bs[st*B64STAGE];
        #pragma unroll
        for (int ks = 0; ks < 4; ks++) {
            uint32_t af[2][4];
            #pragma unroll
            for (int mi = 0; mi < 2; mi++) {
                int base = (wm*32 + mi*16 + gr)*PPITCH + ks*8 + gc;
                af[mi][0] = __float_as_uint(Ab[base]);
                af[mi][1] = __float_as_uint(Ab[base + 8*PPITCH]);
                af[mi][2] = __float_as_uint(Ab[base + 4]);
                af[mi][3] = __float_as_uint(Ab[base + 8*PPITCH + 4]);
            }
            uint32_t bf[4][2];
            #pragma unroll
            for (int ni = 0; ni < 4; ni++) {
                int base = (wn*32 + ni*8 + gr)*PPITCH + ks*8 + gc;
                bf[ni][0] = __float_as_uint(Bb[base]);
                bf[ni][1] = __float_as_uint(Bb[base + 4]);
            }
            #pragma unroll
            for (int mi = 0; mi < 2; mi++)
                #pragma unroll
                for (int ni = 0; ni < 4; ni++)
                    mma_tf32_16x8x8(acc[mi][ni],
                        af[mi][0], af[mi][1], af[mi][2], af[mi][3],
                        bf[ni][0], bf[ni][1]);
        }
        if (c < kch - 1) {
            const int nst = st ^ 1;
            #pragma unroll
            for (int e = 0; e < 4; e++) {
                float* pa = &As[nst*PSTAGE + arow[e]*PPITCH + ac4[e]];
                pa[0] = cvt_tf32(ra[e].x); pa[1] = cvt_tf32(ra[e].y);
                pa[2] = cvt_tf32(ra[e].z); pa[3] = cvt_tf32(ra[e].w);
            }
            #pragma unroll
            for (int e = 0; e < 2; e++) {
                float* pb = &Bs[nst*B64STAGE + brow[e]*PPITCH + bc4[e]];
                pb[0] = cvt_tf32(rb[e].x); pb[1] = cvt_tf32(rb[e].y);
                pb[2] = cvt_tf32(rb[e].z); pb[3] = cvt_tf32(rb[e].w);
            }
        }
        __syncthreads();
    }

    #pragma unroll
    for (int mi = 0; mi < 2; mi++) {
        #pragma unroll
        for (int ni = 0; ni < 4; ni++) {
            int lr = m0 + wm*32 + mi*16 + gr;
            int lc = wn*32 + ni*8 + gc*2;
            const float* a = acc[mi][ni];
            *reinterpret_cast<float2*>(&C[(size_t)lr * ldc + lc]) = make_float2(a[0], a[1]);
            *reinterpret_cast<float2*>(&C[(size_t)(lr+8) * ldc + lc]) = make_float2(a[2], a[3]);
            if (Ct) {
                Ct[(size_t)lc * ldct + lr]       = a[0];
                Ct[(size_t)(lc+1) * ldct + lr]   = a[1];
                Ct[(size_t)lc * ldct + lr + 8]   = a[2];
                Ct[(size_t)(lc+1) * ldct + lr + 8] = a[3];
            }
        }
    }
}

// ---------------- batched 2D transpose: in[z][R][C] -> out[z][C][R] ----------------
__global__ void transpose_kernel(const float* __restrict__ in, float* __restrict__ out,
                                 int R, int C) {
    __shared__ float tile[32][33];
    const int z = blockIdx.z;
    in  += (size_t)z * R * C;
    out += (size_t)z * R * C;
    int c0 = blockIdx.x * 32, r0 = blockIdx.y * 32;
    int tx = threadIdx.x, ty = threadIdx.y;
    #pragma unroll
    for (int j = 0; j < 4; j++)
        tile[ty + j*8][tx] = in[(size_t)(r0 + ty + j*8) * C + c0 + tx];
    __syncthreads();
    #pragma unroll
    for (int j = 0; j < 4; j++)
        out[(size_t)(c0 + ty + j*8) * R + r0 + tx] = tile[tx][ty + j*8];
}

// ================= pinv batched GEMM (unchanged from round 4 — verified) =================
#define PINV_SMEM_BYTES G128_SMEM
__global__ void __launch_bounds__(256, 1) pinv_mma_kernel(
    const float* __restrict__ P, const float* __restrict__ Q,
    const float* __restrict__ U, float* __restrict__ Cn, float* __restrict__ Ct,
    float c1, float c2)
{
    extern __shared__ float sm[];
    const int tid = threadIdx.x;
    const int wid = tid >> 5, lane = tid & 31;
    const int wm = wid >> 2, wn = wid & 3;
    const int gr = lane >> 2, gc = lane & 3;
    const int tile = blockIdx.x;
    const int batch = tile >> 2;
    const int m0 = ((tile >> 1) & 1) << 7;
    const int n0 = (tile & 1) << 7;
    const size_t boff = (size_t)batch << 16;
    P += boff + (size_t)m0 * ML;
    Q += boff + (size_t)n0 * ML;
    if (U) U += boff;
    Cn += boff;
    if (Ct) Ct += boff;

    float acc[4][4][4];
    #pragma unroll
    for (int mi = 0; mi < 4; mi++)
        #pragma unroll
        for (int ni = 0; ni < 4; ni++)
            #pragma unroll
            for (int e = 0; e < 4; e++) acc[mi][ni][e] = 0.f;
    mainloop128x128(P, Q, ML, ML, 8, sm, tid, acc);

    #pragma unroll
    for (int mi = 0; mi < 4; mi++) {
        #pragma unroll
        for (int ni = 0; ni < 4; ni++) {
            int lr = wm*64 + mi*16 + gr;
            int lc = wn*32 + ni*8 + gc*2;
            int grow = m0 + lr, gcol = n0 + lc;
            const float* a = acc[mi][ni];
            float d0, d1, d2, d3;
            if (U) {
                float2 u0 = *reinterpret_cast<const float2*>(&U[(size_t)grow * ML + gcol]);
                float2 u1 = *reinterpret_cast<const float2*>(&U[(size_t)(grow+8) * ML + gcol]);
                d0 = c1*u0.x + c2*a[0]; d1 = c1*u0.y + c2*a[1];
                d2 = c1*u1.x + c2*a[2]; d3 = c1*u1.y + c2*a[3];
            } else {
                d0 = c2*a[0]; d1 = c2*a[1]; d2 = c2*a[2]; d3 = c2*a[3];
            }
            *reinterpret_cast<float2*>(&Cn[(size_t)grow * ML + gcol]) = make_float2(d0, d1);
            *reinterpret_cast<float2*>(&Cn[(size_t)(grow+8) * ML + gcol]) = make_float2(d2, d3);
            if (Ct) {
                Ct[(size_t)gcol * ML + grow]       = d0;
                Ct[(size_t)(gcol+1) * ML + grow]   = d1;
                Ct[(size_t)gcol * ML + grow+8]     = d2;
                Ct[(size_t)(gcol+1) * ML + grow+8] = d3;
            }
        }
    }
}

// ---------------- landmark means ----------------
__global__ void land_kernel() {
    int idx = blockIdx.x * blockDim.x + threadIdx.x;
    if (idx >= BHN*ML*DH) return;
    int d  = idx & 63;
    int j  = (idx >> 6) & 255;
    int bh = idx >> 14;
    size_t base = ((size_t)bh * NTOK + j*4) * DH + d;
    g_ql[idx] = 0.25f * (g_q[base] + g_q[base+64] + g_q[base+128] + g_q[base+192]);
    g_kl[idx] = 0.25f * (g_k[base] + g_k[base+64] + g_k[base+128] + g_k[base+192]);
}

// ---------------- row softmax ----------------
template<int W>
__global__ void softmax_kernel(float* __restrict__ data) {
    __shared__ float red[256];
    float* row = data + (size_t)blockIdx.x * W;
    int t = threadIdx.x;
    constexpr int PE = W / 256;
    float vals[PE];
    float mx = -1e30f;
    #pragma unroll
    for (int e = 0; e < PE; e++) { vals[e] = row[t + e*256]; mx = fmaxf(mx, vals[e]); }
    red[t] = mx; __syncthreads();
    #pragma unroll
    for (int s = 128; s > 0; s >>= 1) { if (t < s) red[t] = fmaxf(red[t], red[t+s]); __syncthreads(); }
    mx = red[0];
    __syncthreads();
    float sum = 0.f;
    #pragma unroll
    for (int e = 0; e < PE; e++) { vals[e] = expf(vals[e] - mx); sum += vals[e]; }
    red[t] = sum; __syncthreads();
    #pragma unroll
    for (int s = 128; s > 0; s >>= 1) { if (t < s) red[t] += red[t+s]; __syncthreads(); }
    float inv = 1.0f / red[0];
    #pragma unroll
    for (int e = 0; e < PE; e++) row[t + e*256] = vals[e] * inv;
}

// ---------------- pinv scale reductions ----------------
__global__ void reset_max_kernel() { if (threadIdx.x == 0) { g_colmax = 0u; g_rowmax = 0u; } }

__global__ void colmax_kernel() {
    int gw = (blockIdx.x * blockDim.x + threadIdx.x) >> 5;
    int lane = threadIdx.x & 31;
    if (gw >= BHN * ML) return;
    const float* row = g_attn2 + (size_t)gw * ML;
    float s = 0.f;
    #pragma unroll
    for (int j = lane; j < ML; j += 32) s += fabsf(row[j]);
    #pragma unroll
    for (int o = 16; o > 0; o >>= 1) s += __shfl_down_sync(0xffffffffu, s, o);
    if (lane == 0) atomicMax(&g_colmax, __float_as_uint(s));
}

__global__ void rowmax_kernel() {
    int idx = blockIdx.x * blockDim.x + threadIdx.x;
    if (idx >= BHN * ML) return;
    int bh = idx >> 8, j = idx & 255;
    const float* base = g_attn2 + (size_t)bh * ML * ML + j;
    float s = 0.f;
    for (int i = 0; i < ML; i++) s += fabsf(base[(size_t)i * ML]);
    atomicMax(&g_rowmax, __float_as_uint(s));
}

__global__ void zinit_kernel() {    // z = x^T * inv ; zs = x * inv
    float inv = 1.0f / (__uint_as_float(g_colmax) * __uint_as_float(g_rowmax));
    size_t idx = (size_t)blockIdx.x * 256 + threadIdx.x;
    int j  = idx & 255;
    int i  = (idx >> 8) & 255;
    size_t bh = idx >> 16;
    g_zA[idx]  = g_attn2[(bh << 16) + ((size_t)j << 8) + i] * inv;
    g_zsA[idx] = g_attn2[idx] * inv;
}

// ---------------- depthwise 33-tap conv residual ----------------
__global__ void res_add_kernel(const float* __restrict__ rk) {
    __shared__ float ker[KSZ];
    int blk = blockIdx.x;
    int bh = blk >> 8;
    int ichunk = blk & 255;
    int h = bh & 7, b = bh >> 3;
    if (threadIdx.x < KSZ) ker[threadIdx.x] = rk[h*KSZ + threadIdx.x];
    __syncthreads();
    int d = threadIdx.x & 63;
    int i = ichunk * 4 + (threadIdx.x >> 6);
    const float* vb = g_v + (size_t)bh * NTOK * DH;
    float s = 0.f;
    #pragma unroll
    for (int t = 0; t < KSZ; t++) {
        int ii = i + t - (KSZ/2);
        if (ii >= 0 && ii < NTOK) s += ker[t] * vb[(size_t)ii * DH + d];
    }
    g_outf[((size_t)(b*NTOK + i)) * CDIM + h*64 + d] += s;
}

// ---------------- host ----------------
extern "C" void kernel_launch(void* const* d_in, const int* in_sizes, int n_in,
                              void* d_out, int out_size) {
    const float* x     = (const float*)d_in[0];
    const float* w_qkv = (const float*)d_in[1];
    const float* w_out = (const float*)d_in[2];
    const float* b_out = (const float*)d_in[3];
    const float* rk    = (const float*)d_in[4];
    float* out = (float*)d_out;

    float *xt, *wqkvT, *woutT, *q, *k, *v, *vt, *ql, *kl, *a1, *a3, *a2;
    float *zA, *zB, *zsA, *zsB, *xz, *xzs, *t1, *t2, *t2s, *av, *avt, *bv, *bvt, *outf;
    cudaGetSymbolAddress((void**)&xt, g_xt);
    cudaGetSymbolAddress((void**)&wqkvT, g_wqkvT);
    cudaGetSymbolAddress((void**)&woutT, g_woutT);
    cudaGetSymbolAddress((void**)&q,  g_q);
    cudaGetSymbolAddress((void**)&k,  g_k);
    cudaGetSymbolAddress((void**)&v,  g_v);
    cudaGetSymbolAddress((void**)&vt, g_vt);
    cudaGetSymbolAddress((void**)&ql, g_ql);
    cudaGetSymbolAddress((void**)&kl, g_kl);
    cudaGetSymbolAddress((void**)&a1, g_attn1);
    cudaGetSymbolAddress((void**)&a3, g_attn3);
    cudaGetSymbolAddress((void**)&a2, g_attn2);
    cudaGetSymbolAddress((void**)&zA, g_zA);
    cudaGetSymbolAddress((void**)&zB, g_zB);
    cudaGetSymbolAddress((void**)&zsA, g_zsA);
    cudaGetSymbolAddress((void**)&zsB, g_zsB);
    cudaGetSymbolAddress((void**)&xz, g_xz);
    cudaGetSymbolAddress((void**)&xzs, g_xzs);
    cudaGetSymbolAddress((void**)&t1, g_t1);
    cudaGetSymbolAddress((void**)&t2, g_t2);
    cudaGetSymbolAddress((void**)&t2s, g_t2s);
    cudaGetSymbolAddress((void**)&av, g_av);
    cudaGetSymbolAddress((void**)&avt, g_avt);
    cudaGetSymbolAddress((void**)&bv, g_bv);
    cudaGetSymbolAddress((void**)&bvt, g_bvt);
    cudaGetSymbolAddress((void**)&outf, g_outf);

    cudaFuncSetAttribute(pinv_mma_kernel,  cudaFuncAttributeMaxDynamicSharedMemorySize, G128_SMEM);
    cudaFuncSetAttribute(gemm_tc_kernel,   cudaFuncAttributeMaxDynamicSharedMemorySize, G128_SMEM);
    cudaFuncSetAttribute(qkv_tc_kernel,    cudaFuncAttributeMaxDynamicSharedMemorySize, G128_SMEM);
    cudaFuncSetAttribute(final_tc_kernel,  cudaFuncAttributeMaxDynamicSharedMemorySize, G128_SMEM);
    cudaFuncSetAttribute(gemm64_tc_kernel, cudaFuncAttributeMaxDynamicSharedMemorySize, G64_SMEM);

    // 0) layout prep: xT, wqkvT, woutT
    transpose_kernel<<<dim3(NTOK/32, CDIM/32, BATCH), dim3(32,8)>>>(x, xt, CDIM, NTOK);
    transpose_kernel<<<dim3(48, 16, 1), dim3(32,8)>>>(w_qkv, wqkvT, CDIM, 3*CDIM);
    transpose_kernel<<<dim3(16, 16, 1), dim3(32,8)>>>(w_out, woutT, CDIM, CDIM);
    // 1) QKV projection (32768 x 1536 x 512) + scatter to q/k/v/vT
    qkv_tc_kernel<<<dim3(12, 256), 256, G128_SMEM>>>();
    // 2) landmarks
    land_kernel<<<(BHN*ML*DH + 255)/256, 256>>>();
    // 3) similarity GEMMs (batched, tf32)
    gemm_tc_kernel<<<dim3(2, 8, BHN), 256, G128_SMEM>>>(q,  kl, a1, DH, DH, ML,   2,
        (size_t)NTOK*DH, (size_t)ML*DH, (size_t)NTOK*ML);                   // sim1
    gemm_tc_kernel<<<dim3(2, 2, BHN), 256, G128_SMEM>>>(ql, kl, a2, DH, DH, ML,   2,
        (size_t)ML*DH,   (size_t)ML*DH, (size_t)ML*ML);                     // sim2
    gemm_tc_kernel<<<dim3(8, 2, BHN), 256, G128_SMEM>>>(ql, k,  a3, DH, DH, NTOK, 2,
        (size_t)ML*DH,   (size_t)NTOK*DH, (size_t)ML*NTOK);                 // sim3
    // 4) softmaxes
    softmax_kernel<256> <<<BHN*NTOK, 256>>>(a1);
    softmax_kernel<256> <<<BHN*ML,   256>>>(a2);
    softmax_kernel<1024><<<BHN*ML,   256>>>(a3);
    // 5) pinv init (z and z^T)
    reset_max_kernel<<<1, 32>>>();
    colmax_kernel<<<(BHN*ML*32)/256, 256>>>();
    rowmax_kernel<<<(BHN*ML)/256, 256>>>();
    zinit_kernel<<<(BHN*ML*ML)/256, 256>>>();
    // 6) 6 Newton–Schulz iterations on tf32 mma
    float *zin = zA, *zout = zB, *zsin = zsA, *zsout = zsB;
    for (int it = 0; it < 6; it++) {
        pinv_mma_kernel<<<1024, 256, G128_SMEM>>>(a2, zsin, nullptr, xz, xzs, 0.0f, 1.0f);
        pinv_mma_kernel<<<1024, 256, G128_SMEM>>>(xzs, xz, xzs, t1, nullptr, 7.0f, -1.0f);
        pinv_mma_kernel<<<1024, 256, G128_SMEM>>>(xz, t1, xz, t2, t2s, 15.0f, -1.0f);
        pinv_mma_kernel<<<1024, 256, G128_SMEM>>>(zin, t2s, zin, zout, zsout, 3.25f, -0.25f);
        float* tmp;
        tmp = zin;  zin  = zout;  zout  = tmp;
        tmp = zsin; zsin = zsout; zsout = tmp;
    }
    // 7) output chain on mma: av = attn3@v ; bv = z@av ; outf = attn1@bv
    gemm64_tc_kernel<<<dim3(2, 1, BHN), 256, G64_SMEM>>>(a3, vt, av, avt,
        NTOK, NTOK, DH, ML, 32, (size_t)ML*NTOK, (size_t)DH*NTOK,
        (size_t)ML*DH, (size_t)DH*ML, 0);
    gemm64_tc_kernel<<<dim3(2, 1, BHN), 256, G64_SMEM>>>(zin, avt, bv, bvt,
        ML, ML, DH, ML, 8, (size_t)ML*ML, (size_t)DH*ML,
        (size_t)ML*DH, (size_t)DH*ML, 0);
    gemm64_tc_kernel<<<dim3(8, 1, BHN), 256, G64_SMEM>>>(a1, bvt, outf, nullptr,
        ML, ML, CDIM, 0, 8, (size_t)NTOK*ML, (size_t)DH*ML,
        0, 0, 1);
    // 8) depthwise conv residual
    res_add_kernel<<<BHN*256, 256>>>(rk);
    // 9) output projection + bias + transposed store
    final_tc_kernel<<<dim3(4, 256), 256, G128_SMEM>>>(b_out, out);
}

// round 6
// speedup vs baseline: 2.7112x; 1.2047x over previous
#include <cuda_runtime.h>
#include <cstdint>
#include <cstddef>

#define BATCH 32
#define HEADS 8
#define NTOK 1024
#define DH 64
#define ML 256          // landmarks
#define CDIM 512
#define BHN (BATCH*HEADS)   // 256
#define KSZ 33

// ---------------- device scratch ----------------
__device__ float g_xt[(size_t)BATCH*NTOK*CDIM];     // x transposed: (b, n, c), tf32-rounded
__device__ float g_wqkvT[3*CDIM*CDIM];              // (1536, 512), tf32-rounded
__device__ float g_woutT[CDIM*CDIM];                // (512, 512), tf32-rounded
__device__ float g_q [BHN*NTOK*DH];
__device__ float g_k [BHN*NTOK*DH];
__device__ float g_v [BHN*NTOK*DH];
__device__ float g_vt[BHN*DH*NTOK];                 // v transposed per bh: (d, n)
__device__ float g_ql[BHN*ML*DH];
__device__ float g_kl[BHN*ML*DH];
__device__ float g_attn1[(size_t)BHN*NTOK*ML];      // (bh,1024,256)
__device__ float g_attn3[(size_t)BHN*ML*NTOK];      // (bh,256,1024)
__device__ float g_attn2[BHN*ML*ML];
__device__ float g_zA[BHN*ML*ML];
__device__ float g_zB[BHN*ML*ML];
__device__ float g_zsA[BHN*ML*ML];   // transposed z
__device__ float g_zsB[BHN*ML*ML];
__device__ float g_xz[BHN*ML*ML];
__device__ float g_xzs[BHN*ML*ML];   // transposed xz
__device__ float g_t1[BHN*ML*ML];    // holds t1^T
__device__ float g_t2[BHN*ML*ML];
__device__ float g_t2s[BHN*ML*ML];   // transposed t2
__device__ float g_av[BHN*ML*DH];
__device__ float g_avt[BHN*DH*ML];
__device__ float g_bv[BHN*ML*DH];
__device__ float g_bvt[BHN*DH*ML];
__device__ float g_outf[(size_t)BATCH*NTOK*CDIM];   // (b, n, 512)
__device__ unsigned g_colmax;
__device__ unsigned g_rowmax;

// ================= tf32 helpers =================
__device__ __forceinline__ float cvt_tf32(float x) {
    uint32_t u;
    asm("cvt.rna.tf32.f32 %0, %1;" : "=r"(u) : "f"(x));
    return __uint_as_float(u);
}
__device__ __forceinline__ void mma_tf32_16x8x8(float c[4],
    uint32_t a0, uint32_t a1, uint32_t a2, uint32_t a3, uint32_t b0, uint32_t b1) {
    asm volatile(
        "mma.sync.aligned.m16n8k8.row.col.f32.tf32.tf32.f32 "
        "{%0,%1,%2,%3},{%4,%5,%6,%7},{%8,%9},{%0,%1,%2,%3};"
        : "+f"(c[0]), "+f"(c[1]), "+f"(c[2]), "+f"(c[3])
        : "r"(a0), "r"(a1), "r"(a2), "r"(a3), "r"(b0), "r"(b1));
}
__device__ __forceinline__ void cp16(uint32_t dst, const float* src) {
    asm volatile("cp.async.cg.shared.global [%0], [%1], 16;" :: "r"(dst), "l"(src));
}
#define CP_COMMIT() asm volatile("cp.async.commit_group;")
#define CP_WAIT1()  asm volatile("cp.async.wait_group 1;" ::: "memory")
#define CP_WAIT0()  asm volatile("cp.async.wait_group 0;" ::: "memory")

#define PPITCH 36
#define PSTAGE (128*PPITCH)
#define G128_SMEM (4*PSTAGE*4)                    // 73728
#define B64STAGE (64*PPITCH)
#define G64_SMEM ((2*PSTAGE + 2*B64STAGE)*4)      // 55296

// ============ shared 128x128 tf32 mainloop (cp.async, 2-stage) ============
// A, B row-major, values ALREADY tf32-rounded. Computes 128x128 tile of A @ B^T.
__device__ __forceinline__ void mainloop128x128(
    const float* __restrict__ A, const float* __restrict__ B,
    int lda, int ldb, int kch, float* sm, int tid, float acc[4][4][4])
{
    const uint32_t sbase = (uint32_t)__cvta_generic_to_shared(sm);
    const int wid = tid >> 5, lane = tid & 31;
    const int gr = lane >> 2, gc = lane & 3;
    const int wm = wid >> 2, wn = wid & 3;
    int rrow[4], rc4[4];
    #pragma unroll
    for (int e = 0; e < 4; e++) {
        int f4 = e * 256 + tid;
        rrow[e] = f4 >> 3;
        rc4[e] = (f4 & 7) << 2;
    }
    // prologue: chunk 0 -> stage 0
    #pragma unroll
    for (int e = 0; e < 4; e++) {
        cp16(sbase + (uint32_t)(rrow[e]*PPITCH + rc4[e])*4,
             &A[(size_t)rrow[e] * lda + rc4[e]]);
        cp16(sbase + (uint32_t)(2*PSTAGE + rrow[e]*PPITCH + rc4[e])*4,
             &B[(size_t)rrow[e] * ldb + rc4[e]]);
    }
    CP_COMMIT();
    for (int c = 0; c < kch; c++) {
        const int st = c & 1;
        if (c + 1 < kch) {
            const int nst = st ^ 1;
            const int k0 = (c + 1) * 32;
            #pragma unroll
            for (int e = 0; e < 4; e++) {
                cp16(sbase + (uint32_t)(nst*PSTAGE + rrow[e]*PPITCH + rc4[e])*4,
                     &A[(size_t)rrow[e] * lda + k0 + rc4[e]]);
                cp16(sbase + (uint32_t)((2+nst)*PSTAGE + rrow[e]*PPITCH + rc4[e])*4,
                     &B[(size_t)rrow[e] * ldb + k0 + rc4[e]]);
            }
            CP_COMMIT();
            CP_WAIT1();
        } else {
            CP_WAIT0();
        }
        __syncthreads();
        const float* Ab = sm + st*PSTAGE;
        const float* Bb = sm + (2+st)*PSTAGE;
        #pragma unroll
        for (int ks = 0; ks < 4; ks++) {
            uint32_t af[4][4];
            #pragma unroll
            for (int mi = 0; mi < 4; mi++) {
                int base = (wm*64 + mi*16 + gr)*PPITCH + ks*8 + gc;
                af[mi][0] = __float_as_uint(Ab[base]);
                af[mi][1] = __float_as_uint(Ab[base + 8*PPITCH]);
                af[mi][2] = __float_as_uint(Ab[base + 4]);
                af[mi][3] = __float_as_uint(Ab[base + 8*PPITCH + 4]);
            }
            uint32_t bf[4][2];
            #pragma unroll
            for (int ni = 0; ni < 4; ni++) {
                int base = (wn*32 + ni*8 + gr)*PPITCH + ks*8 + gc;
                bf[ni][0] = __float_as_uint(Bb[base]);
                bf[ni][1] = __float_as_uint(Bb[base + 4]);
            }
            #pragma unroll
            for (int mi = 0; mi < 4; mi++)
                #pragma unroll
                for (int ni = 0; ni < 4; ni++)
                    mma_tf32_16x8x8(acc[mi][ni],
                        af[mi][0], af[mi][1], af[mi][2], af[mi][3],
                        bf[ni][0], bf[ni][1]);
        }
        __syncthreads();
    }
}

// ============ plain batched GEMM: C[z] = A[z] @ B[z]^T (128x128 tiles) ============
// (outputs feed softmax, which re-rounds — so no rounding here)
__global__ void __launch_bounds__(256, 2) gemm_tc_kernel(
    const float* __restrict__ A, const float* __restrict__ B, float* __restrict__ C,
    int lda, int ldb, int ldc, int kch,
    size_t sA, size_t sB, size_t sC)
{
    extern __shared__ float sm[];
    const int tid = threadIdx.x;
    const int z = blockIdx.z;
    const int m0 = blockIdx.y * 128, n0 = blockIdx.x * 128;
    A += (size_t)z * sA + (size_t)m0 * lda;
    B += (size_t)z * sB + (size_t)n0 * ldb;
    C += (size_t)z * sC;
    float acc[4][4][4];
    #pragma unroll
    for (int mi = 0; mi < 4; mi++)
        #pragma unroll
        for (int ni = 0; ni < 4; ni++)
            #pragma unroll
            for (int e = 0; e < 4; e++) acc[mi][ni][e] = 0.f;
    mainloop128x128(A, B, lda, ldb, kch, sm, tid, acc);
    const int wid = tid >> 5, lane = tid & 31;
    const int gr = lane >> 2, gc = lane & 3;
    const int wm = wid >> 2, wn = wid & 3;
    #pragma unroll
    for (int mi = 0; mi < 4; mi++) {
        #pragma unroll
        for (int ni = 0; ni < 4; ni++) {
            int lr = m0 + wm*64 + mi*16 + gr;
            int lc = n0 + wn*32 + ni*8 + gc*2;
            const float* a = acc[mi][ni];
            *reinterpret_cast<float2*>(&C[(size_t)lr * ldc + lc]) = make_float2(a[0], a[1]);
            *reinterpret_cast<float2*>(&C[(size_t)(lr+8) * ldc + lc]) = make_float2(a[2], a[3]);
        }
    }
}

// ============ QKV GEMM with scatter epilogue (tf32-rounded outputs) ============
__global__ void __launch_bounds__(256, 2) qkv_tc_kernel(void) {
    extern __shared__ float sm[];
    const int tid = threadIdx.x;
    const int m0 = blockIdx.y * 128;        // over 32768 (b*1024+i)
    const int n0 = blockIdx.x * 128;        // over 1536
    const float* A = g_xt + (size_t)m0 * CDIM;
    const float* B = g_wqkvT + (size_t)n0 * CDIM;
    float acc[4][4][4];
    #pragma unroll
    for (int mi = 0; mi < 4; mi++)
        #pragma unroll
        for (int ni = 0; ni < 4; ni++)
            #pragma unroll
            for (int e = 0; e < 4; e++) acc[mi][ni][e] = 0.f;
    mainloop128x128(A, B, CDIM, CDIM, CDIM/32, sm, tid, acc);
    const int wid = tid >> 5, lane = tid & 31;
    const int gr = lane >> 2, gc = lane & 3;
    const int wm = wid >> 2, wn = wid & 3;
    #pragma unroll
    for (int mi = 0; mi < 4; mi++) {
        int m = m0 + wm*64 + mi*16 + gr;
        int b = m >> 10, i = m & 1023;
        #pragma unroll
        for (int ni = 0; ni < 4; ni++) {
            int n = n0 + wn*32 + ni*8 + gc*2;
            int which = n >> 9;
            int h = (n >> 6) & 7;
            int d = n & 63;
            int bh = b*8 + h;
            float* dst = (which == 0) ? g_q : ((which == 1) ? g_k : g_v);
            float sc = (which == 0) ? 0.125f : 1.0f;
            const float* a = acc[mi][ni];
            float r0 = cvt_tf32(a[0]*sc), r1 = cvt_tf32(a[1]*sc);
            float r2 = cvt_tf32(a[2]*sc), r3 = cvt_tf32(a[3]*sc);
            *reinterpret_cast<float2*>(&dst[((size_t)(bh*NTOK + i))*DH + d]) = make_float2(r0, r1);
            *reinterpret_cast<float2*>(&dst[((size_t)(bh*NTOK + i + 8))*DH + d]) = make_float2(r2, r3);
            if (which == 2) {
                g_vt[((size_t)(bh*DH + d))*NTOK + i]       = r0;
                g_vt[((size_t)(bh*DH + d + 1))*NTOK + i]   = r1;
                g_vt[((size_t)(bh*DH + d))*NTOK + i + 8]   = r2;
                g_vt[((size_t)(bh*DH + d + 1))*NTOK + i + 8] = r3;
            }
        }
    }
}

// ============ final GEMM: out = outf @ woutT^T + bias, transposed store (fp32) ============
__global__ void __launch_bounds__(256, 2) final_tc_kernel(
    const float* __restrict__ bias, float* __restrict__ out)
{
    extern __shared__ float sm[];
    const int tid = threadIdx.x;
    const int m0 = blockIdx.y * 128;        // over 32768
    const int n0 = blockIdx.x * 128;        // over 512
    const float* A = g_outf + (size_t)m0 * CDIM;
    const float* B = g_woutT + (size_t)n0 * CDIM;
    float acc[4][4][4];
    #pragma unroll
    for (int mi = 0; mi < 4; mi++)
        #pragma unroll
        for (int ni = 0; ni < 4; ni++)
            #pragma unroll
            for (int e = 0; e < 4; e++) acc[mi][ni][e] = 0.f;
    mainloop128x128(A, B, CDIM, CDIM, CDIM/32, sm, tid, acc);
    const int wid = tid >> 5, lane = tid & 31;
    const int gr = lane >> 2, gc = lane & 3;
    const int wm = wid >> 2, wn = wid & 3;
    #pragma unroll
    for (int mi = 0; mi < 4; mi++) {
        int m = m0 + wm*64 + mi*16 + gr;
        int b = m >> 10, i = m & 1023;
        #pragma unroll
        for (int ni = 0; ni < 4; ni++) {
            int n = n0 + wn*32 + ni*8 + gc*2;
            const float* a = acc[mi][ni];
            float b0 = bias[n], b1 = bias[n+1];
            out[((size_t)(b*CDIM + n))*NTOK + i]       = a[0] + b0;
            out[((size_t)(b*CDIM + n + 1))*NTOK + i]   = a[1] + b1;
            out[((size_t)(b*CDIM + n))*NTOK + i + 8]   = a[2] + b0;
            out[((size_t)(b*CDIM + n + 1))*NTOK + i + 8] = a[3] + b1;
        }
    }
}

// ============ 128x64 batched GEMM (N=64): C = A @ B^T, optional C^T output ============
// (kept reg-staged; cvt is idempotent on pre-rounded inputs). Outputs tf32-rounded.
__global__ void __launch_bounds__(256, 2) gemm64_tc_kernel(
    const float* __restrict__ A, const float* __restrict__ B,
    float* __restrict__ C, float* __restrict__ Ct,
    int lda, int ldb, int ldc, int ldct, int kch,
    size_t sA, size_t sB, size_t sC, size_t sCt, int flatC)
{
    extern __shared__ float sm[];
    float* As = sm;                    // 2 x 128 x 36
    float* Bs = sm + 2*PSTAGE;         // 2 x 64 x 36
    const int tid = threadIdx.x;
    const int wid = tid >> 5, lane = tid & 31;
    const int gr = lane >> 2, gc = lane & 3;
    const int wm = wid >> 1, wn = wid & 1;
    const int z = blockIdx.z;
    const int m0 = blockIdx.x * 128;
    A += (size_t)z * sA + (size_t)m0 * lda;
    B += (size_t)z * sB;
    if (flatC) C += (size_t)(z >> 3) * (NTOK*CDIM) + (size_t)(z & 7) * DH;
    else       C += (size_t)z * sC;
    if (Ct) Ct += (size_t)z * sCt;

    int arow[4], ac4[4], brow[2], bc4[2];
    #pragma unroll
    for (int e = 0; e < 4; e++) {
        int f4 = e * 256 + tid;
        arow[e] = f4 >> 3; ac4[e] = (f4 & 7) << 2;
    }
    #pragma unroll
    for (int e = 0; e < 2; e++) {
        int f4 = e * 256 + tid;
        brow[e] = f4 >> 3; bc4[e] = (f4 & 7) << 2;
    }

    float acc[2][4][4];
    #pragma unroll
    for (int mi = 0; mi < 2; mi++)
        #pragma unroll
        for (int ni = 0; ni < 4; ni++)
            #pragma unroll
            for (int e = 0; e < 4; e++) acc[mi][ni][e] = 0.f;

    float4 ra[4], rb[2];
    #pragma unroll
    for (int e = 0; e < 4; e++)
        ra[e] = *reinterpret_cast<const float4*>(&A[(size_t)arow[e] * lda + ac4[e]]);
    #pragma unroll
    for (int e = 0; e < 2; e++)
        rb[e] = *reinterpret_cast<const float4*>(&B[(size_t)brow[e] * ldb + bc4[e]]);
    #pragma unroll
    for (int e = 0; e < 4; e++) {
        float* pa = &As[arow[e]*PPITCH + ac4[e]];
        pa[0] = ra[e].x; pa[1] = ra[e].y; pa[2] = ra[e].z; pa[3] = ra[e].w;
    }
    #pragma unroll
    for (int e = 0; e < 2; e++) {
        float* pb = &Bs[brow[e]*PPITCH + bc4[e]];
        pb[0] = rb[e].x; pb[1] = rb[e].y; pb[2] = rb[e].z; pb[3] = rb[e].w;
    }
    __syncthreads();

    for (int c = 0; c < kch; c++) {
        const int st = c & 1;
        if (c < kch - 1) {
            const int k0 = (c + 1) * 32;
            #pragma unroll
            for (int e = 0; e < 4; e++)
                ra[e] = *reinterpret_cast<const float4*>(&A[(size_t)arow[e] * lda + k0 + ac4[e]]);
            #pragma unroll
            for (int e = 0; e < 2; e++)
                rb[e] = *reinterpret_cast<const float4*>(&B[(size_t)brow[e] * ldb + k0 + bc4[e]]);
        }
        const float* Ab = &As[st*PSTAGE];
        const float* Bb = &Bs[st*B64STAGE];
        #pragma unroll
        for (int ks = 0; ks < 4; ks++) {
            uint32_t af[2][4];
            #pragma unroll
            for (int mi = 0; mi < 2; mi++) {
                int base = (wm*32 + mi*16 + gr)*PPITCH + ks*8 + gc;
                af[mi][0] = __float_as_uint(Ab[base]);
                af[mi][1] = __float_as_uint(Ab[base + 8*PPITCH]);
                af[mi][2] = __float_as_uint(Ab[base + 4]);
                af[mi][3] = __float_as_uint(Ab[base + 8*PPITCH + 4]);
            }
            uint32_t bf[4][2];
            #pragma unroll
            for (int ni = 0; ni < 4; ni++) {
                int base = (wn*32 + ni*8 + gr)*PPITCH + ks*8 + gc;
                bf[ni][0] = __float_as_uint(Bb[base]);
                bf[ni][1] = __float_as_uint(Bb[base + 4]);
            }
            #pragma unroll
            for (int mi = 0; mi < 2; mi++)
                #pragma unroll
                for (int ni = 0; ni < 4; ni++)
                    mma_tf32_16x8x8(acc[mi][ni],
                        af[mi][0], af[mi][1], af[mi][2], af[mi][3],
                        bf[ni][0], bf[ni][1]);
        }
        if (c < kch - 1) {
            const int nst = st ^ 1;
            #pragma unroll
            for (int e = 0; e < 4; e++) {
                float* pa = &As[nst*PSTAGE + arow[e]*PPITCH + ac4[e]];
                pa[0] = ra[e].x; pa[1] = ra[e].y; pa[2] = ra[e].z; pa[3] = ra[e].w;
            }
            #pragma unroll
            for (int e = 0; e < 2; e++) {
                float* pb = &Bs[nst*B64STAGE + brow[e]*PPITCH + bc4[e]];
                pb[0] = rb[e].x; pb[1] = rb[e].y; pb[2] = rb[e].z; pb[3] = rb[e].w;
            }
        }
        __syncthreads();
    }

    #pragma unroll
    for (int mi = 0; mi < 2; mi++) {
        #pragma unroll
        for (int ni = 0; ni < 4; ni++) {
            int lr = m0 + wm*32 + mi*16 + gr;
            int lc = wn*32 + ni*8 + gc*2;
            const float* a = acc[mi][ni];
            float d0 = cvt_tf32(a[0]), d1 = cvt_tf32(a[1]);
            float d2 = cvt_tf32(a[2]), d3 = cvt_tf32(a[3]);
            *reinterpret_cast<float2*>(&C[(size_t)lr * ldc + lc]) = make_float2(d0, d1);
            *reinterpret_cast<float2*>(&C[(size_t)(lr+8) * ldc + lc]) = make_float2(d2, d3);
            if (Ct) {
                Ct[(size_t)lc * ldct + lr]       = d0;
                Ct[(size_t)(lc+1) * ldct + lr]   = d1;
                Ct[(size_t)lc * ldct + lr + 8]   = d2;
                Ct[(size_t)(lc+1) * ldct + lr + 8] = d3;
            }
        }
    }
}

// ---------------- batched 2D transpose (tf32-rounded output) ----------------
__global__ void transpose_kernel(const float* __restrict__ in, float* __restrict__ out,
                                 int R, int C) {
    __shared__ float tile[32][33];
    const int z = blockIdx.z;
    in  += (size_t)z * R * C;
    out += (size_t)z * R * C;
    int c0 = blockIdx.x * 32, r0 = blockIdx.y * 32;
    int tx = threadIdx.x, ty = threadIdx.y;
    #pragma unroll
    for (int j = 0; j < 4; j++)
        tile[ty + j*8][tx] = in[(size_t)(r0 + ty + j*8) * C + c0 + tx];
    __syncthreads();
    #pragma unroll
    for (int j = 0; j < 4; j++)
        out[(size_t)(c0 + ty + j*8) * R + r0 + tx] = cvt_tf32(tile[tx][ty + j*8]);
}

// ================= pinv batched GEMM (tf32-rounded dual-store epilogue) =================
__global__ void __launch_bounds__(256, 2) pinv_mma_kernel(
    const float* __restrict__ P, const float* __restrict__ Q,
    const float* __restrict__ U, float* __restrict__ Cn, float* __restrict__ Ct,
    float c1, float c2)
{
    extern __shared__ float sm[];
    const int tid = threadIdx.x;
    const int wid = tid >> 5, lane = tid & 31;
    const int wm = wid >> 2, wn = wid & 3;
    const int gr = lane >> 2, gc = lane & 3;
    const int tile = blockIdx.x;
    const int batch = tile >> 2;
    const int m0 = ((tile >> 1) & 1) << 7;
    const int n0 = (tile & 1) << 7;
    const size_t boff = (size_t)batch << 16;
    P += boff + (size_t)m0 * ML;
    Q += boff + (size_t)n0 * ML;
    if (U) U += boff;
    Cn += boff;
    if (Ct) Ct += boff;

    float acc[4][4][4];
    #pragma unroll
    for (int mi = 0; mi < 4; mi++)
        #pragma unroll
        for (int ni = 0; ni < 4; ni++)
            #pragma unroll
            for (int e = 0; e < 4; e++) acc[mi][ni][e] = 0.f;
    mainloop128x128(P, Q, ML, ML, 8, sm, tid, acc);

    #pragma unroll
    for (int mi = 0; mi < 4; mi++) {
        #pragma unroll
        for (int ni = 0; ni < 4; ni++) {
            int lr = wm*64 + mi*16 + gr;
            int lc = wn*32 + ni*8 + gc*2;
            int grow = m0 + lr, gcol = n0 + lc;
            const float* a = acc[mi][ni];
            float d0, d1, d2, d3;
            if (U) {
                float2 u0 = *reinterpret_cast<const float2*>(&U[(size_t)grow * ML + gcol]);
                float2 u1 = *reinterpret_cast<const float2*>(&U[(size_t)(grow+8) * ML + gcol]);
                d0 = c1*u0.x + c2*a[0]; d1 = c1*u0.y + c2*a[1];
                d2 = c1*u1.x + c2*a[2]; d3 = c1*u1.y + c2*a[3];
            } else {
                d0 = c2*a[0]; d1 = c2*a[1]; d2 = c2*a[2]; d3 = c2*a[3];
            }
            d0 = cvt_tf32(d0); d1 = cvt_tf32(d1); d2 = cvt_tf32(d2); d3 = cvt_tf32(d3);
            *reinterpret_cast<float2*>(&Cn[(size_t)grow * ML + gcol]) = make_float2(d0, d1);
            *reinterpret_cast<float2*>(&Cn[(size_t)(grow+8) * ML + gcol]) = make_float2(d2, d3);
            if (Ct) {
                Ct[(size_t)gcol * ML + grow]       = d0;
                Ct[(size_t)(gcol+1) * ML + grow]   = d1;
                Ct[(size_t)gcol * ML + grow+8]     = d2;
                Ct[(size_t)(gcol+1) * ML + grow+8] = d3;
            }
        }
    }
}

// ---------------- landmark means (tf32-rounded) ----------------
__global__ void land_kernel() {
    int idx = blockIdx.x * blockDim.x + threadIdx.x;
    if (idx >= BHN*ML*DH) return;
    int d  = idx & 63;
    int j  = (idx >> 6) & 255;
    int bh = idx >> 14;
    size_t base = ((size_t)bh * NTOK + j*4) * DH + d;
    g_ql[idx] = cvt_tf32(0.25f * (g_q[base] + g_q[base+64] + g_q[base+128] + g_q[base+192]));
    g_kl[idx] = cvt_tf32(0.25f * (g_k[base] + g_k[base+64] + g_k[base+128] + g_k[base+192]));
}

// ---------------- row softmax (tf32-rounded output) ----------------
template<int W>
__global__ void softmax_kernel(float* __restrict__ data) {
    __shared__ float red[256];
    float* row = data + (size_t)blockIdx.x * W;
    int t = threadIdx.x;
    constexpr int PE = W / 256;
    float vals[PE];
    float mx = -1e30f;
    #pragma unroll
    for (int e = 0; e < PE; e++) { vals[e] = row[t + e*256]; mx = fmaxf(mx, vals[e]); }
    red[t] = mx; __syncthreads();
    #pragma unroll
    for (int s = 128; s > 0; s >>= 1) { if (t < s) red[t] = fmaxf(red[t], red[t+s]); __syncthreads(); }
    mx = red[0];
    __syncthreads();
    float sum = 0.f;
    #pragma unroll
    for (int e = 0; e < PE; e++) { vals[e] = expf(vals[e] - mx); sum += vals[e]; }
    red[t] = sum; __syncthreads();
    #pragma unroll
    for (int s = 128; s > 0; s >>= 1) { if (t < s) red[t] += red[t+s]; __syncthreads(); }
    float inv = 1.0f / red[0];
    #pragma unroll
    for (int e = 0; e < PE; e++) row[t + e*256] = cvt_tf32(vals[e] * inv);
}

// ---------------- pinv scale reductions ----------------
__global__ void reset_max_kernel() { if (threadIdx.x == 0) { g_colmax = 0u; g_rowmax = 0u; } }

__global__ void colmax_kernel() {
    int gw = (blockIdx.x * blockDim.x + threadIdx.x) >> 5;
    int lane = threadIdx.x & 31;
    if (gw >= BHN * ML) return;
    const float* row = g_attn2 + (size_t)gw * ML;
    float s = 0.f;
    #pragma unroll
    for (int j = lane; j < ML; j += 32) s += fabsf(row[j]);
    #pragma unroll
    for (int o = 16; o > 0; o >>= 1) s += __shfl_down_sync(0xffffffffu, s, o);
    if (lane == 0) atomicMax(&g_colmax, __float_as_uint(s));
}

__global__ void rowmax_kernel() {
    int idx = blockIdx.x * blockDim.x + threadIdx.x;
    if (idx >= BHN * ML) return;
    int bh = idx >> 8, j = idx & 255;
    const float* base = g_attn2 + (size_t)bh * ML * ML + j;
    float s = 0.f;
    for (int i = 0; i < ML; i++) s += fabsf(base[(size_t)i * ML]);
    atomicMax(&g_rowmax, __float_as_uint(s));
}

__global__ void zinit_kernel() {    // z = x^T * inv ; zs = x * inv (tf32-rounded)
    float inv = 1.0f / (__uint_as_float(g_colmax) * __uint_as_float(g_rowmax));
    size_t idx = (size_t)blockIdx.x * 256 + threadIdx.x;
    int j  = idx & 255;
    int i  = (idx >> 8) & 255;
    size_t bh = idx >> 16;
    g_zA[idx]  = cvt_tf32(g_attn2[(bh << 16) + ((size_t)j << 8) + i] * inv);
    g_zsA[idx] = cvt_tf32(g_attn2[idx] * inv);
}

// ---------------- depthwise 33-tap conv residual (tf32-rounded add) ----------------
__global__ void res_add_kernel(const float* __restrict__ rk) {
    __shared__ float ker[KSZ];
    int blk = blockIdx.x;
    int bh = blk >> 8;
    int ichunk = blk & 255;
    int h = bh & 7, b = bh >> 3;
    if (threadIdx.x < KSZ) ker[threadIdx.x] = rk[h*KSZ + threadIdx.x];
    __syncthreads();
    int d = threadIdx.x & 63;
    int i = ichunk * 4 + (threadIdx.x >> 6);
    const float* vb = g_v + (size_t)bh * NTOK * DH;
    float s = 0.f;
    #pragma unroll
    for (int t = 0; t < KSZ; t++) {
        int ii = i + t - (KSZ/2);
        if (ii >= 0 && ii < NTOK) s += ker[t] * vb[(size_t)ii * DH + d];
    }
    size_t o = ((size_t)(b*NTOK + i)) * CDIM + h*64 + d;
    g_outf[o] = cvt_tf32(g_outf[o] + s);
}

// ---------------- host ----------------
extern "C" void kernel_launch(void* const* d_in, const int* in_sizes, int n_in,
                              void* d_out, int out_size) {
    const float* x     = (const float*)d_in[0];
    const float* w_qkv = (const float*)d_in[1];
    const float* w_out = (const float*)d_in[2];
    const float* b_out = (const float*)d_in[3];
    const float* rk    = (const float*)d_in[4];
    float* out = (float*)d_out;

    float *xt, *wqkvT, *woutT, *q, *k, *v, *vt, *ql, *kl, *a1, *a3, *a2;
    float *zA, *zB, *zsA, *zsB, *xz, *xzs, *t1, *t2, *t2s, *av, *avt, *bv, *bvt, *outf;
    cudaGetSymbolAddress((void**)&xt, g_xt);
    cudaGetSymbolAddress((void**)&wqkvT, g_wqkvT);
    cudaGetSymbolAddress((void**)&woutT, g_woutT);
    cudaGetSymbolAddress((void**)&q,  g_q);
    cudaGetSymbolAddress((void**)&k,  g_k);
    cudaGetSymbolAddress((void**)&v,  g_v);
    cudaGetSymbolAddress((void**)&vt, g_vt);
    cudaGetSymbolAddress((void**)&ql, g_ql);
    cudaGetSymbolAddress((void**)&kl, g_kl);
    cudaGetSymbolAddress((void**)&a1, g_attn1);
    cudaGetSymbolAddress((void**)&a3, g_attn3);
    cudaGetSymbolAddress((void**)&a2, g_attn2);
    cudaGetSymbolAddress((void**)&zA, g_zA);
    cudaGetSymbolAddress((void**)&zB, g_zB);
    cudaGetSymbolAddress((void**)&zsA, g_zsA);
    cudaGetSymbolAddress((void**)&zsB, g_zsB);
    cudaGetSymbolAddress((void**)&xz, g_xz);
    cudaGetSymbolAddress((void**)&xzs, g_xzs);
    cudaGetSymbolAddress((void**)&t1, g_t1);
    cudaGetSymbolAddress((void**)&t2, g_t2);
    cudaGetSymbolAddress((void**)&t2s, g_t2s);
    cudaGetSymbolAddress((void**)&av, g_av);
    cudaGetSymbolAddress((void**)&avt, g_avt);
    cudaGetSymbolAddress((void**)&bv, g_bv);
    cudaGetSymbolAddress((void**)&bvt, g_bvt);
    cudaGetSymbolAddress((void**)&outf, g_outf);

    cudaFuncSetAttribute(pinv_mma_kernel,  cudaFuncAttributeMaxDynamicSharedMemorySize, G128_SMEM);
    cudaFuncSetAttribute(gemm_tc_kernel,   cudaFuncAttributeMaxDynamicSharedMemorySize, G128_SMEM);
    cudaFuncSetAttribute(qkv_tc_kernel,    cudaFuncAttributeMaxDynamicSharedMemorySize, G128_SMEM);
    cudaFuncSetAttribute(final_tc_kernel,  cudaFuncAttributeMaxDynamicSharedMemorySize, G128_SMEM);
    cudaFuncSetAttribute(gemm64_tc_kernel, cudaFuncAttributeMaxDynamicSharedMemorySize, G64_SMEM);

    // 0) layout prep: xT, wqkvT, woutT (tf32-rounded)
    transpose_kernel<<<dim3(NTOK/32, CDIM/32, BATCH), dim3(32,8)>>>(x, xt, CDIM, NTOK);
    transpose_kernel<<<dim3(48, 16, 1), dim3(32,8)>>>(w_qkv, wqkvT, CDIM, 3*CDIM);
    transpose_kernel<<<dim3(16, 16, 1), dim3(32,8)>>>(w_out, woutT, CDIM, CDIM);
    // 1) QKV projection (32768 x 1536 x 512) + scatter to q/k/v/vT
    qkv_tc_kernel<<<dim3(12, 256), 256, G128_SMEM>>>();
    // 2) landmarks
    land_kernel<<<(BHN*ML*DH + 255)/256, 256>>>();
    // 3) similarity GEMMs (batched, tf32)
    gemm_tc_kernel<<<dim3(2, 8, BHN), 256, G128_SMEM>>>(q,  kl, a1, DH, DH, ML,   2,
        (size_t)NTOK*DH, (size_t)ML*DH, (size_t)NTOK*ML);                   // sim1
    gemm_tc_kernel<<<dim3(2, 2, BHN), 256, G128_SMEM>>>(ql, kl, a2, DH, DH, ML,   2,
        (size_t)ML*DH,   (size_t)ML*DH, (size_t)ML*ML);                     // sim2
    gemm_tc_kernel<<<dim3(8, 2, BHN), 256, G128_SMEM>>>(ql, k,  a3, DH, DH, NTOK, 2,
        (size_t)ML*DH,   (size_t)NTOK*DH, (size_t)ML*NTOK);                 // sim3
    // 4) softmaxes (tf32-rounded outputs)
    softmax_kernel<256> <<<BHN*NTOK, 256>>>(a1);
    softmax_kernel<256> <<<BHN*ML,   256>>>(a2);
    softmax_kernel<1024><<<BHN*ML,   256>>>(a3);
    // 5) pinv init (z and z^T)
    reset_max_kernel<<<1, 32>>>();
    colmax_kernel<<<(BHN*ML*32)/256, 256>>>();
    rowmax_kernel<<<(BHN*ML)/256, 256>>>();
    zinit_kernel<<<(BHN*ML*ML)/256, 256>>>();
    // 6) 6 Newton–Schulz iterations on tf32 mma
    float *zin = zA, *zout = zB, *zsin = zsA, *zsout = zsB;
    for (int it = 0; it < 6; it++) {
        pinv_mma_kernel<<<1024, 256, G128_SMEM>>>(a2, zsin, nullptr, xz, xzs, 0.0f, 1.0f);
        pinv_mma_kernel<<<1024, 256, G128_SMEM>>>(xzs, xz, xzs, t1, nullptr, 7.0f, -1.0f);
        pinv_mma_kernel<<<1024, 256, G128_SMEM>>>(xz, t1, xz, t2, t2s, 15.0f, -1.0f);
        pinv_mma_kernel<<<1024, 256, G128_SMEM>>>(zin, t2s, zin, zout, zsout, 3.25f, -0.25f);
        float* tmp;
        tmp = zin;  zin  = zout;  zout  = tmp;
        tmp = zsin; zsin = zsout; zsout = tmp;
    }
    // 7) output chain on mma: av = attn3@v ; bv = z@av ; outf = attn1@bv
    gemm64_tc_kernel<<<dim3(2, 1, BHN), 256, G64_SMEM>>>(a3, vt, av, avt,
        NTOK, NTOK, DH, ML, 32, (size_t)ML*NTOK, (size_t)DH*NTOK,
        (size_t)ML*DH, (size_t)DH*ML, 0);
    gemm64_tc_kernel<<<dim3(2, 1, BHN), 256, G64_SMEM>>>(zin, avt, bv, bvt,
        ML, ML, DH, ML, 8, (size_t)ML*ML, (size_t)DH*ML,
        (size_t)ML*DH, (size_t)DH*ML, 0);
    gemm64_tc_kernel<<<dim3(8, 1, BHN), 256, G64_SMEM>>>(a1, bvt, outf, nullptr,
        ML, ML, CDIM, 0, 8, (size_t)NTOK*ML, (size_t)DH*ML,
        0, 0, 1);
    // 8) depthwise conv residual (rounds outf for final GEMM)
    res_add_kernel<<<BHN*256, 256>>>(rk);
    // 9) output projection + bias + transposed store (fp32)
    final_tc_kernel<<<dim3(4, 256), 256, G128_SMEM>>>(b_out, out);
}

// round 7
// speedup vs baseline: 2.8628x; 1.0559x over previous
#include <cuda_runtime.h>
#include <cstdint>
#include <cstddef>

#define BATCH 32
#define HEADS 8
#define NTOK 1024
#define DH 64
#define ML 256          // landmarks
#define CDIM 512
#define BHN (BATCH*HEADS)   // 256
#define KSZ 33

// ---------------- device scratch ----------------
__device__ float g_xt[(size_t)BATCH*NTOK*CDIM];     // x transposed: (b, n, c), tf32-rounded
__device__ float g_wqkvT[3*CDIM*CDIM];              // (1536, 512), tf32-rounded
__device__ float g_woutT[CDIM*CDIM];                // (512, 512), tf32-rounded
__device__ float g_q [BHN*NTOK*DH];
__device__ float g_k [BHN*NTOK*DH];
__device__ float g_v [BHN*NTOK*DH];
__device__ float g_ql[BHN*ML*DH];
__device__ float g_kl[BHN*ML*DH];
__device__ float g_attn1[(size_t)BHN*NTOK*ML];      // (bh,1024,256)
__device__ float g_attn3[(size_t)BHN*ML*NTOK];      // (bh,256,1024)
__device__ float g_attn2[BHN*ML*ML];
__device__ float g_zA[BHN*ML*ML];
__device__ float g_zB[BHN*ML*ML];
__device__ float g_xz[BHN*ML*ML];
__device__ float g_t1[BHN*ML*ML];
__device__ float g_t2[BHN*ML*ML];
__device__ float g_av[BHN*ML*DH];
__device__ float g_bv[BHN*ML*DH];
__device__ float g_outf[(size_t)BATCH*NTOK*CDIM];   // (b, n, 512)
__device__ unsigned g_colmax;
__device__ unsigned g_rowmax;

// ================= tf32 helpers =================
__device__ __forceinline__ float cvt_tf32(float x) {
    uint32_t u;
    asm("cvt.rna.tf32.f32 %0, %1;" : "=r"(u) : "f"(x));
    return __uint_as_float(u);
}
__device__ __forceinline__ void mma_tf32_16x8x8(float c[4],
    uint32_t a0, uint32_t a1, uint32_t a2, uint32_t a3, uint32_t b0, uint32_t b1) {
    asm volatile(
        "mma.sync.aligned.m16n8k8.row.col.f32.tf32.tf32.f32 "
        "{%0,%1,%2,%3},{%4,%5,%6,%7},{%8,%9},{%0,%1,%2,%3};"
        : "+f"(c[0]), "+f"(c[1]), "+f"(c[2]), "+f"(c[3])
        : "r"(a0), "r"(a1), "r"(a2), "r"(a3), "r"(b0), "r"(b1));
}
__device__ __forceinline__ void cp16(uint32_t dst, const float* src) {
    asm volatile("cp.async.cg.shared.global [%0], [%1], 16;" :: "r"(dst), "l"(src));
}
#define CP_COMMIT() asm volatile("cp.async.commit_group;")
#define CP_WAIT1()  asm volatile("cp.async.wait_group 1;" ::: "memory")
#define CP_WAIT0()  asm volatile("cp.async.wait_group 0;" ::: "memory")

#define PPITCH 36
#define PSTAGE (128*PPITCH)
#define G128_SMEM (4*PSTAGE*4)                    // 73728 (A+B both K-major 128-row)

// row-major-B tiles: [32 k-rows][N cols] with pitch chosen so pitch mod 32 == 8
#define BNP128 136
#define BRSTG128 (32*BNP128)                      // 4352 floats
#define PB_SMEM ((2*PSTAGE + 2*BRSTG128)*4)       // 71680

#define BNP64 72
#define BRSTG64 (32*BNP64)                        // 2304 floats
#define G64R_SMEM ((2*PSTAGE + 2*BRSTG64)*4)      // 55296

// ============ mainloop A: B stored K-major ([N rows][K]) — for sims/qkv/final ============
__device__ __forceinline__ void mainloop128x128(
    const float* __restrict__ A, const float* __restrict__ B,
    int lda, int ldb, int kch, float* sm, int tid, float acc[4][4][4])
{
    const uint32_t sbase = (uint32_t)__cvta_generic_to_shared(sm);
    const int wid = tid >> 5, lane = tid & 31;
    const int gr = lane >> 2, gc = lane & 3;
    const int wm = wid >> 2, wn = wid & 3;
    int rrow[4], rc4[4];
    #pragma unroll
    for (int e = 0; e < 4; e++) {
        int f4 = e * 256 + tid;
        rrow[e] = f4 >> 3;
        rc4[e] = (f4 & 7) << 2;
    }
    #pragma unroll
    for (int e = 0; e < 4; e++) {
        cp16(sbase + (uint32_t)(rrow[e]*PPITCH + rc4[e])*4,
             &A[(size_t)rrow[e] * lda + rc4[e]]);
        cp16(sbase + (uint32_t)(2*PSTAGE + rrow[e]*PPITCH + rc4[e])*4,
             &B[(size_t)rrow[e] * ldb + rc4[e]]);
    }
    CP_COMMIT();
    for (int c = 0; c < kch; c++) {
        const int st = c & 1;
        if (c + 1 < kch) {
            const int nst = st ^ 1;
            const int k0 = (c + 1) * 32;
            #pragma unroll
            for (int e = 0; e < 4; e++) {
                cp16(sbase + (uint32_t)(nst*PSTAGE + rrow[e]*PPITCH + rc4[e])*4,
                     &A[(size_t)rrow[e] * lda + k0 + rc4[e]]);
                cp16(sbase + (uint32_t)((2+nst)*PSTAGE + rrow[e]*PPITCH + rc4[e])*4,
                     &B[(size_t)rrow[e] * ldb + k0 + rc4[e]]);
            }
            CP_COMMIT();
            CP_WAIT1();
        } else {
            CP_WAIT0();
        }
        __syncthreads();
        const float* Ab = sm + st*PSTAGE;
        const float* Bb = sm + (2+st)*PSTAGE;
        #pragma unroll
        for (int ks = 0; ks < 4; ks++) {
            uint32_t af[4][4];
            #pragma unroll
            for (int mi = 0; mi < 4; mi++) {
                int base = (wm*64 + mi*16 + gr)*PPITCH + ks*8 + gc;
                af[mi][0] = __float_as_uint(Ab[base]);
                af[mi][1] = __float_as_uint(Ab[base + 8*PPITCH]);
                af[mi][2] = __float_as_uint(Ab[base + 4]);
                af[mi][3] = __float_as_uint(Ab[base + 8*PPITCH + 4]);
            }
            uint32_t bf[4][2];
            #pragma unroll
            for (int ni = 0; ni < 4; ni++) {
                int base = (wn*32 + ni*8 + gr)*PPITCH + ks*8 + gc;
                bf[ni][0] = __float_as_uint(Bb[base]);
                bf[ni][1] = __float_as_uint(Bb[base + 4]);
            }
            #pragma unroll
            for (int mi = 0; mi < 4; mi++)
                #pragma unroll
                for (int ni = 0; ni < 4; ni++)
                    mma_tf32_16x8x8(acc[mi][ni],
                        af[mi][0], af[mi][1], af[mi][2], af[mi][3],
                        bf[ni][0], bf[ni][1]);
        }
        __syncthreads();
    }
}

// ============ mainloop B: B stored row-major [K][N] — transpose-free chain/pinv ============
// smem B tile: [32 k][BNP128 pitch]; fragment reads conflict-free (pitch mod 32 == 8).
__device__ __forceinline__ void mainloop128x128_rowB(
    const float* __restrict__ A, const float* __restrict__ B,
    int lda, int ldb, int kch, float* sm, int tid, float acc[4][4][4])
{
    const uint32_t sbase = (uint32_t)__cvta_generic_to_shared(sm);
    const int wid = tid >> 5, lane = tid & 31;
    const int gr = lane >> 2, gc = lane & 3;
    const int wm = wid >> 2, wn = wid & 3;
    int arow[4], ac4[4], bk[4], bn4[4];
    #pragma unroll
    for (int e = 0; e < 4; e++) {
        int f4 = e * 256 + tid;
        arow[e] = f4 >> 3;  ac4[e] = (f4 & 7) << 2;
        bk[e]   = f4 >> 5;  bn4[e] = (f4 & 31) << 2;
    }
    #pragma unroll
    for (int e = 0; e < 4; e++) {
        cp16(sbase + (uint32_t)(arow[e]*PPITCH + ac4[e])*4,
             &A[(size_t)arow[e] * lda + ac4[e]]);
        cp16(sbase + (uint32_t)(2*PSTAGE + bk[e]*BNP128 + bn4[e])*4,
             &B[(size_t)bk[e] * ldb + bn4[e]]);
    }
    CP_COMMIT();
    for (int c = 0; c < kch; c++) {
        const int st = c & 1;
        if (c + 1 < kch) {
            const int nst = st ^ 1;
            const int k0 = (c + 1) * 32;
            #pragma unroll
            for (int e = 0; e < 4; e++) {
                cp16(sbase + (uint32_t)(nst*PSTAGE + arow[e]*PPITCH + ac4[e])*4,
                     &A[(size_t)arow[e] * lda + k0 + ac4[e]]);
                cp16(sbase + (uint32_t)(2*PSTAGE + nst*BRSTG128 + bk[e]*BNP128 + bn4[e])*4,
                     &B[(size_t)(k0 + bk[e]) * ldb + bn4[e]]);
            }
            CP_COMMIT();
            CP_WAIT1();
        } else {
            CP_WAIT0();
        }
        __syncthreads();
        const float* Ab = sm + st*PSTAGE;
        const float* Bb = sm + 2*PSTAGE + st*BRSTG128;
        #pragma unroll
        for (int ks = 0; ks < 4; ks++) {
            uint32_t af[4][4];
            #pragma unroll
            for (int mi = 0; mi < 4; mi++) {
                int base = (wm*64 + mi*16 + gr)*PPITCH + ks*8 + gc;
                af[mi][0] = __float_as_uint(Ab[base]);
                af[mi][1] = __float_as_uint(Ab[base + 8*PPITCH]);
                af[mi][2] = __float_as_uint(Ab[base + 4]);
                af[mi][3] = __float_as_uint(Ab[base + 8*PPITCH + 4]);
            }
            uint32_t bf[4][2];
            #pragma unroll
            for (int ni = 0; ni < 4; ni++) {
                int n = wn*32 + ni*8 + gr;
                bf[ni][0] = __float_as_uint(Bb[(ks*8 + gc)*BNP128 + n]);
                bf[ni][1] = __float_as_uint(Bb[(ks*8 + gc + 4)*BNP128 + n]);
            }
            #pragma unroll
            for (int mi = 0; mi < 4; mi++)
                #pragma unroll
                for (int ni = 0; ni < 4; ni++)
                    mma_tf32_16x8x8(acc[mi][ni],
                        af[mi][0], af[mi][1], af[mi][2], af[mi][3],
                        bf[ni][0], bf[ni][1]);
        }
        __syncthreads();
    }
}

// ============ plain batched GEMM: C[z] = A[z] @ B[z]^T (B K-major; sims) ============
__global__ void __launch_bounds__(256, 2) gemm_tc_kernel(
    const float* __restrict__ A, const float* __restrict__ B, float* __restrict__ C,
    int lda, int ldb, int ldc, int kch,
    size_t sA, size_t sB, size_t sC)
{
    extern __shared__ float sm[];
    const int tid = threadIdx.x;
    const int z = blockIdx.z;
    const int m0 = blockIdx.y * 128, n0 = blockIdx.x * 128;
    A += (size_t)z * sA + (size_t)m0 * lda;
    B += (size_t)z * sB + (size_t)n0 * ldb;
    C += (size_t)z * sC;
    float acc[4][4][4];
    #pragma unroll
    for (int mi = 0; mi < 4; mi++)
        #pragma unroll
        for (int ni = 0; ni < 4; ni++)
            #pragma unroll
            for (int e = 0; e < 4; e++) acc[mi][ni][e] = 0.f;
    mainloop128x128(A, B, lda, ldb, kch, sm, tid, acc);
    const int wid = tid >> 5, lane = tid & 31;
    const int gr = lane >> 2, gc = lane & 3;
    const int wm = wid >> 2, wn = wid & 3;
    #pragma unroll
    for (int mi = 0; mi < 4; mi++) {
        #pragma unroll
        for (int ni = 0; ni < 4; ni++) {
            int lr = m0 + wm*64 + mi*16 + gr;
            int lc = n0 + wn*32 + ni*8 + gc*2;
            const float* a = acc[mi][ni];
            *reinterpret_cast<float2*>(&C[(size_t)lr * ldc + lc]) = make_float2(a[0], a[1]);
            *reinterpret_cast<float2*>(&C[(size_t)(lr+8) * ldc + lc]) = make_float2(a[2], a[3]);
        }
    }
}

// ============ QKV GEMM with scatter epilogue (tf32-rounded outputs) ============
__global__ void __launch_bounds__(256, 2) qkv_tc_kernel(void) {
    extern __shared__ float sm[];
    const int tid = threadIdx.x;
    const int m0 = blockIdx.y * 128;        // over 32768 (b*1024+i)
    const int n0 = blockIdx.x * 128;        // over 1536
    const float* A = g_xt + (size_t)m0 * CDIM;
    const float* B = g_wqkvT + (size_t)n0 * CDIM;
    float acc[4][4][4];
    #pragma unroll
    for (int mi = 0; mi < 4; mi++)
        #pragma unroll
        for (int ni = 0; ni < 4; ni++)
            #pragma unroll
            for (int e = 0; e < 4; e++) acc[mi][ni][e] = 0.f;
    mainloop128x128(A, B, CDIM, CDIM, CDIM/32, sm, tid, acc);
    const int wid = tid >> 5, lane = tid & 31;
    const int gr = lane >> 2, gc = lane & 3;
    const int wm = wid >> 2, wn = wid & 3;
    #pragma unroll
    for (int mi = 0; mi < 4; mi++) {
        int m = m0 + wm*64 + mi*16 + gr;
        int b = m >> 10, i = m & 1023;
        #pragma unroll
        for (int ni = 0; ni < 4; ni++) {
            int n = n0 + wn*32 + ni*8 + gc*2;
            int which = n >> 9;
            int h = (n >> 6) & 7;
            int d = n & 63;
            int bh = b*8 + h;
            float* dst = (which == 0) ? g_q : ((which == 1) ? g_k : g_v);
            float sc = (which == 0) ? 0.125f : 1.0f;
            const float* a = acc[mi][ni];
            float r0 = cvt_tf32(a[0]*sc), r1 = cvt_tf32(a[1]*sc);
            float r2 = cvt_tf32(a[2]*sc), r3 = cvt_tf32(a[3]*sc);
            *reinterpret_cast<float2*>(&dst[((size_t)(bh*NTOK + i))*DH + d]) = make_float2(r0, r1);
            *reinterpret_cast<float2*>(&dst[((size_t)(bh*NTOK + i + 8))*DH + d]) = make_float2(r2, r3);
        }
    }
}

// ============ final GEMM: out = outf @ woutT^T + bias, transposed store (fp32) ============
__global__ void __launch_bounds__(256, 2) final_tc_kernel(
    const float* __restrict__ bias, float* __restrict__ out)
{
    extern __shared__ float sm[];
    const int tid = threadIdx.x;
    const int m0 = blockIdx.y * 128;        // over 32768
    const int n0 = blockIdx.x * 128;        // over 512
    const float* A = g_outf + (size_t)m0 * CDIM;
    const float* B = g_woutT + (size_t)n0 * CDIM;
    float acc[4][4][4];
    #pragma unroll
    for (int mi = 0; mi < 4; mi++)
        #pragma unroll
        for (int ni = 0; ni < 4; ni++)
            #pragma unroll
            for (int e = 0; e < 4; e++) acc[mi][ni][e] = 0.f;
    mainloop128x128(A, B, CDIM, CDIM, CDIM/32, sm, tid, acc);
    const int wid = tid >> 5, lane = tid & 31;
    const int gr = lane >> 2, gc = lane & 3;
    const int wm = wid >> 2, wn = wid & 3;
    #pragma unroll
    for (int mi = 0; mi < 4; mi++) {
        int m = m0 + wm*64 + mi*16 + gr;
        int b = m >> 10, i = m & 1023;
        #pragma unroll
        for (int ni = 0; ni < 4; ni++) {
            int n = n0 + wn*32 + ni*8 + gc*2;
            const float* a = acc[mi][ni];
            float b0 = bias[n], b1 = bias[n+1];
            out[((size_t)(b*CDIM + n))*NTOK + i]       = a[0] + b0;
            out[((size_t)(b*CDIM + n + 1))*NTOK + i]   = a[1] + b1;
            out[((size_t)(b*CDIM + n))*NTOK + i + 8]   = a[2] + b0;
            out[((size_t)(b*CDIM + n + 1))*NTOK + i + 8] = a[3] + b1;
        }
    }
}

// ============ 128x64 batched GEMM, B row-major [K,64]: C = A @ B ============
// warps 4x2 (warp tile 32x32), 256 threads, cp.async pipeline. Output tf32-rounded.
__global__ void __launch_bounds__(256, 2) gemm64_rowB_kernel(
    const float* __restrict__ A, const float* __restrict__ B, float* __restrict__ C,
    int lda, int kch, size_t sA, size_t sB, int flatC)
{
    extern __shared__ float sm[];
    const uint32_t sbase = (uint32_t)__cvta_generic_to_shared(sm);
    const int tid = threadIdx.x;
    const int wid = tid >> 5, lane = tid & 31;
    const int gr = lane >> 2, gc = lane & 3;
    const int wm = wid >> 1, wn = wid & 1;
    const int z = blockIdx.z;
    const int m0 = blockIdx.x * 128;
    A += (size_t)z * sA + (size_t)m0 * lda;
    B += (size_t)z * sB;
    if (flatC) C += (size_t)(z >> 3) * (NTOK*CDIM) + (size_t)(z & 7) * DH;
    else       C += (size_t)z * (ML*DH);

    int arow[4], ac4[4], bk[2], bn4[2];
    #pragma unroll
    for (int e = 0; e < 4; e++) {
        int f4 = e * 256 + tid;
        arow[e] = f4 >> 3;  ac4[e] = (f4 & 7) << 2;
    }
    #pragma unroll
    for (int e = 0; e < 2; e++) {
        int f4 = e * 256 + tid;
        bk[e] = f4 >> 4;  bn4[e] = (f4 & 15) << 2;
    }

    float acc[2][4][4];
    #pragma unroll
    for (int mi = 0; mi < 2; mi++)
        #pragma unroll
        for (int ni = 0; ni < 4; ni++)
            #pragma unroll
            for (int e = 0; e < 4; e++) acc[mi][ni][e] = 0.f;

    #pragma unroll
    for (int e = 0; e < 4; e++)
        cp16(sbase + (uint32_t)(arow[e]*PPITCH + ac4[e])*4,
             &A[(size_t)arow[e] * lda + ac4[e]]);
    #pragma unroll
    for (int e = 0; e < 2; e++)
        cp16(sbase + (uint32_t)(2*PSTAGE + bk[e]*BNP64 + bn4[e])*4,
             &B[(size_t)bk[e] * DH + bn4[e]]);
    CP_COMMIT();

    for (int c = 0; c < kch; c++) {
        const int st = c & 1;
        if (c + 1 < kch) {
            const int nst = st ^ 1;
            const int k0 = (c + 1) * 32;
            #pragma unroll
            for (int e = 0; e < 4; e++)
                cp16(sbase + (uint32_t)(nst*PSTAGE + arow[e]*PPITCH + ac4[e])*4,
                     &A[(size_t)arow[e] * lda + k0 + ac4[e]]);
            #pragma unroll
            for (int e = 0; e < 2; e++)
                cp16(sbase + (uint32_t)(2*PSTAGE + nst*BRSTG64 + bk[e]*BNP64 + bn4[e])*4,
                     &B[(size_t)(k0 + bk[e]) * DH + bn4[e]]);
            CP_COMMIT();
            CP_WAIT1();
        } else {
            CP_WAIT0();
        }
        __syncthreads();
        const float* Ab = sm + st*PSTAGE;
        const float* Bb = sm + 2*PSTAGE + st*BRSTG64;
        #pragma unroll
        for (int ks = 0; ks < 4; ks++) {
            uint32_t af[2][4];
            #pragma unroll
            for (int mi = 0; mi < 2; mi++) {
                int base = (wm*32 + mi*16 + gr)*PPITCH + ks*8 + gc;
                af[mi][0] = __float_as_uint(Ab[base]);
                af[mi][1] = __float_as_uint(Ab[base + 8*PPITCH]);
                af[mi][2] = __float_as_uint(Ab[base + 4]);
                af[mi][3] = __float_as_uint(Ab[base + 8*PPITCH + 4]);
            }
            uint32_t bf[4][2];
            #pragma unroll
            for (int ni = 0; ni < 4; ni++) {
                int n = wn*32 + ni*8 + gr;
                bf[ni][0] = __float_as_uint(Bb[(ks*8 + gc)*BNP64 + n]);
                bf[ni][1] = __float_as_uint(Bb[(ks*8 + gc + 4)*BNP64 + n]);
            }
            #pragma unroll
            for (int mi = 0; mi < 2; mi++)
                #pragma unroll
                for (int ni = 0; ni < 4; ni++)
                    mma_tf32_16x8x8(acc[mi][ni],
                        af[mi][0], af[mi][1], af[mi][2], af[mi][3],
                        bf[ni][0], bf[ni][1]);
        }
        __syncthreads();
    }

    #pragma unroll
    for (int mi = 0; mi < 2; mi++) {
        #pragma unroll
        for (int ni = 0; ni < 4; ni++) {
            int lr = m0 + wm*32 + mi*16 + gr;
            int lc = wn*32 + ni*8 + gc*2;
            const float* a = acc[mi][ni];
            float d0 = cvt_tf32(a[0]), d1 = cvt_tf32(a[1]);
            float d2 = cvt_tf32(a[2]), d3 = cvt_tf32(a[3]);
            int ldc = flatC ? CDIM : DH;
            *reinterpret_cast<float2*>(&C[(size_t)lr * ldc + lc]) = make_float2(d0, d1);
            *reinterpret_cast<float2*>(&C[(size_t)(lr+8) * ldc + lc]) = make_float2(d2, d3);
        }
    }
}

// ---------------- batched 2D transpose (tf32-rounded output) ----------------
__global__ void transpose_kernel(const float* __restrict__ in, float* __restrict__ out,
                                 int R, int C) {
    __shared__ float tile[32][33];
    const int z = blockIdx.z;
    in  += (size_t)z * R * C;
    out += (size_t)z * R * C;
    int c0 = blockIdx.x * 32, r0 = blockIdx.y * 32;
    int tx = threadIdx.x, ty = threadIdx.y;
    #pragma unroll
    for (int j = 0; j < 4; j++)
        tile[ty + j*8][tx] = in[(size_t)(r0 + ty + j*8) * C + c0 + tx];
    __syncthreads();
    #pragma unroll
    for (int j = 0; j < 4; j++)
        out[(size_t)(c0 + ty + j*8) * R + r0 + tx] = cvt_tf32(tile[tx][ty + j*8]);
}

// ================= pinv batched GEMM: Cn = c1*U + c2*(P @ Bk), B row-major =================
__global__ void __launch_bounds__(256, 2) pinv_mma_kernel(
    const float* __restrict__ P, const float* __restrict__ B,
    const float* __restrict__ U, float* __restrict__ Cn,
    float c1, float c2)
{
    extern __shared__ float sm[];
    const int tid = threadIdx.x;
    const int wid = tid >> 5, lane = tid & 31;
    const int wm = wid >> 2, wn = wid & 3;
    const int gr = lane >> 2, gc = lane & 3;
    const int tile = blockIdx.x;
    const int batch = tile >> 2;
    const int m0 = ((tile >> 1) & 1) << 7;
    const int n0 = (tile & 1) << 7;
    const size_t boff = (size_t)batch << 16;
    P += boff + (size_t)m0 * ML;
    B += boff + n0;                 // row-major [K=256][N=256], tile columns n0..n0+127
    if (U) U += boff;
    Cn += boff;

    float acc[4][4][4];
    #pragma unroll
    for (int mi = 0; mi < 4; mi++)
        #pragma unroll
        for (int ni = 0; ni < 4; ni++)
            #pragma unroll
            for (int e = 0; e < 4; e++) acc[mi][ni][e] = 0.f;
    mainloop128x128_rowB(P, B, ML, ML, 8, sm, tid, acc);

    #pragma unroll
    for (int mi = 0; mi < 4; mi++) {
        #pragma unroll
        for (int ni = 0; ni < 4; ni++) {
            int lr = wm*64 + mi*16 + gr;
            int lc = wn*32 + ni*8 + gc*2;
            int grow = m0 + lr, gcol = n0 + lc;
            const float* a = acc[mi][ni];
            float d0, d1, d2, d3;
            if (U) {
                float2 u0 = *reinterpret_cast<const float2*>(&U[(size_t)grow * ML + gcol]);
                float2 u1 = *reinterpret_cast<const float2*>(&U[(size_t)(grow+8) * ML + gcol]);
                d0 = c1*u0.x + c2*a[0]; d1 = c1*u0.y + c2*a[1];
                d2 = c1*u1.x + c2*a[2]; d3 = c1*u1.y + c2*a[3];
            } else {
                d0 = c2*a[0]; d1 = c2*a[1]; d2 = c2*a[2]; d3 = c2*a[3];
            }
            d0 = cvt_tf32(d0); d1 = cvt_tf32(d1); d2 = cvt_tf32(d2); d3 = cvt_tf32(d3);
            *reinterpret_cast<float2*>(&Cn[(size_t)grow * ML + gcol]) = make_float2(d0, d1);
            *reinterpret_cast<float2*>(&Cn[(size_t)(grow+8) * ML + gcol]) = make_float2(d2, d3);
        }
    }
}

// ---------------- landmark means (tf32-rounded) ----------------
__global__ void land_kernel() {
    int idx = blockIdx.x * blockDim.x + threadIdx.x;
    if (idx >= BHN*ML*DH) return;
    int d  = idx & 63;
    int j  = (idx >> 6) & 255;
    int bh = idx >> 14;
    size_t base = ((size_t)bh * NTOK + j*4) * DH + d;
    g_ql[idx] = cvt_tf32(0.25f * (g_q[base] + g_q[base+64] + g_q[base+128] + g_q[base+192]));
    g_kl[idx] = cvt_tf32(0.25f * (g_k[base] + g_k[base+64] + g_k[base+128] + g_k[base+192]));
}

// ---------------- row softmax (tf32-rounded output) ----------------
template<int W>
__global__ void softmax_kernel(float* __restrict__ data) {
    __shared__ float red[256];
    float* row = data + (size_t)blockIdx.x * W;
    int t = threadIdx.x;
    constexpr int PE = W / 256;
    float vals[PE];
    float mx = -1e30f;
    #pragma unroll
    for (int e = 0; e < PE; e++) { vals[e] = row[t + e*256]; mx = fmaxf(mx, vals[e]); }
    red[t] = mx; __syncthreads();
    #pragma unroll
    for (int s = 128; s > 0; s >>= 1) { if (t < s) red[t] = fmaxf(red[t], red[t+s]); __syncthreads(); }
    mx = red[0];
    __syncthreads();
    float sum = 0.f;
    #pragma unroll
    for (int e = 0; e < PE; e++) { vals[e] = expf(vals[e] - mx); sum += vals[e]; }
    red[t] = sum; __syncthreads();
    #pragma unroll
    for (int s = 128; s > 0; s >>= 1) { if (t < s) red[t] += red[t+s]; __syncthreads(); }
    float inv = 1.0f / red[0];
    #pragma unroll
    for (int e = 0; e < PE; e++) row[t + e*256] = cvt_tf32(vals[e] * inv);
}

// ---------------- pinv scale reductions ----------------
__global__ void reset_max_kernel() { if (threadIdx.x == 0) { g_colmax = 0u; g_rowmax = 0u; } }

__global__ void colmax_kernel() {
    int gw = (blockIdx.x * blockDim.x + threadIdx.x) >> 5;
    int lane = threadIdx.x & 31;
    if (gw >= BHN * ML) return;
    const float* row = g_attn2 + (size_t)gw * ML;
    float s = 0.f;
    #pragma unroll
    for (int j = lane; j < ML; j += 32) s += fabsf(row[j]);
    #pragma unroll
    for (int o = 16; o > 0; o >>= 1) s += __shfl_down_sync(0xffffffffu, s, o);
    if (lane == 0) atomicMax(&g_colmax, __float_as_uint(s));
}

__global__ void rowmax_kernel() {
    int idx = blockIdx.x * blockDim.x + threadIdx.x;
    if (idx >= BHN * ML) return;
    int bh = idx >> 8, j = idx & 255;
    const float* base = g_attn2 + (size_t)bh * ML * ML + j;
    float s = 0.f;
    for (int i = 0; i < ML; i++) s += fabsf(base[(size_t)i * ML]);
    atomicMax(&g_rowmax, __float_as_uint(s));
}

__global__ void zinit_kernel() {    // z = x^T * inv (tf32-rounded)
    float inv = 1.0f / (__uint_as_float(g_colmax) * __uint_as_float(g_rowmax));
    size_t idx = (size_t)blockIdx.x * 256 + threadIdx.x;
    int j  = idx & 255;
    int i  = (idx >> 8) & 255;
    size_t bh = idx >> 16;
    g_zA[idx] = cvt_tf32(g_attn2[(bh << 16) + ((size_t)j << 8) + i] * inv);
}

// ---------------- depthwise 33-tap conv residual (tf32-rounded add) ----------------
__global__ void res_add_kernel(const float* __restrict__ rk) {
    __shared__ float ker[KSZ];
    int blk = blockIdx.x;
    int bh = blk >> 8;
    int ichunk = blk & 255;
    int h = bh & 7, b = bh >> 3;
    if (threadIdx.x < KSZ) ker[threadIdx.x] = rk[h*KSZ + threadIdx.x];
    __syncthreads();
    int d = threadIdx.x & 63;
    int i = ichunk * 4 + (threadIdx.x >> 6);
    const float* vb = g_v + (size_t)bh * NTOK * DH;
    float s = 0.f;
    #pragma unroll
    for (int t = 0; t < KSZ; t++) {
        int ii = i + t - (KSZ/2);
        if (ii >= 0 && ii < NTOK) s += ker[t] * vb[(size_t)ii * DH + d];
    }
    size_t o = ((size_t)(b*NTOK + i)) * CDIM + h*64 + d;
    g_outf[o] = cvt_tf32(g_outf[o] + s);
}

// ---------------- host ----------------
extern "C" void kernel_launch(void* const* d_in, const int* in_sizes, int n_in,
                              void* d_out, int out_size) {
    const float* x     = (const float*)d_in[0];
    const float* w_qkv = (const float*)d_in[1];
    const float* w_out = (const float*)d_in[2];
    const float* b_out = (const float*)d_in[3];
    const float* rk    = (const float*)d_in[4];
    float* out = (float*)d_out;

    float *xt, *wqkvT, *woutT, *q, *k, *v, *ql, *kl, *a1, *a3, *a2;
    float *zA, *zB, *xz, *t1, *t2, *av, *bv, *outf;
    cudaGetSymbolAddress((void**)&xt, g_xt);
    cudaGetSymbolAddress((void**)&wqkvT, g_wqkvT);
    cudaGetSymbolAddress((void**)&woutT, g_woutT);
    cudaGetSymbolAddress((void**)&q,  g_q);
    cudaGetSymbolAddress((void**)&k,  g_k);
    cudaGetSymbolAddress((void**)&v,  g_v);
    cudaGetSymbolAddress((void**)&ql, g_ql);
    cudaGetSymbolAddress((void**)&kl, g_kl);
    cudaGetSymbolAddress((void**)&a1, g_attn1);
    cudaGetSymbolAddress((void**)&a3, g_attn3);
    cudaGetSymbolAddress((void**)&a2, g_attn2);
    cudaGetSymbolAddress((void**)&zA, g_zA);
    cudaGetSymbolAddress((void**)&zB, g_zB);
    cudaGetSymbolAddress((void**)&xz, g_xz);
    cudaGetSymbolAddress((void**)&t1, g_t1);
    cudaGetSymbolAddress((void**)&t2, g_t2);
    cudaGetSymbolAddress((void**)&av, g_av);
    cudaGetSymbolAddress((void**)&bv, g_bv);
    cudaGetSymbolAddress((void**)&outf, g_outf);

    cudaFuncSetAttribute(pinv_mma_kernel,    cudaFuncAttributeMaxDynamicSharedMemorySize, PB_SMEM);
    cudaFuncSetAttribute(gemm_tc_kernel,     cudaFuncAttributeMaxDynamicSharedMemorySize, G128_SMEM);
    cudaFuncSetAttribute(qkv_tc_kernel,      cudaFuncAttributeMaxDynamicSharedMemorySize, G128_SMEM);
    cudaFuncSetAttribute(final_tc_kernel,    cudaFuncAttributeMaxDynamicSharedMemorySize, G128_SMEM);
    cudaFuncSetAttribute(gemm64_rowB_kernel, cudaFuncAttributeMaxDynamicSharedMemorySize, G64R_SMEM);

    // 0) layout prep: xT, wqkvT, woutT (tf32-rounded)
    transpose_kernel<<<dim3(NTOK/32, CDIM/32, BATCH), dim3(32,8)>>>(x, xt, CDIM, NTOK);
    transpose_kernel<<<dim3(48, 16, 1), dim3(32,8)>>>(w_qkv, wqkvT, CDIM, 3*CDIM);
    transpose_kernel<<<dim3(16, 16, 1), dim3(32,8)>>>(w_out, woutT, CDIM, CDIM);
    // 1) QKV projection (32768 x 1536 x 512) + scatter to q/k/v
    qkv_tc_kernel<<<dim3(12, 256), 256, G128_SMEM>>>();
    // 2) landmarks
    land_kernel<<<(BHN*ML*DH + 255)/256, 256>>>();
    // 3) similarity GEMMs (batched, tf32, B K-major)
    gemm_tc_kernel<<<dim3(2, 8, BHN), 256, G128_SMEM>>>(q,  kl, a1, DH, DH, ML,   2,
        (size_t)NTOK*DH, (size_t)ML*DH, (size_t)NTOK*ML);                   // sim1
    gemm_tc_kernel<<<dim3(2, 2, BHN), 256, G128_SMEM>>>(ql, kl, a2, DH, DH, ML,   2,
        (size_t)ML*DH,   (size_t)ML*DH, (size_t)ML*ML);                     // sim2
    gemm_tc_kernel<<<dim3(8, 2, BHN), 256, G128_SMEM>>>(ql, k,  a3, DH, DH, NTOK, 2,
        (size_t)ML*DH,   (size_t)NTOK*DH, (size_t)ML*NTOK);                 // sim3
    // 4) softmaxes (tf32-rounded outputs)
    softmax_kernel<256> <<<BHN*NTOK, 256>>>(a1);
    softmax_kernel<256> <<<BHN*ML,   256>>>(a2);
    softmax_kernel<1024><<<BHN*ML,   256>>>(a3);
    // 5) pinv init
    reset_max_kernel<<<1, 32>>>();
    colmax_kernel<<<(BHN*ML*32)/256, 256>>>();
    rowmax_kernel<<<(BHN*ML)/256, 256>>>();
    zinit_kernel<<<(BHN*ML*ML)/256, 256>>>();
    // 6) 6 Newton–Schulz iterations, all GEMMs C = A @ B with B row-major
    float *zin = zA, *zout = zB;
    for (int it = 0; it < 6; it++) {
        pinv_mma_kernel<<<1024, 256, PB_SMEM>>>(a2, zin, nullptr, xz, 0.0f, 1.0f);  // xz = x@z
        pinv_mma_kernel<<<1024, 256, PB_SMEM>>>(xz, xz, xz, t1, 7.0f, -1.0f);       // t1 = 7xz - xz@xz
        pinv_mma_kernel<<<1024, 256, PB_SMEM>>>(xz, t1, xz, t2, 15.0f, -1.0f);      // t2 = 15xz - xz@t1
        pinv_mma_kernel<<<1024, 256, PB_SMEM>>>(zin, t2, zin, zout, 3.25f, -0.25f); // z' = 3.25z - 0.25 z@t2
        float* tmp = zin; zin = zout; zout = tmp;
    }
    // 7) output chain (B row-major everywhere): av = attn3@v ; bv = z@av ; outf = attn1@bv
    gemm64_rowB_kernel<<<dim3(2, 1, BHN), 256, G64R_SMEM>>>(a3, v, av,
        NTOK, 32, (size_t)ML*NTOK, (size_t)NTOK*DH, 0);
    gemm64_rowB_kernel<<<dim3(2, 1, BHN), 256, G64R_SMEM>>>(zin, av, bv,
        ML, 8, (size_t)ML*ML, (size_t)ML*DH, 0);
    gemm64_rowB_kernel<<<dim3(8, 1, BHN), 256, G64R_SMEM>>>(a1, bv, outf,
        ML, 8, (size_t)NTOK*ML, (size_t)ML*DH, 1);
    // 8) depthwise conv residual (rounds outf for final GEMM)
    res_add_kernel<<<BHN*256, 256>>>(rk);
    // 9) output projection + bias + transposed store (fp32)
    final_tc_kernel<<<dim3(4, 256), 256, G128_SMEM>>>(b_out, out);
}

// round 8
// speedup vs baseline: 2.9269x; 1.0224x over previous
#include <cuda_runtime.h>
#include <cstdint>
#include <cstddef>

#define BATCH 32
#define HEADS 8
#define NTOK 1024
#define DH 64
#define ML 256          // landmarks
#define CDIM 512
#define BHN (BATCH*HEADS)   // 256
#define KSZ 33

// ---------------- device scratch ----------------
__device__ float g_xt[(size_t)BATCH*NTOK*CDIM];     // x transposed: (b, n, c), tf32-rounded
__device__ float g_wqkvT[3*CDIM*CDIM];              // (1536, 512), tf32-rounded
__device__ float g_woutT[CDIM*CDIM];                // (512, 512), tf32-rounded
__device__ float g_q [BHN*NTOK*DH];
__device__ float g_k [BHN*NTOK*DH];
__device__ float g_v [BHN*NTOK*DH];
__device__ float g_ql[BHN*ML*DH];
__device__ float g_kl[BHN*ML*DH];
__device__ float g_attn1[(size_t)BHN*NTOK*ML];      // (bh,1024,256)
__device__ float g_attn3[(size_t)BHN*ML*NTOK];      // (bh,256,1024)
__device__ float g_attn2[BHN*ML*ML];
__device__ float g_zA[BHN*ML*ML];
__device__ float g_zB[BHN*ML*ML];
__device__ float g_xz[BHN*ML*ML];
__device__ float g_t1[BHN*ML*ML];
__device__ float g_t2[BHN*ML*ML];
__device__ float g_av[BHN*ML*DH];
__device__ float g_bv[BHN*ML*DH];
__device__ float g_outf[(size_t)BATCH*NTOK*CDIM];   // (b, n, 512)
__device__ unsigned g_colmax;
__device__ unsigned g_rowmax;

// ================= tf32 helpers =================
__device__ __forceinline__ float cvt_tf32(float x) {
    uint32_t u;
    asm("cvt.rna.tf32.f32 %0, %1;" : "=r"(u) : "f"(x));
    return __uint_as_float(u);
}
__device__ __forceinline__ void mma_tf32_16x8x8(float c[4],
    uint32_t a0, uint32_t a1, uint32_t a2, uint32_t a3, uint32_t b0, uint32_t b1) {
    asm volatile(
        "mma.sync.aligned.m16n8k8.row.col.f32.tf32.tf32.f32 "
        "{%0,%1,%2,%3},{%4,%5,%6,%7},{%8,%9},{%0,%1,%2,%3};"
        : "+f"(c[0]), "+f"(c[1]), "+f"(c[2]), "+f"(c[3])
        : "r"(a0), "r"(a1), "r"(a2), "r"(a3), "r"(b0), "r"(b1));
}
__device__ __forceinline__ void cp16(uint32_t dst, const float* src) {
    asm volatile("cp.async.cg.shared.global [%0], [%1], 16;" :: "r"(dst), "l"(src));
}
#define CP_COMMIT() asm volatile("cp.async.commit_group;")
#define CP_WAIT1()  asm volatile("cp.async.wait_group 1;" ::: "memory")
#define CP_WAIT0()  asm volatile("cp.async.wait_group 0;" ::: "memory")

#define PPITCH 36
#define PSTAGE (128*PPITCH)
// 3-stage layouts: A stages at [0, 3*PSTAGE), B stages follow.
#define G128_SMEM3 (6*PSTAGE*4)                     // 110592 (A,B both K-major)

#define BNP128 136
#define BRSTG128 (32*BNP128)                        // 4352 floats
#define PB_SMEM3 ((3*PSTAGE + 3*BRSTG128)*4)        // 107520

#define BNP64 72
#define BRSTG64 (32*BNP64)                          // 2304 floats
#define G64R_SMEM3 ((3*PSTAGE + 3*BRSTG64)*4)       // 82944

// ============ mainloop A: B stored K-major ([N rows][K]) — sims/qkv/final ============
// 3-stage cp.async pipeline, one __syncthreads per chunk.
__device__ __forceinline__ void mainloop128x128(
    const float* __restrict__ A, const float* __restrict__ B,
    int lda, int ldb, int kch, float* sm, int tid, float acc[4][4][4])
{
    const uint32_t sbase = (uint32_t)__cvta_generic_to_shared(sm);
    const uint32_t bbase = sbase + 3*PSTAGE*4;
    const int wid = tid >> 5, lane = tid & 31;
    const int gr = lane >> 2, gc = lane & 3;
    const int wm = wid >> 2, wn = wid & 3;
    int rrow[4], rc4[4];
    #pragma unroll
    for (int e = 0; e < 4; e++) {
        int f4 = e * 256 + tid;
        rrow[e] = f4 >> 3;
        rc4[e] = (f4 & 7) << 2;
    }
    // prologue: chunks 0, 1
    #pragma unroll
    for (int p = 0; p < 2; p++) {
        if (p < kch) {
            const int k0 = p * 32;
            #pragma unroll
            for (int e = 0; e < 4; e++) {
                cp16(sbase + (uint32_t)(p*PSTAGE + rrow[e]*PPITCH + rc4[e])*4,
                     &A[(size_t)rrow[e] * lda + k0 + rc4[e]]);
                cp16(bbase + (uint32_t)(p*PSTAGE + rrow[e]*PPITCH + rc4[e])*4,
                     &B[(size_t)rrow[e] * ldb + k0 + rc4[e]]);
            }
        }
        CP_COMMIT();
    }
    for (int c = 0; c < kch; c++) {
        const int st = c % 3;
        if (c + 1 < kch) { CP_WAIT1(); } else { CP_WAIT0(); }
        __syncthreads();
        if (c + 2 < kch) {
            const int nst = (c + 2) % 3;
            const int k0 = (c + 2) * 32;
            #pragma unroll
            for (int e = 0; e < 4; e++) {
                cp16(sbase + (uint32_t)(nst*PSTAGE + rrow[e]*PPITCH + rc4[e])*4,
                     &A[(size_t)rrow[e] * lda + k0 + rc4[e]]);
                cp16(bbase + (uint32_t)(nst*PSTAGE + rrow[e]*PPITCH + rc4[e])*4,
                     &B[(size_t)rrow[e] * ldb + k0 + rc4[e]]);
            }
            CP_COMMIT();
        }
        const float* Ab = sm + st*PSTAGE;
        const float* Bb = sm + (3+st)*PSTAGE;
        #pragma unroll
        for (int ks = 0; ks < 4; ks++) {
            uint32_t af[4][4];
            #pragma unroll
            for (int mi = 0; mi < 4; mi++) {
                int base = (wm*64 + mi*16 + gr)*PPITCH + ks*8 + gc;
                af[mi][0] = __float_as_uint(Ab[base]);
                af[mi][1] = __float_as_uint(Ab[base + 8*PPITCH]);
                af[mi][2] = __float_as_uint(Ab[base + 4]);
                af[mi][3] = __float_as_uint(Ab[base + 8*PPITCH + 4]);
            }
            uint32_t bf[4][2];
            #pragma unroll
            for (int ni = 0; ni < 4; ni++) {
                int base = (wn*32 + ni*8 + gr)*PPITCH + ks*8 + gc;
                bf[ni][0] = __float_as_uint(Bb[base]);
                bf[ni][1] = __float_as_uint(Bb[base + 4]);
            }
            #pragma unroll
            for (int mi = 0; mi < 4; mi++)
                #pragma unroll
                for (int ni = 0; ni < 4; ni++)
                    mma_tf32_16x8x8(acc[mi][ni],
                        af[mi][0], af[mi][1], af[mi][2], af[mi][3],
                        bf[ni][0], bf[ni][1]);
        }
    }
}

// ============ mainloop B: B stored row-major [K][N] — pinv/chain ============
__device__ __forceinline__ void mainloop128x128_rowB(
    const float* __restrict__ A, const float* __restrict__ B,
    int lda, int ldb, int kch, float* sm, int tid, float acc[4][4][4])
{
    const uint32_t sbase = (uint32_t)__cvta_generic_to_shared(sm);
    const uint32_t bbase = sbase + 3*PSTAGE*4;
    const int wid = tid >> 5, lane = tid & 31;
    const int gr = lane >> 2, gc = lane & 3;
    const int wm = wid >> 2, wn = wid & 3;
    int arow[4], ac4[4], bk[4], bn4[4];
    #pragma unroll
    for (int e = 0; e < 4; e++) {
        int f4 = e * 256 + tid;
        arow[e] = f4 >> 3;  ac4[e] = (f4 & 7) << 2;
        bk[e]   = f4 >> 5;  bn4[e] = (f4 & 31) << 2;
    }
    #pragma unroll
    for (int p = 0; p < 2; p++) {
        if (p < kch) {
            const int k0 = p * 32;
            #pragma unroll
            for (int e = 0; e < 4; e++) {
                cp16(sbase + (uint32_t)(p*PSTAGE + arow[e]*PPITCH + ac4[e])*4,
                     &A[(size_t)arow[e] * lda + k0 + ac4[e]]);
                cp16(bbase + (uint32_t)(p*BRSTG128 + bk[e]*BNP128 + bn4[e])*4,
                     &B[(size_t)(k0 + bk[e]) * ldb + bn4[e]]);
            }
        }
        CP_COMMIT();
    }
    for (int c = 0; c < kch; c++) {
        const int st = c % 3;
        if (c + 1 < kch) { CP_WAIT1(); } else { CP_WAIT0(); }
        __syncthreads();
        if (c + 2 < kch) {
            const int nst = (c + 2) % 3;
            const int k0 = (c + 2) * 32;
            #pragma unroll
            for (int e = 0; e < 4; e++) {
                cp16(sbase + (uint32_t)(nst*PSTAGE + arow[e]*PPITCH + ac4[e])*4,
                     &A[(size_t)arow[e] * lda + k0 + ac4[e]]);
                cp16(bbase + (uint32_t)(nst*BRSTG128 + bk[e]*BNP128 + bn4[e])*4,
                     &B[(size_t)(k0 + bk[e]) * ldb + bn4[e]]);
            }
            CP_COMMIT();
        }
        const float* Ab = sm + st*PSTAGE;
        const float* Bb = sm + 3*PSTAGE + st*BRSTG128;
        #pragma unroll
        for (int ks = 0; ks < 4; ks++) {
            uint32_t af[4][4];
            #pragma unroll
            for (int mi = 0; mi < 4; mi++) {
                int base = (wm*64 + mi*16 + gr)*PPITCH + ks*8 + gc;
                af[mi][0] = __float_as_uint(Ab[base]);
                af[mi][1] = __float_as_uint(Ab[base + 8*PPITCH]);
                af[mi][2] = __float_as_uint(Ab[base + 4]);
                af[mi][3] = __float_as_uint(Ab[base + 8*PPITCH + 4]);
            }
            uint32_t bf[4][2];
            #pragma unroll
            for (int ni = 0; ni < 4; ni++) {
                int n = wn*32 + ni*8 + gr;
                bf[ni][0] = __float_as_uint(Bb[(ks*8 + gc)*BNP128 + n]);
                bf[ni][1] = __float_as_uint(Bb[(ks*8 + gc + 4)*BNP128 + n]);
            }
            #pragma unroll
            for (int mi = 0; mi < 4; mi++)
                #pragma unroll
                for (int ni = 0; ni < 4; ni++)
                    mma_tf32_16x8x8(acc[mi][ni],
                        af[mi][0], af[mi][1], af[mi][2], af[mi][3],
                        bf[ni][0], bf[ni][1]);
        }
    }
}

// ============ plain batched GEMM: C[z] = A[z] @ B[z]^T (B K-major; sims) ============
__global__ void __launch_bounds__(256, 2) gemm_tc_kernel(
    const float* __restrict__ A, const float* __restrict__ B, float* __restrict__ C,
    int lda, int ldb, int ldc, int kch,
    size_t sA, size_t sB, size_t sC)
{
    extern __shared__ float sm[];
    const int tid = threadIdx.x;
    const int z = blockIdx.z;
    const int m0 = blockIdx.y * 128, n0 = blockIdx.x * 128;
    A += (size_t)z * sA + (size_t)m0 * lda;
    B += (size_t)z * sB + (size_t)n0 * ldb;
    C += (size_t)z * sC;
    float acc[4][4][4];
    #pragma unroll
    for (int mi = 0; mi < 4; mi++)
        #pragma unroll
        for (int ni = 0; ni < 4; ni++)
            #pragma unroll
            for (int e = 0; e < 4; e++) acc[mi][ni][e] = 0.f;
    mainloop128x128(A, B, lda, ldb, kch, sm, tid, acc);
    const int wid = tid >> 5, lane = tid & 31;
    const int gr = lane >> 2, gc = lane & 3;
    const int wm = wid >> 2, wn = wid & 3;
    #pragma unroll
    for (int mi = 0; mi < 4; mi++) {
        #pragma unroll
        for (int ni = 0; ni < 4; ni++) {
            int lr = m0 + wm*64 + mi*16 + gr;
            int lc = n0 + wn*32 + ni*8 + gc*2;
            const float* a = acc[mi][ni];
            *reinterpret_cast<float2*>(&C[(size_t)lr * ldc + lc]) = make_float2(a[0], a[1]);
            *reinterpret_cast<float2*>(&C[(size_t)(lr+8) * ldc + lc]) = make_float2(a[2], a[3]);
        }
    }
}

// ============ QKV GEMM with scatter epilogue (tf32-rounded outputs) ============
__global__ void __launch_bounds__(256, 2) qkv_tc_kernel(void) {
    extern __shared__ float sm[];
    const int tid = threadIdx.x;
    const int m0 = blockIdx.y * 128;        // over 32768 (b*1024+i)
    const int n0 = blockIdx.x * 128;        // over 1536
    const float* A = g_xt + (size_t)m0 * CDIM;
    const float* B = g_wqkvT + (size_t)n0 * CDIM;
    float acc[4][4][4];
    #pragma unroll
    for (int mi = 0; mi < 4; mi++)
        #pragma unroll
        for (int ni = 0; ni < 4; ni++)
            #pragma unroll
            for (int e = 0; e < 4; e++) acc[mi][ni][e] = 0.f;
    mainloop128x128(A, B, CDIM, CDIM, CDIM/32, sm, tid, acc);
    const int wid = tid >> 5, lane = tid & 31;
    const int gr = lane >> 2, gc = lane & 3;
    const int wm = wid >> 2, wn = wid & 3;
    #pragma unroll
    for (int mi = 0; mi < 4; mi++) {
        int m = m0 + wm*64 + mi*16 + gr;
        int b = m >> 10, i = m & 1023;
        #pragma unroll
        for (int ni = 0; ni < 4; ni++) {
            int n = n0 + wn*32 + ni*8 + gc*2;
            int which = n >> 9;
            int h = (n >> 6) & 7;
            int d = n & 63;
            int bh = b*8 + h;
            float* dst = (which == 0) ? g_q : ((which == 1) ? g_k : g_v);
            float sc = (which == 0) ? 0.125f : 1.0f;
            const float* a = acc[mi][ni];
            float r0 = cvt_tf32(a[0]*sc), r1 = cvt_tf32(a[1]*sc);
            float r2 = cvt_tf32(a[2]*sc), r3 = cvt_tf32(a[3]*sc);
            *reinterpret_cast<float2*>(&dst[((size_t)(bh*NTOK + i))*DH + d]) = make_float2(r0, r1);
            *reinterpret_cast<float2*>(&dst[((size_t)(bh*NTOK + i + 8))*DH + d]) = make_float2(r2, r3);
        }
    }
}

// ============ final GEMM: out = outf @ woutT^T + bias, transposed store (fp32) ============
__global__ void __launch_bounds__(256, 2) final_tc_kernel(
    const float* __restrict__ bias, float* __restrict__ out)
{
    extern __shared__ float sm[];
    const int tid = threadIdx.x;
    const int m0 = blockIdx.y * 128;        // over 32768
    const int n0 = blockIdx.x * 128;        // over 512
    const float* A = g_outf + (size_t)m0 * CDIM;
    const float* B = g_woutT + (size_t)n0 * CDIM;
    float acc[4][4][4];
    #pragma unroll
    for (int mi = 0; mi < 4; mi++)
        #pragma unroll
        for (int ni = 0; ni < 4; ni++)
            #pragma unroll
            for (int e = 0; e < 4; e++) acc[mi][ni][e] = 0.f;
    mainloop128x128(A, B, CDIM, CDIM, CDIM/32, sm, tid, acc);
    const int wid = tid >> 5, lane = tid & 31;
    const int gr = lane >> 2, gc = lane & 3;
    const int wm = wid >> 2, wn = wid & 3;
    #pragma unroll
    for (int mi = 0; mi < 4; mi++) {
        int m = m0 + wm*64 + mi*16 + gr;
        int b = m >> 10, i = m & 1023;
        #pragma unroll
        for (int ni = 0; ni < 4; ni++) {
            int n = n0 + wn*32 + ni*8 + gc*2;
            const float* a = acc[mi][ni];
            float b0 = bias[n], b1 = bias[n+1];
            out[((size_t)(b*CDIM + n))*NTOK + i]       = a[0] + b0;
            out[((size_t)(b*CDIM + n + 1))*NTOK + i]   = a[1] + b1;
            out[((size_t)(b*CDIM + n))*NTOK + i + 8]   = a[2] + b0;
            out[((size_t)(b*CDIM + n + 1))*NTOK + i + 8] = a[3] + b1;
        }
    }
}

// ============ 128x64 batched GEMM, B row-major [K,64]: C = A @ B ============
// warps 4x2 (warp tile 32x32), 256 threads, 3-stage cp.async. Output tf32-rounded.
__global__ void __launch_bounds__(256, 2) gemm64_rowB_kernel(
    const float* __restrict__ A, const float* __restrict__ B, float* __restrict__ C,
    int lda, int kch, size_t sA, size_t sB, int flatC)
{
    extern __shared__ float sm[];
    const uint32_t sbase = (uint32_t)__cvta_generic_to_shared(sm);
    const uint32_t bbase = sbase + 3*PSTAGE*4;
    const int tid = threadIdx.x;
    const int wid = tid >> 5, lane = tid & 31;
    const int gr = lane >> 2, gc = lane & 3;
    const int wm = wid >> 1, wn = wid & 1;
    const int z = blockIdx.z;
    const int m0 = blockIdx.x * 128;
    A += (size_t)z * sA + (size_t)m0 * lda;
    B += (size_t)z * sB;
    if (flatC) C += (size_t)(z >> 3) * (NTOK*CDIM) + (size_t)(z & 7) * DH;
    else       C += (size_t)z * (ML*DH);

    int arow[4], ac4[4], bk[2], bn4[2];
    #pragma unroll
    for (int e = 0; e < 4; e++) {
        int f4 = e * 256 + tid;
        arow[e] = f4 >> 3;  ac4[e] = (f4 & 7) << 2;
    }
    #pragma unroll
    for (int e = 0; e < 2; e++) {
        int f4 = e * 256 + tid;
        bk[e] = f4 >> 4;  bn4[e] = (f4 & 15) << 2;
    }

    float acc[2][4][4];
    #pragma unroll
    for (int mi = 0; mi < 2; mi++)
        #pragma unroll
        for (int ni = 0; ni < 4; ni++)
            #pragma unroll
            for (int e = 0; e < 4; e++) acc[mi][ni][e] = 0.f;

    #pragma unroll
    for (int p = 0; p < 2; p++) {
        if (p < kch) {
            const int k0 = p * 32;
            #pragma unroll
            for (int e = 0; e < 4; e++)
                cp16(sbase + (uint32_t)(p*PSTAGE + arow[e]*PPITCH + ac4[e])*4,
                     &A[(size_t)arow[e] * lda + k0 + ac4[e]]);
            #pragma unroll
            for (int e = 0; e < 2; e++)
                cp16(bbase + (uint32_t)(p*BRSTG64 + bk[e]*BNP64 + bn4[e])*4,
                     &B[(size_t)(k0 + bk[e]) * DH + bn4[e]]);
        }
        CP_COMMIT();
    }

    for (int c = 0; c < kch; c++) {
        const int st = c % 3;
        if (c + 1 < kch) { CP_WAIT1(); } else { CP_WAIT0(); }
        __syncthreads();
        if (c + 2 < kch) {
            const int nst = (c + 2) % 3;
            const int k0 = (c + 2) * 32;
            #pragma unroll
            for (int e = 0; e < 4; e++)
                cp16(sbase + (uint32_t)(nst*PSTAGE + arow[e]*PPITCH + ac4[e])*4,
                     &A[(size_t)arow[e] * lda + k0 + ac4[e]]);
            #pragma unroll
            for (int e = 0; e < 2; e++)
                cp16(bbase + (uint32_t)(nst*BRSTG64 + bk[e]*BNP64 + bn4[e])*4,
                     &B[(size_t)(k0 + bk[e]) * DH + bn4[e]]);
            CP_COMMIT();
        }
        const float* Ab = sm + st*PSTAGE;
        const float* Bb = sm + 3*PSTAGE + st*BRSTG64;
        #pragma unroll
        for (int ks = 0; ks < 4; ks++) {
            uint32_t af[2][4];
            #pragma unroll
            for (int mi = 0; mi < 2; mi++) {
                int base = (wm*32 + mi*16 + gr)*PPITCH + ks*8 + gc;
                af[mi][0] = __float_as_uint(Ab[base]);
                af[mi][1] = __float_as_uint(Ab[base + 8*PPITCH]);
                af[mi][2] = __float_as_uint(Ab[base + 4]);
                af[mi][3] = __float_as_uint(Ab[base + 8*PPITCH + 4]);
            }
            uint32_t bf[4][2];
            #pragma unroll
            for (int ni = 0; ni < 4; ni++) {
                int n = wn*32 + ni*8 + gr;
                bf[ni][0] = __float_as_uint(Bb[(ks*8 + gc)*BNP64 + n]);
                bf[ni][1] = __float_as_uint(Bb[(ks*8 + gc + 4)*BNP64 + n]);
            }
            #pragma unroll
            for (int mi = 0; mi < 2; mi++)
                #pragma unroll
                for (int ni = 0; ni < 4; ni++)
                    mma_tf32_16x8x8(acc[mi][ni],
                        af[mi][0], af[mi][1], af[mi][2], af[mi][3],
                        bf[ni][0], bf[ni][1]);
        }
    }

    #pragma unroll
    for (int mi = 0; mi < 2; mi++) {
        #pragma unroll
        for (int ni = 0; ni < 4; ni++) {
            int lr = m0 + wm*32 + mi*16 + gr;
            int lc = wn*32 + ni*8 + gc*2;
            const float* a = acc[mi][ni];
            float d0 = cvt_tf32(a[0]), d1 = cvt_tf32(a[1]);
            float d2 = cvt_tf32(a[2]), d3 = cvt_tf32(a[3]);
            int ldc = flatC ? CDIM : DH;
            *reinterpret_cast<float2*>(&C[(size_t)lr * ldc + lc]) = make_float2(d0, d1);
            *reinterpret_cast<float2*>(&C[(size_t)(lr+8) * ldc + lc]) = make_float2(d2, d3);
        }
    }
}

// ---------------- batched 2D transpose (tf32-rounded output) ----------------
__global__ void transpose_kernel(const float* __restrict__ in, float* __restrict__ out,
                                 int R, int C) {
    __shared__ float tile[32][33];
    const int z = blockIdx.z;
    in  += (size_t)z * R * C;
    out += (size_t)z * R * C;
    int c0 = blockIdx.x * 32, r0 = blockIdx.y * 32;
    int tx = threadIdx.x, ty = threadIdx.y;
    #pragma unroll
    for (int j = 0; j < 4; j++)
        tile[ty + j*8][tx] = in[(size_t)(r0 + ty + j*8) * C + c0 + tx];
    __syncthreads();
    #pragma unroll
    for (int j = 0; j < 4; j++)
        out[(size_t)(c0 + ty + j*8) * R + r0 + tx] = cvt_tf32(tile[tx][ty + j*8]);
}

// ================= pinv batched GEMM: Cn = c1*U + c2*(P @ B), B row-major =================
__global__ void __launch_bounds__(256, 2) pinv_mma_kernel(
    const float* __restrict__ P, const float* __restrict__ B,
    const float* __restrict__ U, float* __restrict__ Cn,
    float c1, float c2)
{
    extern __shared__ float sm[];
    const int tid = threadIdx.x;
    const int wid = tid >> 5, lane = tid & 31;
    const int wm = wid >> 2, wn = wid & 3;
    const int gr = lane >> 2, gc = lane & 3;
    const int tile = blockIdx.x;
    const int batch = tile >> 2;
    const int m0 = ((tile >> 1) & 1) << 7;
    const int n0 = (tile & 1) << 7;
    const size_t boff = (size_t)batch << 16;
    P += boff + (size_t)m0 * ML;
    B += boff + n0;                 // row-major [K=256][N=256], tile columns n0..n0+127
    if (U) U += boff;
    Cn += boff;

    float acc[4][4][4];
    #pragma unroll
    for (int mi = 0; mi < 4; mi++)
        #pragma unroll
        for (int ni = 0; ni < 4; ni++)
            #pragma unroll
            for (int e = 0; e < 4; e++) acc[mi][ni][e] = 0.f;
    mainloop128x128_rowB(P, B, ML, ML, 8, sm, tid, acc);

    #pragma unroll
    for (int mi = 0; mi < 4; mi++) {
        #pragma unroll
        for (int ni = 0; ni < 4; ni++) {
            int lr = wm*64 + mi*16 + gr;
            int lc = wn*32 + ni*8 + gc*2;
            int grow = m0 + lr, gcol = n0 + lc;
            const float* a = acc[mi][ni];
            float d0, d1, d2, d3;
            if (U) {
                float2 u0 = *reinterpret_cast<const float2*>(&U[(size_t)grow * ML + gcol]);
                float2 u1 = *reinterpret_cast<const float2*>(&U[(size_t)(grow+8) * ML + gcol]);
                d0 = c1*u0.x + c2*a[0]; d1 = c1*u0.y + c2*a[1];
                d2 = c1*u1.x + c2*a[2]; d3 = c1*u1.y + c2*a[3];
            } else {
                d0 = c2*a[0]; d1 = c2*a[1]; d2 = c2*a[2]; d3 = c2*a[3];
            }
            d0 = cvt_tf32(d0); d1 = cvt_tf32(d1); d2 = cvt_tf32(d2); d3 = cvt_tf32(d3);
            *reinterpret_cast<float2*>(&Cn[(size_t)grow * ML + gcol]) = make_float2(d0, d1);
            *reinterpret_cast<float2*>(&Cn[(size_t)(grow+8) * ML + gcol]) = make_float2(d2, d3);
        }
    }
}

// ---------------- landmark means (tf32-rounded) ----------------
__global__ void land_kernel() {
    int idx = blockIdx.x * blockDim.x + threadIdx.x;
    if (idx >= BHN*ML*DH) return;
    int d  = idx & 63;
    int j  = (idx >> 6) & 255;
    int bh = idx >> 14;
    size_t base = ((size_t)bh * NTOK + j*4) * DH + d;
    g_ql[idx] = cvt_tf32(0.25f * (g_q[base] + g_q[base+64] + g_q[base+128] + g_q[base+192]));
    g_kl[idx] = cvt_tf32(0.25f * (g_k[base] + g_k[base+64] + g_k[base+128] + g_k[base+192]));
}

// ---------------- row softmax (tf32-rounded output) ----------------
template<int W>
__global__ void softmax_kernel(float* __restrict__ data) {
    __shared__ float red[256];
    float* row = data + (size_t)blockIdx.x * W;
    int t = threadIdx.x;
    constexpr int PE = W / 256;
    float vals[PE];
    float mx = -1e30f;
    #pragma unroll
    for (int e = 0; e < PE; e++) { vals[e] = row[t + e*256]; mx = fmaxf(mx, vals[e]); }
    red[t] = mx; __syncthreads();
    #pragma unroll
    for (int s = 128; s > 0; s >>= 1) { if (t < s) red[t] = fmaxf(red[t], red[t+s]); __syncthreads(); }
    mx = red[0];
    __syncthreads();
    float sum = 0.f;
    #pragma unroll
    for (int e = 0; e < PE; e++) { vals[e] = expf(vals[e] - mx); sum += vals[e]; }
    red[t] = sum; __syncthreads();
    #pragma unroll
    for (int s = 128; s > 0; s >>= 1) { if (t < s) red[t] += red[t+s]; __syncthreads(); }
    float inv = 1.0f / red[0];
    #pragma unroll
    for (int e = 0; e < PE; e++) row[t + e*256] = cvt_tf32(vals[e] * inv);
}

// ---------------- pinv scale reductions ----------------
__global__ void reset_max_kernel() { if (threadIdx.x == 0) { g_colmax = 0u; g_rowmax = 0u; } }

__global__ void colmax_kernel() {
    int gw = (blockIdx.x * blockDim.x + threadIdx.x) >> 5;
    int lane = threadIdx.x & 31;
    if (gw >= BHN * ML) return;
    const float* row = g_attn2 + (size_t)gw * ML;
    float s = 0.f;
    #pragma unroll
    for (int j = lane; j < ML; j += 32) s += fabsf(row[j]);
    #pragma unroll
    for (int o = 16; o > 0; o >>= 1) s += __shfl_down_sync(0xffffffffu, s, o);
    if (lane == 0) atomicMax(&g_colmax, __float_as_uint(s));
}

__global__ void rowmax_kernel() {
    int idx = blockIdx.x * blockDim.x + threadIdx.x;
    if (idx >= BHN * ML) return;
    int bh = idx >> 8, j = idx & 255;
    const float* base = g_attn2 + (size_t)bh * ML * ML + j;
    float s = 0.f;
    for (int i = 0; i < ML; i++) s += fabsf(base[(size_t)i * ML]);
    atomicMax(&g_rowmax, __float_as_uint(s));
}

__global__ void zinit_kernel() {    // z = x^T * inv (tf32-rounded)
    float inv = 1.0f / (__uint_as_float(g_colmax) * __uint_as_float(g_rowmax));
    size_t idx = (size_t)blockIdx.x * 256 + threadIdx.x;
    int j  = idx & 255;
    int i  = (idx >> 8) & 255;
    size_t bh = idx >> 16;
    g_zA[idx] = cvt_tf32(g_attn2[(bh << 16) + ((size_t)j << 8) + i] * inv);
}

// ---------------- depthwise 33-tap conv residual (tf32-rounded add) ----------------
__global__ void res_add_kernel(const float* __restrict__ rk) {
    __shared__ float ker[KSZ];
    int blk = blockIdx.x;
    int bh = blk >> 8;
    int ichunk = blk & 255;
    int h = bh & 7, b = bh >> 3;
    if (threadIdx.x < KSZ) ker[threadIdx.x] = rk[h*KSZ + threadIdx.x];
    __syncthreads();
    int d = threadIdx.x & 63;
    int i = ichunk * 4 + (threadIdx.x >> 6);
    const float* vb = g_v + (size_t)bh * NTOK * DH;
    float s = 0.f;
    #pragma unroll
    for (int t = 0; t < KSZ; t++) {
        int ii = i + t - (KSZ/2);
        if (ii >= 0 && ii < NTOK) s += ker[t] * vb[(size_t)ii * DH + d];
    }
    size_t o = ((size_t)(b*NTOK + i)) * CDIM + h*64 + d;
    g_outf[o] = cvt_tf32(g_outf[o] + s);
}

// ---------------- host ----------------
extern "C" void kernel_launch(void* const* d_in, const int* in_sizes, int n_in,
                              void* d_out, int out_size) {
    const float* x     = (const float*)d_in[0];
    const float* w_qkv = (const float*)d_in[1];
    const float* w_out = (const float*)d_in[2];
    const float* b_out = (const float*)d_in[3];
    const float* rk    = (const float*)d_in[4];
    float* out = (float*)d_out;

    float *xt, *wqkvT, *woutT, *q, *k, *v, *ql, *kl, *a1, *a3, *a2;
    float *zA, *zB, *xz, *t1, *t2, *av, *bv, *outf;
    cudaGetSymbolAddress((void**)&xt, g_xt);
    cudaGetSymbolAddress((void**)&wqkvT, g_wqkvT);
    cudaGetSymbolAddress((void**)&woutT, g_woutT);
    cudaGetSymbolAddress((void**)&q,  g_q);
    cudaGetSymbolAddress((void**)&k,  g_k);
    cudaGetSymbolAddress((void**)&v,  g_v);
    cudaGetSymbolAddress((void**)&ql, g_ql);
    cudaGetSymbolAddress((void**)&kl, g_kl);
    cudaGetSymbolAddress((void**)&a1, g_attn1);
    cudaGetSymbolAddress((void**)&a3, g_attn3);
    cudaGetSymbolAddress((void**)&a2, g_attn2);
    cudaGetSymbolAddress((void**)&zA, g_zA);
    cudaGetSymbolAddress((void**)&zB, g_zB);
    cudaGetSymbolAddress((void**)&xz, g_xz);
    cudaGetSymbolAddress((void**)&t1, g_t1);
    cudaGetSymbolAddress((void**)&t2, g_t2);
    cudaGetSymbolAddress((void**)&av, g_av);
    cudaGetSymbolAddress((void**)&bv, g_bv);
    cudaGetSymbolAddress((void**)&outf, g_outf);

    cudaFuncSetAttribute(pinv_mma_kernel,    cudaFuncAttributeMaxDynamicSharedMemorySize, PB_SMEM3);
    cudaFuncSetAttribute(gemm_tc_kernel,     cudaFuncAttributeMaxDynamicSharedMemorySize, G128_SMEM3);
    cudaFuncSetAttribute(qkv_tc_kernel,      cudaFuncAttributeMaxDynamicSharedMemorySize, G128_SMEM3);
    cudaFuncSetAttribute(final_tc_kernel,    cudaFuncAttributeMaxDynamicSharedMemorySize, G128_SMEM3);
    cudaFuncSetAttribute(gemm64_rowB_kernel, cudaFuncAttributeMaxDynamicSharedMemorySize, G64R_SMEM3);

    // 0) layout prep: xT, wqkvT, woutT (tf32-rounded)
    transpose_kernel<<<dim3(NTOK/32, CDIM/32, BATCH), dim3(32,8)>>>(x, xt, CDIM, NTOK);
    transpose_kernel<<<dim3(48, 16, 1), dim3(32,8)>>>(w_qkv, wqkvT, CDIM, 3*CDIM);
    transpose_kernel<<<dim3(16, 16, 1), dim3(32,8)>>>(w_out, woutT, CDIM, CDIM);
    // 1) QKV projection (32768 x 1536 x 512) + scatter to q/k/v
    qkv_tc_kernel<<<dim3(12, 256), 256, G128_SMEM3>>>();
    // 2) landmarks
    land_kernel<<<(BHN*ML*DH + 255)/256, 256>>>();
    // 3) similarity GEMMs (batched, tf32, B K-major)
    gemm_tc_kernel<<<dim3(2, 8, BHN), 256, G128_SMEM3>>>(q,  kl, a1, DH, DH, ML,   2,
        (size_t)NTOK*DH, (size_t)ML*DH, (size_t)NTOK*ML);                   // sim1
    gemm_tc_kernel<<<dim3(2, 2, BHN), 256, G128_SMEM3>>>(ql, kl, a2, DH, DH, ML,   2,
        (size_t)ML*DH,   (size_t)ML*DH, (size_t)ML*ML);                     // sim2
    gemm_tc_kernel<<<dim3(8, 2, BHN), 256, G128_SMEM3>>>(ql, k,  a3, DH, DH, NTOK, 2,
        (size_t)ML*DH,   (size_t)NTOK*DH, (size_t)ML*NTOK);                 // sim3
    // 4) softmaxes (tf32-rounded outputs)
    softmax_kernel<256> <<<BHN*NTOK, 256>>>(a1);
    softmax_kernel<256> <<<BHN*ML,   256>>>(a2);
    softmax_kernel<1024><<<BHN*ML,   256>>>(a3);
    // 5) pinv init
    reset_max_kernel<<<1, 32>>>();
    colmax_kernel<<<(BHN*ML*32)/256, 256>>>();
    rowmax_kernel<<<(BHN*ML)/256, 256>>>();
    zinit_kernel<<<(BHN*ML*ML)/256, 256>>>();
    // 6) 6 Newton–Schulz iterations, all GEMMs C = A @ B with B row-major
    float *zin = zA, *zout = zB;
    for (int it = 0; it < 6; it++) {
        pinv_mma_kernel<<<1024, 256, PB_SMEM3>>>(a2, zin, nullptr, xz, 0.0f, 1.0f);  // xz = x@z
        pinv_mma_kernel<<<1024, 256, PB_SMEM3>>>(xz, xz, xz, t1, 7.0f, -1.0f);       // t1 = 7xz - xz@xz
        pinv_mma_kernel<<<1024, 256, PB_SMEM3>>>(xz, t1, xz, t2, 15.0f, -1.0f);      // t2 = 15xz - xz@t1
        pinv_mma_kernel<<<1024, 256, PB_SMEM3>>>(zin, t2, zin, zout, 3.25f, -0.25f); // z' = 3.25z - 0.25 z@t2
        float* tmp = zin; zin = zout; zout = tmp;
    }
    // 7) output chain (B row-major everywhere): av = attn3@v ; bv = z@av ; outf = attn1@bv
    gemm64_rowB_kernel<<<dim3(2, 1, BHN), 256, G64R_SMEM3>>>(a3, v, av,
        NTOK, 32, (size_t)ML*NTOK, (size_t)NTOK*DH, 0);
    gemm64_rowB_kernel<<<dim3(2, 1, BHN), 256, G64R_SMEM3>>>(zin, av, bv,
        ML, 8, (size_t)ML*ML, (size_t)ML*DH, 0);
    gemm64_rowB_kernel<<<dim3(8, 1, BHN), 256, G64R_SMEM3>>>(a1, bv, outf,
        ML, 8, (size_t)NTOK*ML, (size_t)ML*DH, 1);
    // 8) depthwise conv residual (rounds outf for final GEMM)
    res_add_kernel<<<BHN*256, 256>>>(rk);
    // 9) output projection + bias + transposed store (fp32)
    final_tc_kernel<<<dim3(4, 256), 256, G128_SMEM3>>>(b_out, out);
}

// round 9
// speedup vs baseline: 2.9922x; 1.0223x over previous
#include <cuda_runtime.h>
#include <cstdint>
#include <cstddef>

#define BATCH 32
#define HEADS 8
#define NTOK 1024
#define DH 64
#define ML 256          // landmarks
#define CDIM 512
#define BHN (BATCH*HEADS)   // 256
#define KSZ 33

// ---------------- device scratch ----------------
__device__ float g_xt[(size_t)BATCH*NTOK*CDIM];     // x transposed: (b, n, c), tf32-rounded
__device__ float g_wqkvT[3*CDIM*CDIM];              // (1536, 512), tf32-rounded
__device__ float g_woutT[CDIM*CDIM];                // (512, 512), tf32-rounded
__device__ float g_q [BHN*NTOK*DH];
__device__ float g_k [BHN*NTOK*DH];
__device__ float g_v [BHN*NTOK*DH];
__device__ float g_ql[BHN*ML*DH];
__device__ float g_kl[BHN*ML*DH];
__device__ float g_attn1[(size_t)BHN*NTOK*ML];      // (bh,1024,256)
__device__ float g_attn3[(size_t)BHN*ML*NTOK];      // (bh,256,1024)
__device__ float g_attn2[BHN*ML*ML];
__device__ float g_zA[BHN*ML*ML];
__device__ float g_zB[BHN*ML*ML];
__device__ float g_xz[BHN*ML*ML];
__device__ float g_t1[BHN*ML*ML];
__device__ float g_t2[BHN*ML*ML];
__device__ float g_av[BHN*ML*DH];
__device__ float g_bv[BHN*ML*DH];
__device__ float g_outf[(size_t)BATCH*NTOK*CDIM];   // (b, n, 512)
__device__ unsigned g_colmax;
__device__ unsigned g_rowmax;

// ================= tf32 helpers =================
__device__ __forceinline__ float cvt_tf32(float x) {
    uint32_t u;
    asm("cvt.rna.tf32.f32 %0, %1;" : "=r"(u) : "f"(x));
    return __uint_as_float(u);
}
__device__ __forceinline__ void mma_tf32_16x8x8(float c[4],
    uint32_t a0, uint32_t a1, uint32_t a2, uint32_t a3, uint32_t b0, uint32_t b1) {
    asm volatile(
        "mma.sync.aligned.m16n8k8.row.col.f32.tf32.tf32.f32 "
        "{%0,%1,%2,%3},{%4,%5,%6,%7},{%8,%9},{%0,%1,%2,%3};"
        : "+f"(c[0]), "+f"(c[1]), "+f"(c[2]), "+f"(c[3])
        : "r"(a0), "r"(a1), "r"(a2), "r"(a3), "r"(b0), "r"(b1));
}
// ldmatrix on 32-bit data: each m8n8.b16 matrix = one 8x4 fp32 quadrant,
// thread t <-> element (t/4, t%4) — exactly the tf32 mma fragment mapping.
__device__ __forceinline__ void ldsm_x4(uint32_t& r0, uint32_t& r1,
                                        uint32_t& r2, uint32_t& r3, uint32_t saddr) {
    asm volatile("ldmatrix.sync.aligned.m8n8.x4.shared.b16 {%0,%1,%2,%3}, [%4];"
                 : "=r"(r0), "=r"(r1), "=r"(r2), "=r"(r3) : "r"(saddr));
}
__device__ __forceinline__ void cp16(uint32_t dst, const float* src) {
    asm volatile("cp.async.cg.shared.global [%0], [%1], 16;" :: "r"(dst), "l"(src));
}
#define CP_COMMIT() asm volatile("cp.async.commit_group;")
#define CP_WAIT1()  asm volatile("cp.async.wait_group 1;" ::: "memory")
#define CP_WAIT0()  asm volatile("cp.async.wait_group 0;" ::: "memory")

#define PPITCH 36
#define PSTAGE (128*PPITCH)
// 3-stage layouts: A stages at [0, 3*PSTAGE), B stages follow.
#define G128_SMEM3 (6*PSTAGE*4)                     // 110592 (A,B both K-major)

#define BNP128 136
#define BRSTG128 (32*BNP128)                        // 4352 floats
#define PB_SMEM3 ((3*PSTAGE + 3*BRSTG128)*4)        // 107520

#define BNP64 72
#define BRSTG64 (32*BNP64)                          // 2304 floats
#define G64R_SMEM3 ((3*PSTAGE + 3*BRSTG64)*4)       // 82944

// ============ mainloop A: B stored K-major ([N rows][K]) — sims/qkv/final ============
// 3-stage cp.async pipeline; fragments via ldmatrix.x4.
__device__ __forceinline__ void mainloop128x128(
    const float* __restrict__ A, const float* __restrict__ B,
    int lda, int ldb, int kch, float* sm, int tid, float acc[4][4][4])
{
    const uint32_t sbase = (uint32_t)__cvta_generic_to_shared(sm);
    const uint32_t bbase = sbase + 3*PSTAGE*4;
    const int wid = tid >> 5, lane = tid & 31;
    const int wm = wid >> 2, wn = wid & 3;
    const int g = lane >> 3, r8 = lane & 7;
    // per-thread ldmatrix base offsets (bytes, within one stage)
    const uint32_t a_lm = (uint32_t)((wm*64 + (g&1)*8 + r8)*PPITCH + (g>>1)*4)*4;
    const uint32_t b_lm = (uint32_t)((wn*32 + (g>>1)*8 + r8)*PPITCH + (g&1)*4)*4;
    int rrow[4], rc4[4];
    #pragma unroll
    for (int e = 0; e < 4; e++) {
        int f4 = e * 256 + tid;
        rrow[e] = f4 >> 3;
        rc4[e] = (f4 & 7) << 2;
    }
    // prologue: chunks 0, 1
    #pragma unroll
    for (int p = 0; p < 2; p++) {
        if (p < kch) {
            const int k0 = p * 32;
            #pragma unroll
            for (int e = 0; e < 4; e++) {
                cp16(sbase + (uint32_t)(p*PSTAGE + rrow[e]*PPITCH + rc4[e])*4,
                     &A[(size_t)rrow[e] * lda + k0 + rc4[e]]);
                cp16(bbase + (uint32_t)(p*PSTAGE + rrow[e]*PPITCH + rc4[e])*4,
                     &B[(size_t)rrow[e] * ldb + k0 + rc4[e]]);
            }
        }
        CP_COMMIT();
    }
    for (int c = 0; c < kch; c++) {
        const int st = c % 3;
        if (c + 1 < kch) { CP_WAIT1(); } else { CP_WAIT0(); }
        __syncthreads();
        if (c + 2 < kch) {
            const int nst = (c + 2) % 3;
            const int k0 = (c + 2) * 32;
            #pragma unroll
            for (int e = 0; e < 4; e++) {
                cp16(sbase + (uint32_t)(nst*PSTAGE + rrow[e]*PPITCH + rc4[e])*4,
                     &A[(size_t)rrow[e] * lda + k0 + rc4[e]]);
                cp16(bbase + (uint32_t)(nst*PSTAGE + rrow[e]*PPITCH + rc4[e])*4,
                     &B[(size_t)rrow[e] * ldb + k0 + rc4[e]]);
            }
            CP_COMMIT();
        }
        const uint32_t a_st = sbase + (uint32_t)(st*PSTAGE)*4 + a_lm;
        const uint32_t b_st = bbase + (uint32_t)(st*PSTAGE)*4 + b_lm;
        #pragma unroll
        for (int ks = 0; ks < 4; ks++) {
            uint32_t af[4][4];
            #pragma unroll
            for (int mi = 0; mi < 4; mi++)
                ldsm_x4(af[mi][0], af[mi][1], af[mi][2], af[mi][3],
                        a_st + (uint32_t)(mi*16*PPITCH + ks*8)*4);
            uint32_t bf[4][2];
            #pragma unroll
            for (int p = 0; p < 2; p++)
                ldsm_x4(bf[2*p][0], bf[2*p][1], bf[2*p+1][0], bf[2*p+1][1],
                        b_st + (uint32_t)(p*16*PPITCH + ks*8)*4);
            #pragma unroll
            for (int mi = 0; mi < 4; mi++)
                #pragma unroll
                for (int ni = 0; ni < 4; ni++)
                    mma_tf32_16x8x8(acc[mi][ni],
                        af[mi][0], af[mi][1], af[mi][2], af[mi][3],
                        bf[ni][0], bf[ni][1]);
        }
    }
}

// ============ mainloop B: B stored row-major [K][N] — pinv/chain ============
// A fragments via ldmatrix; B fragments scalar (orientation precludes ldmatrix).
__device__ __forceinline__ void mainloop128x128_rowB(
    const float* __restrict__ A, const float* __restrict__ B,
    int lda, int ldb, int kch, float* sm, int tid, float acc[4][4][4])
{
    const uint32_t sbase = (uint32_t)__cvta_generic_to_shared(sm);
    const uint32_t bbase = sbase + 3*PSTAGE*4;
    const int wid = tid >> 5, lane = tid & 31;
    const int gr = lane >> 2, gc = lane & 3;
    const int wm = wid >> 2, wn = wid & 3;
    const int g = lane >> 3, r8 = lane & 7;
    const uint32_t a_lm = (uint32_t)((wm*64 + (g&1)*8 + r8)*PPITCH + (g>>1)*4)*4;
    int arow[4], ac4[4], bk[4], bn4[4];
    #pragma unroll
    for (int e = 0; e < 4; e++) {
        int f4 = e * 256 + tid;
        arow[e] = f4 >> 3;  ac4[e] = (f4 & 7) << 2;
        bk[e]   = f4 >> 5;  bn4[e] = (f4 & 31) << 2;
    }
    #pragma unroll
    for (int p = 0; p < 2; p++) {
        if (p < kch) {
            const int k0 = p * 32;
            #pragma unroll
            for (int e = 0; e < 4; e++) {
                cp16(sbase + (uint32_t)(p*PSTAGE + arow[e]*PPITCH + ac4[e])*4,
                     &A[(size_t)arow[e] * lda + k0 + ac4[e]]);
                cp16(bbase + (uint32_t)(p*BRSTG128 + bk[e]*BNP128 + bn4[e])*4,
                     &B[(size_t)(k0 + bk[e]) * ldb + bn4[e]]);
            }
        }
        CP_COMMIT();
    }
    for (int c = 0; c < kch; c++) {
        const int st = c % 3;
        if (c + 1 < kch) { CP_WAIT1(); } else { CP_WAIT0(); }
        __syncthreads();
        if (c + 2 < kch) {
            const int nst = (c + 2) % 3;
            const int k0 = (c + 2) * 32;
            #pragma unroll
            for (int e = 0; e < 4; e++) {
                cp16(sbase + (uint32_t)(nst*PSTAGE + arow[e]*PPITCH + ac4[e])*4,
                     &A[(size_t)arow[e] * lda + k0 + ac4[e]]);
                cp16(bbase + (uint32_t)(nst*BRSTG128 + bk[e]*BNP128 + bn4[e])*4,
                     &B[(size_t)(k0 + bk[e]) * ldb + bn4[e]]);
            }
            CP_COMMIT();
        }
        const uint32_t a_st = sbase + (uint32_t)(st*PSTAGE)*4 + a_lm;
        const float* Bb = sm + 3*PSTAGE + st*BRSTG128;
        #pragma unroll
        for (int ks = 0; ks < 4; ks++) {
            uint32_t af[4][4];
            #pragma unroll
            for (int mi = 0; mi < 4; mi++)
                ldsm_x4(af[mi][0], af[mi][1], af[mi][2], af[mi][3],
                        a_st + (uint32_t)(mi*16*PPITCH + ks*8)*4);
            uint32_t bf[4][2];
            #pragma unroll
            for (int ni = 0; ni < 4; ni++) {
                int n = wn*32 + ni*8 + gr;
                bf[ni][0] = __float_as_uint(Bb[(ks*8 + gc)*BNP128 + n]);
                bf[ni][1] = __float_as_uint(Bb[(ks*8 + gc + 4)*BNP128 + n]);
            }
            #pragma unroll
            for (int mi = 0; mi < 4; mi++)
                #pragma unroll
                for (int ni = 0; ni < 4; ni++)
                    mma_tf32_16x8x8(acc[mi][ni],
                        af[mi][0], af[mi][1], af[mi][2], af[mi][3],
                        bf[ni][0], bf[ni][1]);
        }
    }
}

// ============ plain batched GEMM: C[z] = A[z] @ B[z]^T (B K-major; sims) ============
__global__ void __launch_bounds__(256, 2) gemm_tc_kernel(
    const float* __restrict__ A, const float* __restrict__ B, float* __restrict__ C,
    int lda, int ldb, int ldc, int kch,
    size_t sA, size_t sB, size_t sC)
{
    extern __shared__ float sm[];
    const int tid = threadIdx.x;
    const int z = blockIdx.z;
    const int m0 = blockIdx.y * 128, n0 = blockIdx.x * 128;
    A += (size_t)z * sA + (size_t)m0 * lda;
    B += (size_t)z * sB + (size_t)n0 * ldb;
    C += (size_t)z * sC;
    float acc[4][4][4];
    #pragma unroll
    for (int mi = 0; mi < 4; mi++)
        #pragma unroll
        for (int ni = 0; ni < 4; ni++)
            #pragma unroll
            for (int e = 0; e < 4; e++) acc[mi][ni][e] = 0.f;
    mainloop128x128(A, B, lda, ldb, kch, sm, tid, acc);
    const int wid = tid >> 5, lane = tid & 31;
    const int gr = lane >> 2, gc = lane & 3;
    const int wm = wid >> 2, wn = wid & 3;
    #pragma unroll
    for (int mi = 0; mi < 4; mi++) {
        #pragma unroll
        for (int ni = 0; ni < 4; ni++) {
            int lr = m0 + wm*64 + mi*16 + gr;
            int lc = n0 + wn*32 + ni*8 + gc*2;
            const float* a = acc[mi][ni];
            *reinterpret_cast<float2*>(&C[(size_t)lr * ldc + lc]) = make_float2(a[0], a[1]);
            *reinterpret_cast<float2*>(&C[(size_t)(lr+8) * ldc + lc]) = make_float2(a[2], a[3]);
        }
    }
}

// ============ QKV GEMM with scatter epilogue (tf32-rounded outputs) ============
__global__ void __launch_bounds__(256, 2) qkv_tc_kernel(void) {
    extern __shared__ float sm[];
    const int tid = threadIdx.x;
    const int m0 = blockIdx.y * 128;        // over 32768 (b*1024+i)
    const int n0 = blockIdx.x * 128;        // over 1536
    const float* A = g_xt + (size_t)m0 * CDIM;
    const float* B = g_wqkvT + (size_t)n0 * CDIM;
    float acc[4][4][4];
    #pragma unroll
    for (int mi = 0; mi < 4; mi++)
        #pragma unroll
        for (int ni = 0; ni < 4; ni++)
            #pragma unroll
            for (int e = 0; e < 4; e++) acc[mi][ni][e] = 0.f;
    mainloop128x128(A, B, CDIM, CDIM, CDIM/32, sm, tid, acc);
    const int wid = tid >> 5, lane = tid & 31;
    const int gr = lane >> 2, gc = lane & 3;
    const int wm = wid >> 2, wn = wid & 3;
    #pragma unroll
    for (int mi = 0; mi < 4; mi++) {
        int m = m0 + wm*64 + mi*16 + gr;
        int b = m >> 10, i = m & 1023;
        #pragma unroll
        for (int ni = 0; ni < 4; ni++) {
            int n = n0 + wn*32 + ni*8 + gc*2;
            int which = n >> 9;
            int h = (n >> 6) & 7;
            int d = n & 63;
            int bh = b*8 + h;
            float* dst = (which == 0) ? g_q : ((which == 1) ? g_k : g_v);
            float sc = (which == 0) ? 0.125f : 1.0f;
            const float* a = acc[mi][ni];
            float r0 = cvt_tf32(a[0]*sc), r1 = cvt_tf32(a[1]*sc);
            float r2 = cvt_tf32(a[2]*sc), r3 = cvt_tf32(a[3]*sc);
            *reinterpret_cast<float2*>(&dst[((size_t)(bh*NTOK + i))*DH + d]) = make_float2(r0, r1);
            *reinterpret_cast<float2*>(&dst[((size_t)(bh*NTOK + i + 8))*DH + d]) = make_float2(r2, r3);
        }
    }
}

// ============ final GEMM: out = outf @ woutT^T + bias, transposed store (fp32) ============
__global__ void __launch_bounds__(256, 2) final_tc_kernel(
    const float* __restrict__ bias, float* __restrict__ out)
{
    extern __shared__ float sm[];
    const int tid = threadIdx.x;
    const int m0 = blockIdx.y * 128;        // over 32768
    const int n0 = blockIdx.x * 128;        // over 512
    const float* A = g_outf + (size_t)m0 * CDIM;
    const float* B = g_woutT + (size_t)n0 * CDIM;
    float acc[4][4][4];
    #pragma unroll
    for (int mi = 0; mi < 4; mi++)
        #pragma unroll
        for (int ni = 0; ni < 4; ni++)
            #pragma unroll
            for (int e = 0; e < 4; e++) acc[mi][ni][e] = 0.f;
    mainloop128x128(A, B, CDIM, CDIM, CDIM/32, sm, tid, acc);
    const int wid = tid >> 5, lane = tid & 31;
    const int gr = lane >> 2, gc = lane & 3;
    const int wm = wid >> 2, wn = wid & 3;
    #pragma unroll
    for (int mi = 0; mi < 4; mi++) {
        int m = m0 + wm*64 + mi*16 + gr;
        int b = m >> 10, i = m & 1023;
        #pragma unroll
        for (int ni = 0; ni < 4; ni++) {
            int n = n0 + wn*32 + ni*8 + gc*2;
            const float* a = acc[mi][ni];
            float b0 = bias[n], b1 = bias[n+1];
            out[((size_t)(b*CDIM + n))*NTOK + i]       = a[0] + b0;
            out[((size_t)(b*CDIM + n + 1))*NTOK + i]   = a[1] + b1;
            out[((size_t)(b*CDIM + n))*NTOK + i + 8]   = a[2] + b0;
            out[((size_t)(b*CDIM + n + 1))*NTOK + i + 8] = a[3] + b1;
        }
    }
}

// ============ 128x64 batched GEMM, B row-major [K,64]: C = A @ B ============
// warps 4x2 (warp tile 32x32), 3-stage cp.async, A via ldmatrix. Output tf32-rounded.
__global__ void __launch_bounds__(256, 2) gemm64_rowB_kernel(
    const float* __restrict__ A, const float* __restrict__ B, float* __restrict__ C,
    int lda, int kch, size_t sA, size_t sB, int flatC)
{
    extern __shared__ float sm[];
    const uint32_t sbase = (uint32_t)__cvta_generic_to_shared(sm);
    const uint32_t bbase = sbase + 3*PSTAGE*4;
    const int tid = threadIdx.x;
    const int wid = tid >> 5, lane = tid & 31;
    const int gr = lane >> 2, gc = lane & 3;
    const int wm = wid >> 1, wn = wid & 1;
    const int g = lane >> 3, r8 = lane & 7;
    const uint32_t a_lm = (uint32_t)((wm*32 + (g&1)*8 + r8)*PPITCH + (g>>1)*4)*4;
    const int z = blockIdx.z;
    const int m0 = blockIdx.x * 128;
    A += (size_t)z * sA + (size_t)m0 * lda;
    B += (size_t)z * sB;
    if (flatC) C += (size_t)(z >> 3) * (NTOK*CDIM) + (size_t)(z & 7) * DH;
    else       C += (size_t)z * (ML*DH);

    int arow[4], ac4[4], bk[2], bn4[2];
    #pragma unroll
    for (int e = 0; e < 4; e++) {
        int f4 = e * 256 + tid;
        arow[e] = f4 >> 3;  ac4[e] = (f4 & 7) << 2;
    }
    #pragma unroll
    for (int e = 0; e < 2; e++) {
        int f4 = e * 256 + tid;
        bk[e] = f4 >> 4;  bn4[e] = (f4 & 15) << 2;
    }

    float acc[2][4][4];
    #pragma unroll
    for (int mi = 0; mi < 2; mi++)
        #pragma unroll
        for (int ni = 0; ni < 4; ni++)
            #pragma unroll
            for (int e = 0; e < 4; e++) acc[mi][ni][e] = 0.f;

    #pragma unroll
    for (int p = 0; p < 2; p++) {
        if (p < kch) {
            const int k0 = p * 32;
            #pragma unroll
            for (int e = 0; e < 4; e++)
                cp16(sbase + (uint32_t)(p*PSTAGE + arow[e]*PPITCH + ac4[e])*4,
                     &A[(size_t)arow[e] * lda + k0 + ac4[e]]);
            #pragma unroll
            for (int e = 0; e < 2; e++)
                cp16(bbase + (uint32_t)(p*BRSTG64 + bk[e]*BNP64 + bn4[e])*4,
                     &B[(size_t)(k0 + bk[e]) * DH + bn4[e]]);
        }
        CP_COMMIT();
    }

    for (int c = 0; c < kch; c++) {
        const int st = c % 3;
        if (c + 1 < kch) { CP_WAIT1(); } else { CP_WAIT0(); }
        __syncthreads();
        if (c + 2 < kch) {
            const int nst = (c + 2) % 3;
            const int k0 = (c + 2) * 32;
            #pragma unroll
            for (int e = 0; e < 4; e++)
                cp16(sbase + (uint32_t)(nst*PSTAGE + arow[e]*PPITCH + ac4[e])*4,
                     &A[(size_t)arow[e] * lda + k0 + ac4[e]]);
            #pragma unroll
            for (int e = 0; e < 2; e++)
                cp16(bbase + (uint32_t)(nst*BRSTG64 + bk[e]*BNP64 + bn4[e])*4,
                     &B[(size_t)(k0 + bk[e]) * DH + bn4[e]]);
            CP_COMMIT();
        }
        const uint32_t a_st = sbase + (uint32_t)(st*PSTAGE)*4 + a_lm;
        const float* Bb = sm + 3*PSTAGE + st*BRSTG64;
        #pragma unroll
        for (int ks = 0; ks < 4; ks++) {
            uint32_t af[2][4];
            #pragma unroll
            for (int mi = 0; mi < 2; mi++)
                ldsm_x4(af[mi][0], af[mi][1], af[mi][2], af[mi][3],
                        a_st + (uint32_t)(mi*16*PPITCH + ks*8)*4);
            uint32_t bf[4][2];
            #pragma unroll
            for (int ni = 0; ni < 4; ni++) {
                int n = wn*32 + ni*8 + gr;
                bf[ni][0] = __float_as_uint(Bb[(ks*8 + gc)*BNP64 + n]);
                bf[ni][1] = __float_as_uint(Bb[(ks*8 + gc + 4)*BNP64 + n]);
            }
            #pragma unroll
            for (int mi = 0; mi < 2; mi++)
                #pragma unroll
                for (int ni = 0; ni < 4; ni++)
                    mma_tf32_16x8x8(acc[mi][ni],
                        af[mi][0], af[mi][1], af[mi][2], af[mi][3],
                        bf[ni][0], bf[ni][1]);
        }
    }

    #pragma unroll
    for (int mi = 0; mi < 2; mi++) {
        #pragma unroll
        for (int ni = 0; ni < 4; ni++) {
            int lr = m0 + wm*32 + mi*16 + gr;
            int lc = wn*32 + ni*8 + gc*2;
            const float* a = acc[mi][ni];
            float d0 = cvt_tf32(a[0]), d1 = cvt_tf32(a[1]);
            float d2 = cvt_tf32(a[2]), d3 = cvt_tf32(a[3]);
            int ldc = flatC ? CDIM : DH;
            *reinterpret_cast<float2*>(&C[(size_t)lr * ldc + lc]) = make_float2(d0, d1);
            *reinterpret_cast<float2*>(&C[(size_t)(lr+8) * ldc + lc]) = make_float2(d2, d3);
        }
    }
}

// ---------------- batched 2D transpose (tf32-rounded output) ----------------
__global__ void transpose_kernel(const float* __restrict__ in, float* __restrict__ out,
                                 int R, int C) {
    __shared__ float tile[32][33];
    const int z = blockIdx.z;
    in  += (size_t)z * R * C;
    out += (size_t)z * R * C;
    int c0 = blockIdx.x * 32, r0 = blockIdx.y * 32;
    int tx = threadIdx.x, ty = threadIdx.y;
    #pragma unroll
    for (int j = 0; j < 4; j++)
        tile[ty + j*8][tx] = in[(size_t)(r0 + ty + j*8) * C + c0 + tx];
    __syncthreads();
    #pragma unroll
    for (int j = 0; j < 4; j++)
        out[(size_t)(c0 + ty + j*8) * R + r0 + tx] = cvt_tf32(tile[tx][ty + j*8]);
}

// ================= pinv batched GEMM: Cn = c1*U + c2*(P @ B), B row-major =================
__global__ void __launch_bounds__(256, 2) pinv_mma_kernel(
    const float* __restrict__ P, const float* __restrict__ B,
    const float* __restrict__ U, float* __restrict__ Cn,
    float c1, float c2)
{
    extern __shared__ float sm[];
    const int tid = threadIdx.x;
    const int wid = tid >> 5, lane = tid & 31;
    const int wm = wid >> 2, wn = wid & 3;
    const int gr = lane >> 2, gc = lane & 3;
    const int tile = blockIdx.x;
    const int batch = tile >> 2;
    const int m0 = ((tile >> 1) & 1) << 7;
    const int n0 = (tile & 1) << 7;
    const size_t boff = (size_t)batch << 16;
    P += boff + (size_t)m0 * ML;
    B += boff + n0;                 // row-major [K=256][N=256], tile columns n0..n0+127
    if (U) U += boff;
    Cn += boff;

    float acc[4][4][4];
    #pragma unroll
    for (int mi = 0; mi < 4; mi++)
        #pragma unroll
        for (int ni = 0; ni < 4; ni++)
            #pragma unroll
            for (int e = 0; e < 4; e++) acc[mi][ni][e] = 0.f;
    mainloop128x128_rowB(P, B, ML, ML, 8, sm, tid, acc);

    #pragma unroll
    for (int mi = 0; mi < 4; mi++) {
        #pragma unroll
        for (int ni = 0; ni < 4; ni++) {
            int lr = wm*64 + mi*16 + gr;
            int lc = wn*32 + ni*8 + gc*2;
            int grow = m0 + lr, gcol = n0 + lc;
            const float* a = acc[mi][ni];
            float d0, d1, d2, d3;
            if (U) {
                float2 u0 = *reinterpret_cast<const float2*>(&U[(size_t)grow * ML + gcol]);
                float2 u1 = *reinterpret_cast<const float2*>(&U[(size_t)(grow+8) * ML + gcol]);
                d0 = c1*u0.x + c2*a[0]; d1 = c1*u0.y + c2*a[1];
                d2 = c1*u1.x + c2*a[2]; d3 = c1*u1.y + c2*a[3];
            } else {
                d0 = c2*a[0]; d1 = c2*a[1]; d2 = c2*a[2]; d3 = c2*a[3];
            }
            d0 = cvt_tf32(d0); d1 = cvt_tf32(d1); d2 = cvt_tf32(d2); d3 = cvt_tf32(d3);
            *reinterpret_cast<float2*>(&Cn[(size_t)grow * ML + gcol]) = make_float2(d0, d1);
            *reinterpret_cast<float2*>(&Cn[(size_t)(grow+8) * ML + gcol]) = make_float2(d2, d3);
        }
    }
}

// ---------------- landmark means (tf32-rounded) ----------------
__global__ void land_kernel() {
    int idx = blockIdx.x * blockDim.x + threadIdx.x;
    if (idx >= BHN*ML*DH) return;
    int d  = idx & 63;
    int j  = (idx >> 6) & 255;
    int bh = idx >> 14;
    size_t base = ((size_t)bh * NTOK + j*4) * DH + d;
    g_ql[idx] = cvt_tf32(0.25f * (g_q[base] + g_q[base+64] + g_q[base+128] + g_q[base+192]));
    g_kl[idx] = cvt_tf32(0.25f * (g_k[base] + g_k[base+64] + g_k[base+128] + g_k[base+192]));
}

// ---------------- row softmax (tf32-rounded output) ----------------
template<int W>
__global__ void softmax_kernel(float* __restrict__ data) {
    __shared__ float red[256];
    float* row = data + (size_t)blockIdx.x * W;
    int t = threadIdx.x;
    constexpr int PE = W / 256;
    float vals[PE];
    float mx = -1e30f;
    #pragma unroll
    for (int e = 0; e < PE; e++) { vals[e] = row[t + e*256]; mx = fmaxf(mx, vals[e]); }
    red[t] = mx; __syncthreads();
    #pragma unroll
    for (int s = 128; s > 0; s >>= 1) { if (t < s) red[t] = fmaxf(red[t], red[t+s]); __syncthreads(); }
    mx = red[0];
    __syncthreads();
    float sum = 0.f;
    #pragma unroll
    for (int e = 0; e < PE; e++) { vals[e] = expf(vals[e] - mx); sum += vals[e]; }
    red[t] = sum; __syncthreads();
    #pragma unroll
    for (int s = 128; s > 0; s >>= 1) { if (t < s) red[t] += red[t+s]; __syncthreads(); }
    float inv = 1.0f / red[0];
    #pragma unroll
    for (int e = 0; e < PE; e++) row[t + e*256] = cvt_tf32(vals[e] * inv);
}

// ---------------- pinv scale reductions ----------------
__global__ void reset_max_kernel() { if (threadIdx.x == 0) { g_colmax = 0u; g_rowmax = 0u; } }

__global__ void colmax_kernel() {
    int gw = (blockIdx.x * blockDim.x + threadIdx.x) >> 5;
    int lane = threadIdx.x & 31;
    if (gw >= BHN * ML) return;
    const float* row = g_attn2 + (size_t)gw * ML;
    float s = 0.f;
    #pragma unroll
    for (int j = lane; j < ML; j += 32) s += fabsf(row[j]);
    #pragma unroll
    for (int o = 16; o > 0; o >>= 1) s += __shfl_down_sync(0xffffffffu, s, o);
    if (lane == 0) atomicMax(&g_colmax, __float_as_uint(s));
}

__global__ void rowmax_kernel() {
    int idx = blockIdx.x * blockDim.x + threadIdx.x;
    if (idx >= BHN * ML) return;
    int bh = idx >> 8, j = idx & 255;
    const float* base = g_attn2 + (size_t)bh * ML * ML + j;
    float s = 0.f;
    for (int i = 0; i < ML; i++) s += fabsf(base[(size_t)i * ML]);
    atomicMax(&g_rowmax, __float_as_uint(s));
}

__global__ void zinit_kernel() {    // z = x^T * inv (tf32-rounded)
    float inv = 1.0f / (__uint_as_float(g_colmax) * __uint_as_float(g_rowmax));
    size_t idx = (size_t)blockIdx.x * 256 + threadIdx.x;
    int j  = idx & 255;
    int i  = (idx >> 8) & 255;
    size_t bh = idx >> 16;
    g_zA[idx] = cvt_tf32(g_attn2[(bh << 16) + ((size_t)j << 8) + i] * inv);
}

// ---------------- depthwise 33-tap conv residual (tf32-rounded add) ----------------
__global__ void res_add_kernel(const float* __restrict__ rk) {
    __shared__ float ker[KSZ];
    int blk = blockIdx.x;
    int bh = blk >> 8;
    int ichunk = blk & 255;
    int h = bh & 7, b = bh >> 3;
    if (threadIdx.x < KSZ) ker[threadIdx.x] = rk[h*KSZ + threadIdx.x];
    __syncthreads();
    int d = threadIdx.x & 63;
    int i = ichunk * 4 + (threadIdx.x >> 6);
    const float* vb = g_v + (size_t)bh * NTOK * DH;
    float s = 0.f;
    #pragma unroll
    for (int t = 0; t < KSZ; t++) {
        int ii = i + t - (KSZ/2);
        if (ii >= 0 && ii < NTOK) s += ker[t] * vb[(size_t)ii * DH + d];
    }
    size_t o = ((size_t)(b*NTOK + i)) * CDIM + h*64 + d;
    g_outf[o] = cvt_tf32(g_outf[o] + s);
}

// ---------------- host ----------------
extern "C" void kernel_launch(void* const* d_in, const int* in_sizes, int n_in,
                              void* d_out, int out_size) {
    const float* x     = (const float*)d_in[0];
    const float* w_qkv = (const float*)d_in[1];
    const float* w_out = (const float*)d_in[2];
    const float* b_out = (const float*)d_in[3];
    const float* rk    = (const float*)d_in[4];
    float* out = (float*)d_out;

    float *xt, *wqkvT, *woutT, *q, *k, *v, *ql, *kl, *a1, *a3, *a2;
    float *zA, *zB, *xz, *t1, *t2, *av, *bv, *outf;
    cudaGetSymbolAddress((void**)&xt, g_xt);
    cudaGetSymbolAddress((void**)&wqkvT, g_wqkvT);
    cudaGetSymbolAddress((void**)&woutT, g_woutT);
    cudaGetSymbolAddress((void**)&q,  g_q);
    cudaGetSymbolAddress((void**)&k,  g_k);
    cudaGetSymbolAddress((void**)&v,  g_v);
    cudaGetSymbolAddress((void**)&ql, g_ql);
    cudaGetSymbolAddress((void**)&kl, g_kl);
    cudaGetSymbolAddress((void**)&a1, g_attn1);
    cudaGetSymbolAddress((void**)&a3, g_attn3);
    cudaGetSymbolAddress((void**)&a2, g_attn2);
    cudaGetSymbolAddress((void**)&zA, g_zA);
    cudaGetSymbolAddress((void**)&zB, g_zB);
    cudaGetSymbolAddress((void**)&xz, g_xz);
    cudaGetSymbolAddress((void**)&t1, g_t1);
    cudaGetSymbolAddress((void**)&t2, g_t2);
    cudaGetSymbolAddress((void**)&av, g_av);
    cudaGetSymbolAddress((void**)&bv, g_bv);
    cudaGetSymbolAddress((void**)&outf, g_outf);

    cudaFuncSetAttribute(pinv_mma_kernel,    cudaFuncAttributeMaxDynamicSharedMemorySize, PB_SMEM3);
    cudaFuncSetAttribute(gemm_tc_kernel,     cudaFuncAttributeMaxDynamicSharedMemorySize, G128_SMEM3);
    cudaFuncSetAttribute(qkv_tc_kernel,      cudaFuncAttributeMaxDynamicSharedMemorySize, G128_SMEM3);
    cudaFuncSetAttribute(final_tc_kernel,    cudaFuncAttributeMaxDynamicSharedMemorySize, G128_SMEM3);
    cudaFuncSetAttribute(gemm64_rowB_kernel, cudaFuncAttributeMaxDynamicSharedMemorySize, G64R_SMEM3);

    // 0) layout prep: xT, wqkvT, woutT (tf32-rounded)
    transpose_kernel<<<dim3(NTOK/32, CDIM/32, BATCH), dim3(32,8)>>>(x, xt, CDIM, NTOK);
    transpose_kernel<<<dim3(48, 16, 1), dim3(32,8)>>>(w_qkv, wqkvT, CDIM, 3*CDIM);
    transpose_kernel<<<dim3(16, 16, 1), dim3(32,8)>>>(w_out, woutT, CDIM, CDIM);
    // 1) QKV projection (32768 x 1536 x 512) + scatter to q/k/v
    qkv_tc_kernel<<<dim3(12, 256), 256, G128_SMEM3>>>();
    // 2) landmarks
    land_kernel<<<(BHN*ML*DH + 255)/256, 256>>>();
    // 3) similarity GEMMs (batched, tf32, B K-major)
    gemm_tc_kernel<<<dim3(2, 8, BHN), 256, G128_SMEM3>>>(q,  kl, a1, DH, DH, ML,   2,
        (size_t)NTOK*DH, (size_t)ML*DH, (size_t)NTOK*ML);                   // sim1
    gemm_tc_kernel<<<dim3(2, 2, BHN), 256, G128_SMEM3>>>(ql, kl, a2, DH, DH, ML,   2,
        (size_t)ML*DH,   (size_t)ML*DH, (size_t)ML*ML);                     // sim2
    gemm_tc_kernel<<<dim3(8, 2, BHN), 256, G128_SMEM3>>>(ql, k,  a3, DH, DH, NTOK, 2,
        (size_t)ML*DH,   (size_t)NTOK*DH, (size_t)ML*NTOK);                 // sim3
    // 4) softmaxes (tf32-rounded outputs)
    softmax_kernel<256> <<<BHN*NTOK, 256>>>(a1);
    softmax_kernel<256> <<<BHN*ML,   256>>>(a2);
    softmax_kernel<1024><<<BHN*ML,   256>>>(a3);
    // 5) pinv init
    reset_max_kernel<<<1, 32>>>();
    colmax_kernel<<<(BHN*ML*32)/256, 256>>>();
    rowmax_kernel<<<(BHN*ML)/256, 256>>>();
    zinit_kernel<<<(BHN*ML*ML)/256, 256>>>();
    // 6) 6 Newton–Schulz iterations, all GEMMs C = A @ B with B row-major
    float *zin = zA, *zout = zB;
    for (int it = 0; it < 6; it++) {
        pinv_mma_kernel<<<1024, 256, PB_SMEM3>>>(a2, zin, nullptr, xz, 0.0f, 1.0f);  // xz = x@z
        pinv_mma_kernel<<<1024, 256, PB_SMEM3>>>(xz, xz, xz, t1, 7.0f, -1.0f);       // t1 = 7xz - xz@xz
        pinv_mma_kernel<<<1024, 256, PB_SMEM3>>>(xz, t1, xz, t2, 15.0f, -1.0f);      // t2 = 15xz - xz@t1
        pinv_mma_kernel<<<1024, 256, PB_SMEM3>>>(zin, t2, zin, zout, 3.25f, -0.25f); // z' = 3.25z - 0.25 z@t2
        float* tmp = zin; zin = zout; zout = tmp;
    }
    // 7) output chain (B row-major everywhere): av = attn3@v ; bv = z@av ; outf = attn1@bv
    gemm64_rowB_kernel<<<dim3(2, 1, BHN), 256, G64R_SMEM3>>>(a3, v, av,
        NTOK, 32, (size_t)ML*NTOK, (size_t)NTOK*DH, 0);
    gemm64_rowB_kernel<<<dim3(2, 1, BHN), 256, G64R_SMEM3>>>(zin, av, bv,
        ML, 8, (size_t)ML*ML, (size_t)ML*DH, 0);
    gemm64_rowB_kernel<<<dim3(8, 1, BHN), 256, G64R_SMEM3>>>(a1, bv, outf,
        ML, 8, (size_t)NTOK*ML, (size_t)ML*DH, 1);
    // 8) depthwise conv residual (rounds outf for final GEMM)
    res_add_kernel<<<BHN*256, 256>>>(rk);
    // 9) output projection + bias + transposed store (fp32)
    final_tc_kernel<<<dim3(4, 256), 256, G128_SMEM3>>>(b_out, out);
}

// round 10
// speedup vs baseline: 3.2340x; 1.0808x over previous
#include <cuda_runtime.h>
#include <cuda_bf16.h>
#include <cstdint>
#include <cstddef>

#define BATCH 32
#define HEADS 8
#define NTOK 1024
#define DH 64
#define ML 256          // landmarks
#define CDIM 512
#define BHN (BATCH*HEADS)   // 256
#define KSZ 33

// ---------------- device scratch ----------------
__device__ float g_xt[(size_t)BATCH*NTOK*CDIM];     // x transposed: (b, n, c), tf32-rounded
__device__ float g_wqkvT[3*CDIM*CDIM];              // (1536, 512), tf32-rounded
__device__ float g_woutT[CDIM*CDIM];                // (512, 512), tf32-rounded
__device__ float g_q [BHN*NTOK*DH];
__device__ float g_k [BHN*NTOK*DH];
__device__ float g_v [BHN*NTOK*DH];
__device__ float g_ql[BHN*ML*DH];
__device__ float g_kl[BHN*ML*DH];
__device__ float g_attn1[(size_t)BHN*NTOK*ML];      // (bh,1024,256)
__device__ float g_attn3[(size_t)BHN*ML*NTOK];      // (bh,256,1024)
__device__ float g_attn2[BHN*ML*ML];
__device__ float g_zA[BHN*ML*ML];
__device__ float g_zB[BHN*ML*ML];
__device__ float g_xz[BHN*ML*ML];
__device__ float g_t1[BHN*ML*ML];
__device__ float g_t2[BHN*ML*ML];
__device__ float g_av[BHN*ML*DH];
__device__ float g_bv[BHN*ML*DH];
__device__ float g_outf[(size_t)BATCH*NTOK*CDIM];   // (b, n, 512)
__device__ unsigned g_colmax;
__device__ unsigned g_rowmax;
// bf16 pinv buffers
__device__ __nv_bfloat16 g_a2h [BHN*ML*ML];   // bf16(a2), row-major [M][K]
__device__ __nv_bfloat16 g_zhA [BHN*ML*ML];   // z row-major
__device__ __nv_bfloat16 g_zhB [BHN*ML*ML];
__device__ __nv_bfloat16 g_zhTA[BHN*ML*ML];   // z^T (K-major for B operand)
__device__ __nv_bfloat16 g_zhTB[BHN*ML*ML];
__device__ __nv_bfloat16 g_xzh [BHN*ML*ML];
__device__ __nv_bfloat16 g_xzhT[BHN*ML*ML];
__device__ __nv_bfloat16 g_t1hT[BHN*ML*ML];
__device__ __nv_bfloat16 g_t2hT[BHN*ML*ML];

// ================= helpers =================
__device__ __forceinline__ float cvt_tf32(float x) {
    uint32_t u;
    asm("cvt.rna.tf32.f32 %0, %1;" : "=r"(u) : "f"(x));
    return __uint_as_float(u);
}
__device__ __forceinline__ void mma_tf32_16x8x8(float c[4],
    uint32_t a0, uint32_t a1, uint32_t a2, uint32_t a3, uint32_t b0, uint32_t b1) {
    asm volatile(
        "mma.sync.aligned.m16n8k8.row.col.f32.tf32.tf32.f32 "
        "{%0,%1,%2,%3},{%4,%5,%6,%7},{%8,%9},{%0,%1,%2,%3};"
        : "+f"(c[0]), "+f"(c[1]), "+f"(c[2]), "+f"(c[3])
        : "r"(a0), "r"(a1), "r"(a2), "r"(a3), "r"(b0), "r"(b1));
}
__device__ __forceinline__ void mma_bf16_16x8x16(float c[4],
    uint32_t a0, uint32_t a1, uint32_t a2, uint32_t a3, uint32_t b0, uint32_t b1) {
    asm volatile(
        "mma.sync.aligned.m16n8k16.row.col.f32.bf16.bf16.f32 "
        "{%0,%1,%2,%3},{%4,%5,%6,%7},{%8,%9},{%0,%1,%2,%3};"
        : "+f"(c[0]), "+f"(c[1]), "+f"(c[2]), "+f"(c[3])
        : "r"(a0), "r"(a1), "r"(a2), "r"(a3), "r"(b0), "r"(b1));
}
__device__ __forceinline__ void ldsm_x4(uint32_t& r0, uint32_t& r1,
                                        uint32_t& r2, uint32_t& r3, uint32_t saddr) {
    asm volatile("ldmatrix.sync.aligned.m8n8.x4.shared.b16 {%0,%1,%2,%3}, [%4];"
                 : "=r"(r0), "=r"(r1), "=r"(r2), "=r"(r3) : "r"(saddr));
}
__device__ __forceinline__ void cp16(uint32_t dst, const void* src) {
    asm volatile("cp.async.cg.shared.global [%0], [%1], 16;" :: "r"(dst), "l"(src));
}
#define CP_COMMIT() asm volatile("cp.async.commit_group;")
#define CP_WAIT1()  asm volatile("cp.async.wait_group 1;" ::: "memory")
#define CP_WAIT0()  asm volatile("cp.async.wait_group 0;" ::: "memory")

#define PPITCH 36
#define PSTAGE (128*PPITCH)
#define G128_SMEM3 (6*PSTAGE*4)                     // 110592 (A,B both K-major fp32)

#define BNP128 136
#define BRSTG128 (32*BNP128)
#define PB_SMEM3 ((3*PSTAGE + 3*BRSTG128)*4)        // 107520

#define BNP64 72
#define BRSTG64 (32*BNP64)
#define G64R_SMEM3 ((3*PSTAGE + 3*BRSTG64)*4)       // 82944

// bf16 tiles: [128 rows][KPH halves] per chunk (32 halves data, pitch 40)
#define KPH 40
#define HSTG (128*KPH)                               // halves per stage
#define BH_SMEM3 (6*HSTG*2)                          // 61440 bytes

// ============ mainloop A: B stored K-major ([N rows][K]) — sims/qkv/final ============
__device__ __forceinline__ void mainloop128x128(
    const float* __restrict__ A, const float* __restrict__ B,
    int lda, int ldb, int kch, float* sm, int tid, float acc[4][4][4])
{
    const uint32_t sbase = (uint32_t)__cvta_generic_to_shared(sm);
    const uint32_t bbase = sbase + 3*PSTAGE*4;
    const int wid = tid >> 5, lane = tid & 31;
    const int wm = wid >> 2, wn = wid & 3;
    const int g = lane >> 3, r8 = lane & 7;
    const uint32_t a_lm = (uint32_t)((wm*64 + (g&1)*8 + r8)*PPITCH + (g>>1)*4)*4;
    const uint32_t b_lm = (uint32_t)((wn*32 + (g>>1)*8 + r8)*PPITCH + (g&1)*4)*4;
    int rrow[4], rc4[4];
    #pragma unroll
    for (int e = 0; e < 4; e++) {
        int f4 = e * 256 + tid;
        rrow[e] = f4 >> 3;
        rc4[e] = (f4 & 7) << 2;
    }
    #pragma unroll
    for (int p = 0; p < 2; p++) {
        if (p < kch) {
            const int k0 = p * 32;
            #pragma unroll
            for (int e = 0; e < 4; e++) {
                cp16(sbase + (uint32_t)(p*PSTAGE + rrow[e]*PPITCH + rc4[e])*4,
                     &A[(size_t)rrow[e] * lda + k0 + rc4[e]]);
                cp16(bbase + (uint32_t)(p*PSTAGE + rrow[e]*PPITCH + rc4[e])*4,
                     &B[(size_t)rrow[e] * ldb + k0 + rc4[e]]);
            }
        }
        CP_COMMIT();
    }
    for (int c = 0; c < kch; c++) {
        const int st = c % 3;
        if (c + 1 < kch) { CP_WAIT1(); } else { CP_WAIT0(); }
        __syncthreads();
        if (c + 2 < kch) {
            const int nst = (c + 2) % 3;
            const int k0 = (c + 2) * 32;
            #pragma unroll
            for (int e = 0; e < 4; e++) {
                cp16(sbase + (uint32_t)(nst*PSTAGE + rrow[e]*PPITCH + rc4[e])*4,
                     &A[(size_t)rrow[e] * lda + k0 + rc4[e]]);
                cp16(bbase + (uint32_t)(nst*PSTAGE + rrow[e]*PPITCH + rc4[e])*4,
                     &B[(size_t)rrow[e] * ldb + k0 + rc4[e]]);
            }
            CP_COMMIT();
        }
        const uint32_t a_st = sbase + (uint32_t)(st*PSTAGE)*4 + a_lm;
        const uint32_t b_st = bbase + (uint32_t)(st*PSTAGE)*4 + b_lm;
        #pragma unroll
        for (int ks = 0; ks < 4; ks++) {
            uint32_t af[4][4];
            #pragma unroll
            for (int mi = 0; mi < 4; mi++)
                ldsm_x4(af[mi][0], af[mi][1], af[mi][2], af[mi][3],
                        a_st + (uint32_t)(mi*16*PPITCH + ks*8)*4);
            uint32_t bf[4][2];
            #pragma unroll
            for (int p = 0; p < 2; p++)
                ldsm_x4(bf[2*p][0], bf[2*p][1], bf[2*p+1][0], bf[2*p+1][1],
                        b_st + (uint32_t)(p*16*PPITCH + ks*8)*4);
            #pragma unroll
            for (int mi = 0; mi < 4; mi++)
                #pragma unroll
                for (int ni = 0; ni < 4; ni++)
                    mma_tf32_16x8x8(acc[mi][ni],
                        af[mi][0], af[mi][1], af[mi][2], af[mi][3],
                        bf[ni][0], bf[ni][1]);
        }
    }
}

// ============ mainloop B: B stored row-major [K][N] — tf32 pinv/chain ============
__device__ __forceinline__ void mainloop128x128_rowB(
    const float* __restrict__ A, const float* __restrict__ B,
    int lda, int ldb, int kch, float* sm, int tid, float acc[4][4][4])
{
    const uint32_t sbase = (uint32_t)__cvta_generic_to_shared(sm);
    const uint32_t bbase = sbase + 3*PSTAGE*4;
    const int wid = tid >> 5, lane = tid & 31;
    const int gr = lane >> 2, gc = lane & 3;
    const int wm = wid >> 2, wn = wid & 3;
    const int g = lane >> 3, r8 = lane & 7;
    const uint32_t a_lm = (uint32_t)((wm*64 + (g&1)*8 + r8)*PPITCH + (g>>1)*4)*4;
    int arow[4], ac4[4], bk[4], bn4[4];
    #pragma unroll
    for (int e = 0; e < 4; e++) {
        int f4 = e * 256 + tid;
        arow[e] = f4 >> 3;  ac4[e] = (f4 & 7) << 2;
        bk[e]   = f4 >> 5;  bn4[e] = (f4 & 31) << 2;
    }
    #pragma unroll
    for (int p = 0; p < 2; p++) {
        if (p < kch) {
            const int k0 = p * 32;
            #pragma unroll
            for (int e = 0; e < 4; e++) {
                cp16(sbase + (uint32_t)(p*PSTAGE + arow[e]*PPITCH + ac4[e])*4,
                     &A[(size_t)arow[e] * lda + k0 + ac4[e]]);
                cp16(bbase + (uint32_t)(p*BRSTG128 + bk[e]*BNP128 + bn4[e])*4,
                     &B[(size_t)(k0 + bk[e]) * ldb + bn4[e]]);
            }
        }
        CP_COMMIT();
    }
    for (int c = 0; c < kch; c++) {
        const int st = c % 3;
        if (c + 1 < kch) { CP_WAIT1(); } else { CP_WAIT0(); }
        __syncthreads();
        if (c + 2 < kch) {
            const int nst = (c + 2) % 3;
            const int k0 = (c + 2) * 32;
            #pragma unroll
            for (int e = 0; e < 4; e++) {
                cp16(sbase + (uint32_t)(nst*PSTAGE + arow[e]*PPITCH + ac4[e])*4,
                     &A[(size_t)arow[e] * lda + k0 + ac4[e]]);
                cp16(bbase + (uint32_t)(nst*BRSTG128 + bk[e]*BNP128 + bn4[e])*4,
                     &B[(size_t)(k0 + bk[e]) * ldb + bn4[e]]);
            }
            CP_COMMIT();
        }
        const uint32_t a_st = sbase + (uint32_t)(st*PSTAGE)*4 + a_lm;
        const float* Bb = sm + 3*PSTAGE + st*BRSTG128;
        #pragma unroll
        for (int ks = 0; ks < 4; ks++) {
            uint32_t af[4][4];
            #pragma unroll
            for (int mi = 0; mi < 4; mi++)
                ldsm_x4(af[mi][0], af[mi][1], af[mi][2], af[mi][3],
                        a_st + (uint32_t)(mi*16*PPITCH + ks*8)*4);
            uint32_t bf[4][2];
            #pragma unroll
            for (int ni = 0; ni < 4; ni++) {
                int n = wn*32 + ni*8 + gr;
                bf[ni][0] = __float_as_uint(Bb[(ks*8 + gc)*BNP128 + n]);
                bf[ni][1] = __float_as_uint(Bb[(ks*8 + gc + 4)*BNP128 + n]);
            }
            #pragma unroll
            for (int mi = 0; mi < 4; mi++)
                #pragma unroll
                for (int ni = 0; ni < 4; ni++)
                    mma_tf32_16x8x8(acc[mi][ni],
                        af[mi][0], af[mi][1], af[mi][2], af[mi][3],
                        bf[ni][0], bf[ni][1]);
        }
    }
}

// ============ bf16 pinv batched GEMM: D = c1*U + c2*(A @ B^T), both K-major ============
// A [M][K] bf16, B [N][K] bf16 (K-major), U [M][N] bf16.
// Outputs (each optional): Cn bf16 [M][N], Ct bf16 [N][M], Cf fp32 tf32-rounded [M][N].
__global__ void __launch_bounds__(256, 2) pinv_bf16_kernel(
    const __nv_bfloat16* __restrict__ A, const __nv_bfloat16* __restrict__ B,
    const __nv_bfloat16* __restrict__ U,
    __nv_bfloat16* __restrict__ Cn, __nv_bfloat16* __restrict__ Ct,
    float* __restrict__ Cf, float c1, float c2)
{
    extern __shared__ __nv_bfloat16 smh[];
    const uint32_t sbase = (uint32_t)__cvta_generic_to_shared(smh);
    const uint32_t bbase = sbase + 3*HSTG*2;
    const int tid = threadIdx.x;
    const int wid = tid >> 5, lane = tid & 31;
    const int wm = wid >> 2, wn = wid & 3;
    const int gr = lane >> 2, gc = lane & 3;
    const int mtx = lane >> 3, mrow = lane & 7;
    // ldmatrix per-thread address offsets (bytes within a tile row-block)
    const uint32_t a_lm = ((uint32_t)(((mtx&1)*8 + mrow)) * KPH + (uint32_t)((mtx>>1)*8)) * 2;
    const uint32_t b_lm = ((uint32_t)(((mtx>>1)*8 + mrow)) * KPH + (uint32_t)((mtx&1)*8)) * 2;

    const int tile = blockIdx.x;
    const int batch = tile >> 2;
    const int m0 = ((tile >> 1) & 1) << 7;
    const int n0 = (tile & 1) << 7;
    const size_t boff = (size_t)batch << 16;
    A += boff + (size_t)m0 * ML;
    B += boff + (size_t)n0 * ML;
    if (U)  U  += boff;
    if (Cn) Cn += boff;
    if (Ct) Ct += boff;
    if (Cf) Cf += boff;

    // cp.async mapping: 512 x 16B per matrix per chunk, 2 per thread
    int crow[2], cseg[2];
    #pragma unroll
    for (int e = 0; e < 2; e++) {
        int f = e * 256 + tid;
        crow[e] = f >> 2;
        cseg[e] = (f & 3) * 8;   // halves
    }

    float acc[4][4][4];
    #pragma unroll
    for (int mi = 0; mi < 4; mi++)
        #pragma unroll
        for (int ni = 0; ni < 4; ni++)
            #pragma unroll
            for (int e = 0; e < 4; e++) acc[mi][ni][e] = 0.f;

    // prologue: chunks 0,1
    #pragma unroll
    for (int p = 0; p < 2; p++) {
        const int k0 = p * 32;
        #pragma unroll
        for (int e = 0; e < 2; e++) {
            cp16(sbase + (uint32_t)(p*HSTG + crow[e]*KPH + cseg[e])*2,
                 &A[(size_t)crow[e] * ML + k0 + cseg[e]]);
            cp16(bbase + (uint32_t)(p*HSTG + crow[e]*KPH + cseg[e])*2,
                 &B[(size_t)crow[e] * ML + k0 + cseg[e]]);
        }
        CP_COMMIT();
    }
    for (int c = 0; c < 8; c++) {
        const int st = c % 3;
        if (c + 1 < 8) { CP_WAIT1(); } else { CP_WAIT0(); }
        __syncthreads();
        if (c + 2 < 8) {
            const int nst = (c + 2) % 3;
            const int k0 = (c + 2) * 32;
            #pragma unroll
            for (int e = 0; e < 2; e++) {
                cp16(sbase + (uint32_t)(nst*HSTG + crow[e]*KPH + cseg[e])*2,
                     &A[(size_t)crow[e] * ML + k0 + cseg[e]]);
                cp16(bbase + (uint32_t)(nst*HSTG + crow[e]*KPH + cseg[e])*2,
                     &B[(size_t)crow[e] * ML + k0 + cseg[e]]);
            }
            CP_COMMIT();
        }
        const uint32_t a_st = sbase + (uint32_t)(st*HSTG)*2 + a_lm;
        const uint32_t b_st = bbase + (uint32_t)(st*HSTG)*2 + b_lm;
        #pragma unroll
        for (int ks = 0; ks < 2; ks++) {
            uint32_t af[4][4];
            #pragma unroll
            for (int mi = 0; mi < 4; mi++)
                ldsm_x4(af[mi][0], af[mi][1], af[mi][2], af[mi][3],
                        a_st + (uint32_t)((wm*64 + mi*16)*KPH + ks*16)*2);
            uint32_t bf[4][2];
            #pragma unroll
            for (int p = 0; p < 2; p++)
                ldsm_x4(bf[2*p][0], bf[2*p][1], bf[2*p+1][0], bf[2*p+1][1],
                        b_st + (uint32_t)((wn*32 + p*16)*KPH + ks*16)*2);
            #pragma unroll
            for (int mi = 0; mi < 4; mi++)
                #pragma unroll
                for (int ni = 0; ni < 4; ni++)
                    mma_bf16_16x8x16(acc[mi][ni],
                        af[mi][0], af[mi][1], af[mi][2], af[mi][3],
                        bf[ni][0], bf[ni][1]);
        }
    }

    #pragma unroll
    for (int mi = 0; mi < 4; mi++) {
        #pragma unroll
        for (int ni = 0; ni < 4; ni++) {
            int grow = m0 + wm*64 + mi*16 + gr;
            int gcol = n0 + wn*32 + ni*8 + gc*2;
            const float* a = acc[mi][ni];
            float d0, d1, d2, d3;
            if (U) {
                __nv_bfloat162 u0 = *reinterpret_cast<const __nv_bfloat162*>(&U[(size_t)grow * ML + gcol]);
                __nv_bfloat162 u1 = *reinterpret_cast<const __nv_bfloat162*>(&U[(size_t)(grow+8) * ML + gcol]);
                d0 = c1*__bfloat162float(u0.x) + c2*a[0];
                d1 = c1*__bfloat162float(u0.y) + c2*a[1];
                d2 = c1*__bfloat162float(u1.x) + c2*a[2];
                d3 = c1*__bfloat162float(u1.y) + c2*a[3];
            } else {
                d0 = c2*a[0]; d1 = c2*a[1]; d2 = c2*a[2]; d3 = c2*a[3];
            }
            __nv_bfloat16 h0 = __float2bfloat16(d0), h1 = __float2bfloat16(d1);
            __nv_bfloat16 h2 = __float2bfloat16(d2), h3 = __float2bfloat16(d3);
            if (Cn) {
                __nv_bfloat162 p0; p0.x = h0; p0.y = h1;
                __nv_bfloat162 p1; p1.x = h2; p1.y = h3;
                *reinterpret_cast<__nv_bfloat162*>(&Cn[(size_t)grow * ML + gcol]) = p0;
                *reinterpret_cast<__nv_bfloat162*>(&Cn[(size_t)(grow+8) * ML + gcol]) = p1;
            }
            if (Ct) {
                Ct[(size_t)gcol * ML + grow]       = h0;
                Ct[(size_t)(gcol+1) * ML + grow]   = h1;
                Ct[(size_t)gcol * ML + grow+8]     = h2;
                Ct[(size_t)(gcol+1) * ML + grow+8] = h3;
            }
            if (Cf) {
                *reinterpret_cast<float2*>(&Cf[(size_t)grow * ML + gcol]) =
                    make_float2(cvt_tf32(d0), cvt_tf32(d1));
                *reinterpret_cast<float2*>(&Cf[(size_t)(grow+8) * ML + gcol]) =
                    make_float2(cvt_tf32(d2), cvt_tf32(d3));
            }
        }
    }
}

// ============ plain batched GEMM: C[z] = A[z] @ B[z]^T (B K-major; sims) ============
__global__ void __launch_bounds__(256, 2) gemm_tc_kernel(
    const float* __restrict__ A, const float* __restrict__ B, float* __restrict__ C,
    int lda, int ldb, int ldc, int kch,
    size_t sA, size_t sB, size_t sC)
{
    extern __shared__ float sm[];
    const int tid = threadIdx.x;
    const int z = blockIdx.z;
    const int m0 = blockIdx.y * 128, n0 = blockIdx.x * 128;
    A += (size_t)z * sA + (size_t)m0 * lda;
    B += (size_t)z * sB + (size_t)n0 * ldb;
    C += (size_t)z * sC;
    float acc[4][4][4];
    #pragma unroll
    for (int mi = 0; mi < 4; mi++)
        #pragma unroll
        for (int ni = 0; ni < 4; ni++)
            #pragma unroll
            for (int e = 0; e < 4; e++) acc[mi][ni][e] = 0.f;
    mainloop128x128(A, B, lda, ldb, kch, sm, tid, acc);
    const int wid = tid >> 5, lane = tid & 31;
    const int gr = lane >> 2, gc = lane & 3;
    const int wm = wid >> 2, wn = wid & 3;
    #pragma unroll
    for (int mi = 0; mi < 4; mi++) {
        #pragma unroll
        for (int ni = 0; ni < 4; ni++) {
            int lr = m0 + wm*64 + mi*16 + gr;
            int lc = n0 + wn*32 + ni*8 + gc*2;
            const float* a = acc[mi][ni];
            *reinterpret_cast<float2*>(&C[(size_t)lr * ldc + lc]) = make_float2(a[0], a[1]);
            *reinterpret_cast<float2*>(&C[(size_t)(lr+8) * ldc + lc]) = make_float2(a[2], a[3]);
        }
    }
}

// ============ QKV GEMM with scatter epilogue (tf32-rounded outputs) ============
__global__ void __launch_bounds__(256, 2) qkv_tc_kernel(void) {
    extern __shared__ float sm[];
    const int tid = threadIdx.x;
    const int m0 = blockIdx.y * 128;
    const int n0 = blockIdx.x * 128;
    const float* A = g_xt + (size_t)m0 * CDIM;
    const float* B = g_wqkvT + (size_t)n0 * CDIM;
    float acc[4][4][4];
    #pragma unroll
    for (int mi = 0; mi < 4; mi++)
        #pragma unroll
        for (int ni = 0; ni < 4; ni++)
            #pragma unroll
            for (int e = 0; e < 4; e++) acc[mi][ni][e] = 0.f;
    mainloop128x128(A, B, CDIM, CDIM, CDIM/32, sm, tid, acc);
    const int wid = tid >> 5, lane = tid & 31;
    const int gr = lane >> 2, gc = lane & 3;
    const int wm = wid >> 2, wn = wid & 3;
    #pragma unroll
    for (int mi = 0; mi < 4; mi++) {
        int m = m0 + wm*64 + mi*16 + gr;
        int b = m >> 10, i = m & 1023;
        #pragma unroll
        for (int ni = 0; ni < 4; ni++) {
            int n = n0 + wn*32 + ni*8 + gc*2;
            int which = n >> 9;
            int h = (n >> 6) & 7;
            int d = n & 63;
            int bh = b*8 + h;
            float* dst = (which == 0) ? g_q : ((which == 1) ? g_k : g_v);
            float sc = (which == 0) ? 0.125f : 1.0f;
            const float* a = acc[mi][ni];
            float r0 = cvt_tf32(a[0]*sc), r1 = cvt_tf32(a[1]*sc);
            float r2 = cvt_tf32(a[2]*sc), r3 = cvt_tf32(a[3]*sc);
            *reinterpret_cast<float2*>(&dst[((size_t)(bh*NTOK + i))*DH + d]) = make_float2(r0, r1);
            *reinterpret_cast<float2*>(&dst[((size_t)(bh*NTOK + i + 8))*DH + d]) = make_float2(r2, r3);
        }
    }
}

// ============ final GEMM: out = outf @ woutT^T + bias, transposed store (fp32) ============
__global__ void __launch_bounds__(256, 2) final_tc_kernel(
    const float* __restrict__ bias, float* __restrict__ out)
{
    extern __shared__ float sm[];
    const int tid = threadIdx.x;
    const int m0 = blockIdx.y * 128;
    const int n0 = blockIdx.x * 128;
    const float* A = g_outf + (size_t)m0 * CDIM;
    const float* B = g_woutT + (size_t)n0 * CDIM;
    float acc[4][4][4];
    #pragma unroll
    for (int mi = 0; mi < 4; mi++)
        #pragma unroll
        for (int ni = 0; ni < 4; ni++)
            #pragma unroll
            for (int e = 0; e < 4; e++) acc[mi][ni][e] = 0.f;
    mainloop128x128(A, B, CDIM, CDIM, CDIM/32, sm, tid, acc);
    const int wid = tid >> 5, lane = tid & 31;
    const int gr = lane >> 2, gc = lane & 3;
    const int wm = wid >> 2, wn = wid & 3;
    #pragma unroll
    for (int mi = 0; mi < 4; mi++) {
        int m = m0 + wm*64 + mi*16 + gr;
        int b = m >> 10, i = m & 1023;
        #pragma unroll
        for (int ni = 0; ni < 4; ni++) {
            int n = n0 + wn*32 + ni*8 + gc*2;
            const float* a = acc[mi][ni];
            float b0 = bias[n], b1 = bias[n+1];
            out[((size_t)(b*CDIM + n))*NTOK + i]       = a[0] + b0;
            out[((size_t)(b*CDIM + n + 1))*NTOK + i]   = a[1] + b1;
            out[((size_t)(b*CDIM + n))*NTOK + i + 8]   = a[2] + b0;
            out[((size_t)(b*CDIM + n + 1))*NTOK + i + 8] = a[3] + b1;
        }
    }
}

// ============ 128x64 batched GEMM, B row-major [K,64]: C = A @ B ============
__global__ void __launch_bounds__(256, 2) gemm64_rowB_kernel(
    const float* __restrict__ A, const float* __restrict__ B, float* __restrict__ C,
    int lda, int kch, size_t sA, size_t sB, int flatC)
{
    extern __shared__ float sm[];
    const uint32_t sbase = (uint32_t)__cvta_generic_to_shared(sm);
    const uint32_t bbase = sbase + 3*PSTAGE*4;
    const int tid = threadIdx.x;
    const int wid = tid >> 5, lane = tid & 31;
    const int gr = lane >> 2, gc = lane & 3;
    const int wm = wid >> 1, wn = wid & 1;
    const int g = lane >> 3, r8 = lane & 7;
    const uint32_t a_lm = (uint32_t)((wm*32 + (g&1)*8 + r8)*PPITCH + (g>>1)*4)*4;
    const int z = blockIdx.z;
    const int m0 = blockIdx.x * 128;
    A += (size_t)z * sA + (size_t)m0 * lda;
    B += (size_t)z * sB;
    if (flatC) C += (size_t)(z >> 3) * (NTOK*CDIM) + (size_t)(z & 7) * DH;
    else       C += (size_t)z * (ML*DH);

    int arow[4], ac4[4], bk[2], bn4[2];
    #pragma unroll
    for (int e = 0; e < 4; e++) {
        int f4 = e * 256 + tid;
        arow[e] = f4 >> 3;  ac4[e] = (f4 & 7) << 2;
    }
    #pragma unroll
    for (int e = 0; e < 2; e++) {
        int f4 = e * 256 + tid;
        bk[e] = f4 >> 4;  bn4[e] = (f4 & 15) << 2;
    }

    float acc[2][4][4];
    #pragma unroll
    for (int mi = 0; mi < 2; mi++)
        #pragma unroll
        for (int ni = 0; ni < 4; ni++)
            #pragma unroll
            for (int e = 0; e < 4; e++) acc[mi][ni][e] = 0.f;

    #pragma unroll
    for (int p = 0; p < 2; p++) {
        if (p < kch) {
            const int k0 = p * 32;
            #pragma unroll
            for (int e = 0; e < 4; e++)
                cp16(sbase + (uint32_t)(p*PSTAGE + arow[e]*PPITCH + ac4[e])*4,
                     &A[(size_t)arow[e] * lda + k0 + ac4[e]]);
            #pragma unroll
            for (int e = 0; e < 2; e++)
                cp16(bbase + (uint32_t)(p*BRSTG64 + bk[e]*BNP64 + bn4[e])*4,
                     &B[(size_t)(k0 + bk[e]) * DH + bn4[e]]);
        }
        CP_COMMIT();
    }

    for (int c = 0; c < kch; c++) {
        const int st = c % 3;
        if (c + 1 < kch) { CP_WAIT1(); } else { CP_WAIT0(); }
        __syncthreads();
        if (c + 2 < kch) {
            const int nst = (c + 2) % 3;
            const int k0 = (c + 2) * 32;
            #pragma unroll
            for (int e = 0; e < 4; e++)
                cp16(sbase + (uint32_t)(nst*PSTAGE + arow[e]*PPITCH + ac4[e])*4,
                     &A[(size_t)arow[e] * lda + k0 + ac4[e]]);
            #pragma unroll
            for (int e = 0; e < 2; e++)
                cp16(bbase + (uint32_t)(nst*BRSTG64 + bk[e]*BNP64 + bn4[e])*4,
                     &B[(size_t)(k0 + bk[e]) * DH + bn4[e]]);
            CP_COMMIT();
        }
        const uint32_t a_st = sbase + (uint32_t)(st*PSTAGE)*4 + a_lm;
        const float* Bb = sm + 3*PSTAGE + st*BRSTG64;
        #pragma unroll
        for (int ks = 0; ks < 4; ks++) {
            uint32_t af[2][4];
            #pragma unroll
            for (int mi = 0; mi < 2; mi++)
                ldsm_x4(af[mi][0], af[mi][1], af[mi][2], af[mi][3],
                        a_st + (uint32_t)(mi*16*PPITCH + ks*8)*4);
            uint32_t bf[4][2];
            #pragma unroll
            for (int ni = 0; ni < 4; ni++) {
                int n = wn*32 + ni*8 + gr;
                bf[ni][0] = __float_as_uint(Bb[(ks*8 + gc)*BNP64 + n]);
                bf[ni][1] = __float_as_uint(Bb[(ks*8 + gc + 4)*BNP64 + n]);
            }
            #pragma unroll
            for (int mi = 0; mi < 2; mi++)
                #pragma unroll
                for (int ni = 0; ni < 4; ni++)
                    mma_tf32_16x8x8(acc[mi][ni],
                        af[mi][0], af[mi][1], af[mi][2], af[mi][3],
                        bf[ni][0], bf[ni][1]);
        }
    }

    #pragma unroll
    for (int mi = 0; mi < 2; mi++) {
        #pragma unroll
        for (int ni = 0; ni < 4; ni++) {
            int lr = m0 + wm*32 + mi*16 + gr;
            int lc = wn*32 + ni*8 + gc*2;
            const float* a = acc[mi][ni];
            float d0 = cvt_tf32(a[0]), d1 = cvt_tf32(a[1]);
            float d2 = cvt_tf32(a[2]), d3 = cvt_tf32(a[3]);
            int ldc = flatC ? CDIM : DH;
            *reinterpret_cast<float2*>(&C[(size_t)lr * ldc + lc]) = make_float2(d0, d1);
            *reinterpret_cast<float2*>(&C[(size_t)(lr+8) * ldc + lc]) = make_float2(d2, d3);
        }
    }
}

// ---------------- batched 2D transpose (tf32-rounded output) ----------------
__global__ void transpose_kernel(const float* __restrict__ in, float* __restrict__ out,
                                 int R, int C) {
    __shared__ float tile[32][33];
    const int z = blockIdx.z;
    in  += (size_t)z * R * C;
    out += (size_t)z * R * C;
    int c0 = blockIdx.x * 32, r0 = blockIdx.y * 32;
    int tx = threadIdx.x, ty = threadIdx.y;
    #pragma unroll
    for (int j = 0; j < 4; j++)
        tile[ty + j*8][tx] = in[(size_t)(r0 + ty + j*8) * C + c0 + tx];
    __syncthreads();
    #pragma unroll
    for (int j = 0; j < 4; j++)
        out[(size_t)(c0 + ty + j*8) * R + r0 + tx] = cvt_tf32(tile[tx][ty + j*8]);
}

// ================= tf32 pinv batched GEMM: Cn = c1*U + c2*(P @ B), B row-major =================
__global__ void __launch_bounds__(256, 2) pinv_mma_kernel(
    const float* __restrict__ P, const float* __restrict__ B,
    const float* __restrict__ U, float* __restrict__ Cn,
    float c1, float c2)
{
    extern __shared__ float sm[];
    const int tid = threadIdx.x;
    const int wid = tid >> 5, lane = tid & 31;
    const int wm = wid >> 2, wn = wid & 3;
    const int gr = lane >> 2, gc = lane & 3;
    const int tile = blockIdx.x;
    const int batch = tile >> 2;
    const int m0 = ((tile >> 1) & 1) << 7;
    const int n0 = (tile & 1) << 7;
    const size_t boff = (size_t)batch << 16;
    P += boff + (size_t)m0 * ML;
    B += boff + n0;
    if (U) U += boff;
    Cn += boff;

    float acc[4][4][4];
    #pragma unroll
    for (int mi = 0; mi < 4; mi++)
        #pragma unroll
        for (int ni = 0; ni < 4; ni++)
            #pragma unroll
            for (int e = 0; e < 4; e++) acc[mi][ni][e] = 0.f;
    mainloop128x128_rowB(P, B, ML, ML, 8, sm, tid, acc);

    #pragma unroll
    for (int mi = 0; mi < 4; mi++) {
        #pragma unroll
        for (int ni = 0; ni < 4; ni++) {
            int lr = wm*64 + mi*16 + gr;
            int lc = wn*32 + ni*8 + gc*2;
            int grow = m0 + lr, gcol = n0 + lc;
            const float* a = acc[mi][ni];
            float d0, d1, d2, d3;
            if (U) {
                float2 u0 = *reinterpret_cast<const float2*>(&U[(size_t)grow * ML + gcol]);
                float2 u1 = *reinterpret_cast<const float2*>(&U[(size_t)(grow+8) * ML + gcol]);
                d0 = c1*u0.x + c2*a[0]; d1 = c1*u0.y + c2*a[1];
                d2 = c1*u1.x + c2*a[2]; d3 = c1*u1.y + c2*a[3];
            } else {
                d0 = c2*a[0]; d1 = c2*a[1]; d2 = c2*a[2]; d3 = c2*a[3];
            }
            d0 = cvt_tf32(d0); d1 = cvt_tf32(d1); d2 = cvt_tf32(d2); d3 = cvt_tf32(d3);
            *reinterpret_cast<float2*>(&Cn[(size_t)grow * ML + gcol]) = make_float2(d0, d1);
            *reinterpret_cast<float2*>(&Cn[(size_t)(grow+8) * ML + gcol]) = make_float2(d2, d3);
        }
    }
}

// ---------------- landmark means (tf32-rounded) ----------------
__global__ void land_kernel() {
    int idx = blockIdx.x * blockDim.x + threadIdx.x;
    if (idx >= BHN*ML*DH) return;
    int d  = idx & 63;
    int j  = (idx >> 6) & 255;
    int bh = idx >> 14;
    size_t base = ((size_t)bh * NTOK + j*4) * DH + d;
    g_ql[idx] = cvt_tf32(0.25f * (g_q[base] + g_q[base+64] + g_q[base+128] + g_q[base+192]));
    g_kl[idx] = cvt_tf32(0.25f * (g_k[base] + g_k[base+64] + g_k[base+128] + g_k[base+192]));
}

// ---------------- row softmax (tf32-rounded output) ----------------
template<int W>
__global__ void softmax_kernel(float* __restrict__ data) {
    __shared__ float red[256];
    float* row = data + (size_t)blockIdx.x * W;
    int t = threadIdx.x;
    constexpr int PE = W / 256;
    float vals[PE];
    float mx = -1e30f;
    #pragma unroll
    for (int e = 0; e < PE; e++) { vals[e] = row[t + e*256]; mx = fmaxf(mx, vals[e]); }
    red[t] = mx; __syncthreads();
    #pragma unroll
    for (int s = 128; s > 0; s >>= 1) { if (t < s) red[t] = fmaxf(red[t], red[t+s]); __syncthreads(); }
    mx = red[0];
    __syncthreads();
    float sum = 0.f;
    #pragma unroll
    for (int e = 0; e < PE; e++) { vals[e] = expf(vals[e] - mx); sum += vals[e]; }
    red[t] = sum; __syncthreads();
    #pragma unroll
    for (int s = 128; s > 0; s >>= 1) { if (t < s) red[t] += red[t+s]; __syncthreads(); }
    float inv = 1.0f / red[0];
    #pragma unroll
    for (int e = 0; e < PE; e++) row[t + e*256] = cvt_tf32(vals[e] * inv);
}

// ---------------- pinv scale reductions ----------------
__global__ void reset_max_kernel() { if (threadIdx.x == 0) { g_colmax = 0u; g_rowmax = 0u; } }

__global__ void colmax_kernel() {
    int gw = (blockIdx.x * blockDim.x + threadIdx.x) >> 5;
    int lane = threadIdx.x & 31;
    if (gw >= BHN * ML) return;
    const float* row = g_attn2 + (size_t)gw * ML;
    float s = 0.f;
    #pragma unroll
    for (int j = lane; j < ML; j += 32) s += fabsf(row[j]);
    #pragma unroll
    for (int o = 16; o > 0; o >>= 1) s += __shfl_down_sync(0xffffffffu, s, o);
    if (lane == 0) atomicMax(&g_colmax, __float_as_uint(s));
}

__global__ void rowmax_kernel() {
    int idx = blockIdx.x * blockDim.x + threadIdx.x;
    if (idx >= BHN * ML) return;
    int bh = idx >> 8, j = idx & 255;
    const float* base = g_attn2 + (size_t)bh * ML * ML + j;
    float s = 0.f;
    for (int i = 0; i < ML; i++) s += fabsf(base[(size_t)i * ML]);
    atomicMax(&g_rowmax, __float_as_uint(s));
}

// zinit: z0 (bf16, row + transposed) and a2h (bf16 of a2)
__global__ void zinit_kernel() {
    float inv = 1.0f / (__uint_as_float(g_colmax) * __uint_as_float(g_rowmax));
    size_t idx = (size_t)blockIdx.x * 256 + threadIdx.x;
    int j  = idx & 255;
    int i  = (idx >> 8) & 255;
    size_t bh = idx >> 16;
    float a2v  = g_attn2[idx];
    float a2tv = g_attn2[(bh << 16) + ((size_t)j << 8) + i];
    g_zhA[idx]  = __float2bfloat16(a2tv * inv);   // z0 row-major = scaled x^T
    g_zhTA[idx] = __float2bfloat16(a2v * inv);    // z0^T = scaled x
    g_a2h[idx]  = __float2bfloat16(a2v);
}

// ---------------- depthwise 33-tap conv residual (tf32-rounded add) ----------------
__global__ void res_add_kernel(const float* __restrict__ rk) {
    __shared__ float ker[KSZ];
    int blk = blockIdx.x;
    int bh = blk >> 8;
    int ichunk = blk & 255;
    int h = bh & 7, b = bh >> 3;
    if (threadIdx.x < KSZ) ker[threadIdx.x] = rk[h*KSZ + threadIdx.x];
    __syncthreads();
    int d = threadIdx.x & 63;
    int i = ichunk * 4 + (threadIdx.x >> 6);
    const float* vb = g_v + (size_t)bh * NTOK * DH;
    float s = 0.f;
    #pragma unroll
    for (int t = 0; t < KSZ; t++) {
        int ii = i + t - (KSZ/2);
        if (ii >= 0 && ii < NTOK) s += ker[t] * vb[(size_t)ii * DH + d];
    }
    size_t o = ((size_t)(b*NTOK + i)) * CDIM + h*64 + d;
    g_outf[o] = cvt_tf32(g_outf[o] + s);
}

// ---------------- host ----------------
extern "C" void kernel_launch(void* const* d_in, const int* in_sizes, int n_in,
                              void* d_out, int out_size) {
    const float* x     = (const float*)d_in[0];
    const float* w_qkv = (const float*)d_in[1];
    const float* w_out = (const float*)d_in[2];
    const float* b_out = (const float*)d_in[3];
    const float* rk    = (const float*)d_in[4];
    float* out = (float*)d_out;

    float *xt, *wqkvT, *woutT, *q, *k, *v, *ql, *kl, *a1, *a3, *a2;
    float *zA, *zB, *xz, *t1, *t2, *av, *bv, *outf;
    __nv_bfloat16 *a2h, *zhA, *zhB, *zhTA, *zhTB, *xzh, *xzhT, *t1hT, *t2hT;
    cudaGetSymbolAddress((void**)&xt, g_xt);
    cudaGetSymbolAddress((void**)&wqkvT, g_wqkvT);
    cudaGetSymbolAddress((void**)&woutT, g_woutT);
    cudaGetSymbolAddress((void**)&q,  g_q);
    cudaGetSymbolAddress((void**)&k,  g_k);
    cudaGetSymbolAddress((void**)&v,  g_v);
    cudaGetSymbolAddress((void**)&ql, g_ql);
    cudaGetSymbolAddress((void**)&kl, g_kl);
    cudaGetSymbolAddress((void**)&a1, g_attn1);
    cudaGetSymbolAddress((void**)&a3, g_attn3);
    cudaGetSymbolAddress((void**)&a2, g_attn2);
    cudaGetSymbolAddress((void**)&zA, g_zA);
    cudaGetSymbolAddress((void**)&zB, g_zB);
    cudaGetSymbolAddress((void**)&xz, g_xz);
    cudaGetSymbolAddress((void**)&t1, g_t1);
    cudaGetSymbolAddress((void**)&t2, g_t2);
    cudaGetSymbolAddress((void**)&av, g_av);
    cudaGetSymbolAddress((void**)&bv, g_bv);
    cudaGetSymbolAddress((void**)&outf, g_outf);
    cudaGetSymbolAddress((void**)&a2h,  g_a2h);
    cudaGetSymbolAddress((void**)&zhA,  g_zhA);
    cudaGetSymbolAddress((void**)&zhB,  g_zhB);
    cudaGetSymbolAddress((void**)&zhTA, g_zhTA);
    cudaGetSymbolAddress((void**)&zhTB, g_zhTB);
    cudaGetSymbolAddress((void**)&xzh,  g_xzh);
    cudaGetSymbolAddress((void**)&xzhT, g_xzhT);
    cudaGetSymbolAddress((void**)&t1hT, g_t1hT);
    cudaGetSymbolAddress((void**)&t2hT, g_t2hT);

    cudaFuncSetAttribute(pinv_mma_kernel,    cudaFuncAttributeMaxDynamicSharedMemorySize, PB_SMEM3);
    cudaFuncSetAttribute(pinv_bf16_kernel,   cudaFuncAttributeMaxDynamicSharedMemorySize, BH_SMEM3);
    cudaFuncSetAttribute(gemm_tc_kernel,     cudaFuncAttributeMaxDynamicSharedMemorySize, G128_SMEM3);
    cudaFuncSetAttribute(qkv_tc_kernel,      cudaFuncAttributeMaxDynamicSharedMemorySize, G128_SMEM3);
    cudaFuncSetAttribute(final_tc_kernel,    cudaFuncAttributeMaxDynamicSharedMemorySize, G128_SMEM3);
    cudaFuncSetAttribute(gemm64_rowB_kernel, cudaFuncAttributeMaxDynamicSharedMemorySize, G64R_SMEM3);

    // 0) layout prep
    transpose_kernel<<<dim3(NTOK/32, CDIM/32, BATCH), dim3(32,8)>>>(x, xt, CDIM, NTOK);
    transpose_kernel<<<dim3(48, 16, 1), dim3(32,8)>>>(w_qkv, wqkvT, CDIM, 3*CDIM);
    transpose_kernel<<<dim3(16, 16, 1), dim3(32,8)>>>(w_out, woutT, CDIM, CDIM);
    // 1) QKV projection
    qkv_tc_kernel<<<dim3(12, 256), 256, G128_SMEM3>>>();
    // 2) landmarks
    land_kernel<<<(BHN*ML*DH + 255)/256, 256>>>();
    // 3) similarity GEMMs
    gemm_tc_kernel<<<dim3(2, 8, BHN), 256, G128_SMEM3>>>(q,  kl, a1, DH, DH, ML,   2,
        (size_t)NTOK*DH, (size_t)ML*DH, (size_t)NTOK*ML);
    gemm_tc_kernel<<<dim3(2, 2, BHN), 256, G128_SMEM3>>>(ql, kl, a2, DH, DH, ML,   2,
        (size_t)ML*DH,   (size_t)ML*DH, (size_t)ML*ML);
    gemm_tc_kernel<<<dim3(8, 2, BHN), 256, G128_SMEM3>>>(ql, k,  a3, DH, DH, NTOK, 2,
        (size_t)ML*DH,   (size_t)NTOK*DH, (size_t)ML*NTOK);
    // 4) softmaxes
    softmax_kernel<256> <<<BHN*NTOK, 256>>>(a1);
    softmax_kernel<256> <<<BHN*ML,   256>>>(a2);
    softmax_kernel<1024><<<BHN*ML,   256>>>(a3);
    // 5) pinv init (bf16 z0 / z0^T / a2h)
    reset_max_kernel<<<1, 32>>>();
    colmax_kernel<<<(BHN*ML*32)/256, 256>>>();
    rowmax_kernel<<<(BHN*ML)/256, 256>>>();
    zinit_kernel<<<(BHN*ML*ML)/256, 256>>>();
    // 6) Newton–Schulz: iterations 1–4 in bf16 (self-correcting), 5–6 in tf32.
    __nv_bfloat16 *zh_in = zhA, *zh_out = zhB, *zhT_in = zhTA, *zhT_out = zhTB;
    for (int it = 0; it < 4; it++) {
        pinv_bf16_kernel<<<1024, 256, BH_SMEM3>>>(a2h, zhT_in, nullptr, xzh, xzhT, nullptr, 0.0f, 1.0f);
        pinv_bf16_kernel<<<1024, 256, BH_SMEM3>>>(xzh, xzhT, xzh, nullptr, t1hT, nullptr, 7.0f, -1.0f);
        pinv_bf16_kernel<<<1024, 256, BH_SMEM3>>>(xzh, t1hT, xzh, nullptr, t2hT, nullptr, 15.0f, -1.0f);
        if (it < 3) {
            pinv_bf16_kernel<<<1024, 256, BH_SMEM3>>>(zh_in, t2hT, zh_in, zh_out, zhT_out, nullptr, 3.25f, -0.25f);
            __nv_bfloat16* tmp;
            tmp = zh_in;  zh_in  = zh_out;  zh_out  = tmp;
            tmp = zhT_in; zhT_in = zhT_out; zhT_out = tmp;
        } else {
            // hand off to fp32/tf32: z4 written tf32-rounded fp32
            pinv_bf16_kernel<<<1024, 256, BH_SMEM3>>>(zh_in, t2hT, zh_in, nullptr, nullptr, zA, 3.25f, -0.25f);
        }
    }
    float *zin = zA, *zout = zB;
    for (int it = 0; it < 2; it++) {
        pinv_mma_kernel<<<1024, 256, PB_SMEM3>>>(a2, zin, nullptr, xz, 0.0f, 1.0f);
        pinv_mma_kernel<<<1024, 256, PB_SMEM3>>>(xz, xz, xz, t1, 7.0f, -1.0f);
        pinv_mma_kernel<<<1024, 256, PB_SMEM3>>>(xz, t1, xz, t2, 15.0f, -1.0f);
        pinv_mma_kernel<<<1024, 256, PB_SMEM3>>>(zin, t2, zin, zout, 3.25f, -0.25f);
        float* tmp = zin; zin = zout; zout = tmp;
    }
    // 7) output chain: av = attn3@v ; bv = z@av ; outf = attn1@bv
    gemm64_rowB_kernel<<<dim3(2, 1, BHN), 256, G64R_SMEM3>>>(a3, v, av,
        NTOK, 32, (size_t)ML*NTOK, (size_t)NTOK*DH, 0);
    gemm64_rowB_kernel<<<dim3(2, 1, BHN), 256, G64R_SMEM3>>>(zin, av, bv,
        ML, 8, (size_t)ML*ML, (size_t)ML*DH, 0);
    gemm64_rowB_kernel<<<dim3(8, 1, BHN), 256, G64R_SMEM3>>>(a1, bv, outf,
        ML, 8, (size_t)NTOK*ML, (size_t)ML*DH, 1);
    // 8) depthwise conv residual
    res_add_kernel<<<BHN*256, 256>>>(rk);
    // 9) output projection + bias + transposed store
    final_tc_kernel<<<dim3(4, 256), 256, G128_SMEM3>>>(b_out, out);
}

// round 11
// speedup vs baseline: 3.3072x; 1.0226x over previous
#include <cuda_runtime.h>
#include <cuda_bf16.h>
#include <cstdint>
#include <cstddef>

#define BATCH 32
#define HEADS 8
#define NTOK 1024
#define DH 64
#define ML 256          // landmarks
#define CDIM 512
#define BHN (BATCH*HEADS)   // 256
#define KSZ 33

// ---------------- device scratch ----------------
__device__ float g_xt[(size_t)BATCH*NTOK*CDIM];     // x transposed: (b, n, c), tf32-rounded
__device__ float g_wqkvT[3*CDIM*CDIM];              // (1536, 512), tf32-rounded
__device__ float g_woutT[CDIM*CDIM];                // (512, 512), tf32-rounded
__device__ float g_q [BHN*NTOK*DH];
__device__ float g_k [BHN*NTOK*DH];
__device__ float g_v [BHN*NTOK*DH];
__device__ float g_ql[BHN*ML*DH];
__device__ float g_kl[BHN*ML*DH];
__device__ float g_attn1[(size_t)BHN*NTOK*ML];      // (bh,1024,256)
__device__ float g_attn3[(size_t)BHN*ML*NTOK];      // (bh,256,1024)
__device__ float g_attn2[BHN*ML*ML];
__device__ float g_zA[BHN*ML*ML];
__device__ float g_zB[BHN*ML*ML];
__device__ float g_xz[BHN*ML*ML];
__device__ float g_t1[BHN*ML*ML];
__device__ float g_t2[BHN*ML*ML];
__device__ float g_av[BHN*ML*DH];
__device__ float g_bv[BHN*ML*DH];
__device__ float g_outf[(size_t)BATCH*NTOK*CDIM];   // (b, n, 512)
__device__ unsigned g_colmax;
__device__ unsigned g_rowmax;
// bf16 pinv buffers
__device__ __nv_bfloat16 g_a2h [BHN*ML*ML];   // bf16(a2), row-major [M][K]
__device__ __nv_bfloat16 g_zhA [BHN*ML*ML];   // z row-major
__device__ __nv_bfloat16 g_zhB [BHN*ML*ML];
__device__ __nv_bfloat16 g_zhTA[BHN*ML*ML];   // z^T (K-major for B operand)
__device__ __nv_bfloat16 g_zhTB[BHN*ML*ML];
__device__ __nv_bfloat16 g_xzh [BHN*ML*ML];
__device__ __nv_bfloat16 g_xzhT[BHN*ML*ML];
__device__ __nv_bfloat16 g_t1hT[BHN*ML*ML];
__device__ __nv_bfloat16 g_t2hT[BHN*ML*ML];

// ================= helpers =================
__device__ __forceinline__ float cvt_tf32(float x) {
    uint32_t u;
    asm("cvt.rna.tf32.f32 %0, %1;" : "=r"(u) : "f"(x));
    return __uint_as_float(u);
}
__device__ __forceinline__ void mma_tf32_16x8x8(float c[4],
    uint32_t a0, uint32_t a1, uint32_t a2, uint32_t a3, uint32_t b0, uint32_t b1) {
    asm volatile(
        "mma.sync.aligned.m16n8k8.row.col.f32.tf32.tf32.f32 "
        "{%0,%1,%2,%3},{%4,%5,%6,%7},{%8,%9},{%0,%1,%2,%3};"
        : "+f"(c[0]), "+f"(c[1]), "+f"(c[2]), "+f"(c[3])
        : "r"(a0), "r"(a1), "r"(a2), "r"(a3), "r"(b0), "r"(b1));
}
__device__ __forceinline__ void mma_bf16_16x8x16(float c[4],
    uint32_t a0, uint32_t a1, uint32_t a2, uint32_t a3, uint32_t b0, uint32_t b1) {
    asm volatile(
        "mma.sync.aligned.m16n8k16.row.col.f32.bf16.bf16.f32 "
        "{%0,%1,%2,%3},{%4,%5,%6,%7},{%8,%9},{%0,%1,%2,%3};"
        : "+f"(c[0]), "+f"(c[1]), "+f"(c[2]), "+f"(c[3])
        : "r"(a0), "r"(a1), "r"(a2), "r"(a3), "r"(b0), "r"(b1));
}
__device__ __forceinline__ void ldsm_x4(uint32_t& r0, uint32_t& r1,
                                        uint32_t& r2, uint32_t& r3, uint32_t saddr) {
    asm volatile("ldmatrix.sync.aligned.m8n8.x4.shared.b16 {%0,%1,%2,%3}, [%4];"
                 : "=r"(r0), "=r"(r1), "=r"(r2), "=r"(r3) : "r"(saddr));
}
__device__ __forceinline__ void cp16(uint32_t dst, const void* src) {
    asm volatile("cp.async.cg.shared.global [%0], [%1], 16;" :: "r"(dst), "l"(src));
}
#define CP_COMMIT() asm volatile("cp.async.commit_group;")
#define CP_WAIT1()  asm volatile("cp.async.wait_group 1;" ::: "memory")
#define CP_WAIT0()  asm volatile("cp.async.wait_group 0;" ::: "memory")

#define PPITCH 36
#define PSTAGE (128*PPITCH)
#define G128_SMEM3 (6*PSTAGE*4)                     // 110592 (A,B both K-major fp32)

#define BNP128 136
#define BRSTG128 (32*BNP128)
#define PB_SMEM3 ((3*PSTAGE + 3*BRSTG128)*4)        // 107520

#define BNP64 72
#define BRSTG64 (32*BNP64)
#define G64R_SMEM3 ((3*PSTAGE + 3*BRSTG64)*4)       // 82944

// bf16 tiles: [128 rows][KPH halves] per chunk (32 halves data, pitch 40)
#define KPH 40
#define HSTG (128*KPH)                               // halves per stage
#define BH_SMEM3 (6*HSTG*2)                          // 61440 bytes

// ============ mainloop A: B stored K-major ([N rows][K]) — sims/qkv/final ============
__device__ __forceinline__ void mainloop128x128(
    const float* __restrict__ A, const float* __restrict__ B,
    int lda, int ldb, int kch, float* sm, int tid, float acc[4][4][4])
{
    const uint32_t sbase = (uint32_t)__cvta_generic_to_shared(sm);
    const uint32_t bbase = sbase + 3*PSTAGE*4;
    const int wid = tid >> 5, lane = tid & 31;
    const int wm = wid >> 2, wn = wid & 3;
    const int g = lane >> 3, r8 = lane & 7;
    const uint32_t a_lm = (uint32_t)((wm*64 + (g&1)*8 + r8)*PPITCH + (g>>1)*4)*4;
    const uint32_t b_lm = (uint32_t)((wn*32 + (g>>1)*8 + r8)*PPITCH + (g&1)*4)*4;
    int rrow[4], rc4[4];
    #pragma unroll
    for (int e = 0; e < 4; e++) {
        int f4 = e * 256 + tid;
        rrow[e] = f4 >> 3;
        rc4[e] = (f4 & 7) << 2;
    }
    #pragma unroll
    for (int p = 0; p < 2; p++) {
        if (p < kch) {
            const int k0 = p * 32;
            #pragma unroll
            for (int e = 0; e < 4; e++) {
                cp16(sbase + (uint32_t)(p*PSTAGE + rrow[e]*PPITCH + rc4[e])*4,
                     &A[(size_t)rrow[e] * lda + k0 + rc4[e]]);
                cp16(bbase + (uint32_t)(p*PSTAGE + rrow[e]*PPITCH + rc4[e])*4,
                     &B[(size_t)rrow[e] * ldb + k0 + rc4[e]]);
            }
        }
        CP_COMMIT();
    }
    for (int c = 0; c < kch; c++) {
        const int st = c % 3;
        if (c + 1 < kch) { CP_WAIT1(); } else { CP_WAIT0(); }
        __syncthreads();
        if (c + 2 < kch) {
            const int nst = (c + 2) % 3;
            const int k0 = (c + 2) * 32;
            #pragma unroll
            for (int e = 0; e < 4; e++) {
                cp16(sbase + (uint32_t)(nst*PSTAGE + rrow[e]*PPITCH + rc4[e])*4,
                     &A[(size_t)rrow[e] * lda + k0 + rc4[e]]);
                cp16(bbase + (uint32_t)(nst*PSTAGE + rrow[e]*PPITCH + rc4[e])*4,
                     &B[(size_t)rrow[e] * ldb + k0 + rc4[e]]);
            }
            CP_COMMIT();
        }
        const uint32_t a_st = sbase + (uint32_t)(st*PSTAGE)*4 + a_lm;
        const uint32_t b_st = bbase + (uint32_t)(st*PSTAGE)*4 + b_lm;
        #pragma unroll
        for (int ks = 0; ks < 4; ks++) {
            uint32_t af[4][4];
            #pragma unroll
            for (int mi = 0; mi < 4; mi++)
                ldsm_x4(af[mi][0], af[mi][1], af[mi][2], af[mi][3],
                        a_st + (uint32_t)(mi*16*PPITCH + ks*8)*4);
            uint32_t bf[4][2];
            #pragma unroll
            for (int p = 0; p < 2; p++)
                ldsm_x4(bf[2*p][0], bf[2*p][1], bf[2*p+1][0], bf[2*p+1][1],
                        b_st + (uint32_t)(p*16*PPITCH + ks*8)*4);
            #pragma unroll
            for (int mi = 0; mi < 4; mi++)
                #pragma unroll
                for (int ni = 0; ni < 4; ni++)
                    mma_tf32_16x8x8(acc[mi][ni],
                        af[mi][0], af[mi][1], af[mi][2], af[mi][3],
                        bf[ni][0], bf[ni][1]);
        }
    }
}

// ============ mainloop B: B stored row-major [K][N] — tf32 pinv/chain ============
__device__ __forceinline__ void mainloop128x128_rowB(
    const float* __restrict__ A, const float* __restrict__ B,
    int lda, int ldb, int kch, float* sm, int tid, float acc[4][4][4])
{
    const uint32_t sbase = (uint32_t)__cvta_generic_to_shared(sm);
    const uint32_t bbase = sbase + 3*PSTAGE*4;
    const int wid = tid >> 5, lane = tid & 31;
    const int gr = lane >> 2, gc = lane & 3;
    const int wm = wid >> 2, wn = wid & 3;
    const int g = lane >> 3, r8 = lane & 7;
    const uint32_t a_lm = (uint32_t)((wm*64 + (g&1)*8 + r8)*PPITCH + (g>>1)*4)*4;
    int arow[4], ac4[4], bk[4], bn4[4];
    #pragma unroll
    for (int e = 0; e < 4; e++) {
        int f4 = e * 256 + tid;
        arow[e] = f4 >> 3;  ac4[e] = (f4 & 7) << 2;
        bk[e]   = f4 >> 5;  bn4[e] = (f4 & 31) << 2;
    }
    #pragma unroll
    for (int p = 0; p < 2; p++) {
        if (p < kch) {
            const int k0 = p * 32;
            #pragma unroll
            for (int e = 0; e < 4; e++) {
                cp16(sbase + (uint32_t)(p*PSTAGE + arow[e]*PPITCH + ac4[e])*4,
                     &A[(size_t)arow[e] * lda + k0 + ac4[e]]);
                cp16(bbase + (uint32_t)(p*BRSTG128 + bk[e]*BNP128 + bn4[e])*4,
                     &B[(size_t)(k0 + bk[e]) * ldb + bn4[e]]);
            }
        }
        CP_COMMIT();
    }
    for (int c = 0; c < kch; c++) {
        const int st = c % 3;
        if (c + 1 < kch) { CP_WAIT1(); } else { CP_WAIT0(); }
        __syncthreads();
        if (c + 2 < kch) {
            const int nst = (c + 2) % 3;
            const int k0 = (c + 2) * 32;
            #pragma unroll
            for (int e = 0; e < 4; e++) {
                cp16(sbase + (uint32_t)(nst*PSTAGE + arow[e]*PPITCH + ac4[e])*4,
                     &A[(size_t)arow[e] * lda + k0 + ac4[e]]);
                cp16(bbase + (uint32_t)(nst*BRSTG128 + bk[e]*BNP128 + bn4[e])*4,
                     &B[(size_t)(k0 + bk[e]) * ldb + bn4[e]]);
            }
            CP_COMMIT();
        }
        const uint32_t a_st = sbase + (uint32_t)(st*PSTAGE)*4 + a_lm;
        const float* Bb = sm + 3*PSTAGE + st*BRSTG128;
        #pragma unroll
        for (int ks = 0; ks < 4; ks++) {
            uint32_t af[4][4];
            #pragma unroll
            for (int mi = 0; mi < 4; mi++)
                ldsm_x4(af[mi][0], af[mi][1], af[mi][2], af[mi][3],
                        a_st + (uint32_t)(mi*16*PPITCH + ks*8)*4);
            uint32_t bf[4][2];
            #pragma unroll
            for (int ni = 0; ni < 4; ni++) {
                int n = wn*32 + ni*8 + gr;
                bf[ni][0] = __float_as_uint(Bb[(ks*8 + gc)*BNP128 + n]);
                bf[ni][1] = __float_as_uint(Bb[(ks*8 + gc + 4)*BNP128 + n]);
            }
            #pragma unroll
            for (int mi = 0; mi < 4; mi++)
                #pragma unroll
                for (int ni = 0; ni < 4; ni++)
                    mma_tf32_16x8x8(acc[mi][ni],
                        af[mi][0], af[mi][1], af[mi][2], af[mi][3],
                        bf[ni][0], bf[ni][1]);
        }
    }
}

// ============ bf16 pinv batched GEMM: D = c1*U + c2*(A @ B^T), both K-major ============
// Outputs (each optional): Cn bf16 [M][N], Ct bf16 [N][M], Cf fp32 tf32-rounded [M][N].
__global__ void __launch_bounds__(256, 2) pinv_bf16_kernel(
    const __nv_bfloat16* __restrict__ A, const __nv_bfloat16* __restrict__ B,
    const __nv_bfloat16* __restrict__ U,
    __nv_bfloat16* __restrict__ Cn, __nv_bfloat16* __restrict__ Ct,
    float* __restrict__ Cf, float c1, float c2)
{
    extern __shared__ __nv_bfloat16 smh[];
    const uint32_t sbase = (uint32_t)__cvta_generic_to_shared(smh);
    const uint32_t bbase = sbase + 3*HSTG*2;
    const int tid = threadIdx.x;
    const int wid = tid >> 5, lane = tid & 31;
    const int wm = wid >> 2, wn = wid & 3;
    const int gr = lane >> 2, gc = lane & 3;
    const int mtx = lane >> 3, mrow = lane & 7;
    const uint32_t a_lm = ((uint32_t)(((mtx&1)*8 + mrow)) * KPH + (uint32_t)((mtx>>1)*8)) * 2;
    const uint32_t b_lm = ((uint32_t)(((mtx>>1)*8 + mrow)) * KPH + (uint32_t)((mtx&1)*8)) * 2;

    const int tile = blockIdx.x;
    const int batch = tile >> 2;
    const int m0 = ((tile >> 1) & 1) << 7;
    const int n0 = (tile & 1) << 7;
    const size_t boff = (size_t)batch << 16;
    A += boff + (size_t)m0 * ML;
    B += boff + (size_t)n0 * ML;
    if (U)  U  += boff;
    if (Cn) Cn += boff;
    if (Ct) Ct += boff;
    if (Cf) Cf += boff;

    int crow[2], cseg[2];
    #pragma unroll
    for (int e = 0; e < 2; e++) {
        int f = e * 256 + tid;
        crow[e] = f >> 2;
        cseg[e] = (f & 3) * 8;
    }

    float acc[4][4][4];
    #pragma unroll
    for (int mi = 0; mi < 4; mi++)
        #pragma unroll
        for (int ni = 0; ni < 4; ni++)
            #pragma unroll
            for (int e = 0; e < 4; e++) acc[mi][ni][e] = 0.f;

    #pragma unroll
    for (int p = 0; p < 2; p++) {
        const int k0 = p * 32;
        #pragma unroll
        for (int e = 0; e < 2; e++) {
            cp16(sbase + (uint32_t)(p*HSTG + crow[e]*KPH + cseg[e])*2,
                 &A[(size_t)crow[e] * ML + k0 + cseg[e]]);
            cp16(bbase + (uint32_t)(p*HSTG + crow[e]*KPH + cseg[e])*2,
                 &B[(size_t)crow[e] * ML + k0 + cseg[e]]);
        }
        CP_COMMIT();
    }
    for (int c = 0; c < 8; c++) {
        const int st = c % 3;
        if (c + 1 < 8) { CP_WAIT1(); } else { CP_WAIT0(); }
        __syncthreads();
        if (c + 2 < 8) {
            const int nst = (c + 2) % 3;
            const int k0 = (c + 2) * 32;
            #pragma unroll
            for (int e = 0; e < 2; e++) {
                cp16(sbase + (uint32_t)(nst*HSTG + crow[e]*KPH + cseg[e])*2,
                     &A[(size_t)crow[e] * ML + k0 + cseg[e]]);
                cp16(bbase + (uint32_t)(nst*HSTG + crow[e]*KPH + cseg[e])*2,
                     &B[(size_t)crow[e] * ML + k0 + cseg[e]]);
            }
            CP_COMMIT();
        }
        const uint32_t a_st = sbase + (uint32_t)(st*HSTG)*2 + a_lm;
        const uint32_t b_st = bbase + (uint32_t)(st*HSTG)*2 + b_lm;
        #pragma unroll
        for (int ks = 0; ks < 2; ks++) {
            uint32_t af[4][4];
            #pragma unroll
            for (int mi = 0; mi < 4; mi++)
                ldsm_x4(af[mi][0], af[mi][1], af[mi][2], af[mi][3],
                        a_st + (uint32_t)((wm*64 + mi*16)*KPH + ks*16)*2);
            uint32_t bf[4][2];
            #pragma unroll
            for (int p = 0; p < 2; p++)
                ldsm_x4(bf[2*p][0], bf[2*p][1], bf[2*p+1][0], bf[2*p+1][1],
                        b_st + (uint32_t)((wn*32 + p*16)*KPH + ks*16)*2);
            #pragma unroll
            for (int mi = 0; mi < 4; mi++)
                #pragma unroll
                for (int ni = 0; ni < 4; ni++)
                    mma_bf16_16x8x16(acc[mi][ni],
                        af[mi][0], af[mi][1], af[mi][2], af[mi][3],
                        bf[ni][0], bf[ni][1]);
        }
    }

    #pragma unroll
    for (int mi = 0; mi < 4; mi++) {
        #pragma unroll
        for (int ni = 0; ni < 4; ni++) {
            int grow = m0 + wm*64 + mi*16 + gr;
            int gcol = n0 + wn*32 + ni*8 + gc*2;
            const float* a = acc[mi][ni];
            float d0, d1, d2, d3;
            if (U) {
                __nv_bfloat162 u0 = *reinterpret_cast<const __nv_bfloat162*>(&U[(size_t)grow * ML + gcol]);
                __nv_bfloat162 u1 = *reinterpret_cast<const __nv_bfloat162*>(&U[(size_t)(grow+8) * ML + gcol]);
                d0 = c1*__bfloat162float(u0.x) + c2*a[0];
                d1 = c1*__bfloat162float(u0.y) + c2*a[1];
                d2 = c1*__bfloat162float(u1.x) + c2*a[2];
                d3 = c1*__bfloat162float(u1.y) + c2*a[3];
            } else {
                d0 = c2*a[0]; d1 = c2*a[1]; d2 = c2*a[2]; d3 = c2*a[3];
            }
            __nv_bfloat16 h0 = __float2bfloat16(d0), h1 = __float2bfloat16(d1);
            __nv_bfloat16 h2 = __float2bfloat16(d2), h3 = __float2bfloat16(d3);
            if (Cn) {
                __nv_bfloat162 p0; p0.x = h0; p0.y = h1;
                __nv_bfloat162 p1; p1.x = h2; p1.y = h3;
                *reinterpret_cast<__nv_bfloat162*>(&Cn[(size_t)grow * ML + gcol]) = p0;
                *reinterpret_cast<__nv_bfloat162*>(&Cn[(size_t)(grow+8) * ML + gcol]) = p1;
            }
            if (Ct) {
                Ct[(size_t)gcol * ML + grow]       = h0;
                Ct[(size_t)(gcol+1) * ML + grow]   = h1;
                Ct[(size_t)gcol * ML + grow+8]     = h2;
                Ct[(size_t)(gcol+1) * ML + grow+8] = h3;
            }
            if (Cf) {
                *reinterpret_cast<float2*>(&Cf[(size_t)grow * ML + gcol]) =
                    make_float2(cvt_tf32(d0), cvt_tf32(d1));
                *reinterpret_cast<float2*>(&Cf[(size_t)(grow+8) * ML + gcol]) =
                    make_float2(cvt_tf32(d2), cvt_tf32(d3));
            }
        }
    }
}

// ============ plain batched GEMM: C[z] = A[z] @ B[z]^T (B K-major; sims) ============
__global__ void __launch_bounds__(256, 2) gemm_tc_kernel(
    const float* __restrict__ A, const float* __restrict__ B, float* __restrict__ C,
    int lda, int ldb, int ldc, int kch,
    size_t sA, size_t sB, size_t sC)
{
    extern __shared__ float sm[];
    const int tid = threadIdx.x;
    const int z = blockIdx.z;
    const int m0 = blockIdx.y * 128, n0 = blockIdx.x * 128;
    A += (size_t)z * sA + (size_t)m0 * lda;
    B += (size_t)z * sB + (size_t)n0 * ldb;
    C += (size_t)z * sC;
    float acc[4][4][4];
    #pragma unroll
    for (int mi = 0; mi < 4; mi++)
        #pragma unroll
        for (int ni = 0; ni < 4; ni++)
            #pragma unroll
            for (int e = 0; e < 4; e++) acc[mi][ni][e] = 0.f;
    mainloop128x128(A, B, lda, ldb, kch, sm, tid, acc);
    const int wid = tid >> 5, lane = tid & 31;
    const int gr = lane >> 2, gc = lane & 3;
    const int wm = wid >> 2, wn = wid & 3;
    #pragma unroll
    for (int mi = 0; mi < 4; mi++) {
        #pragma unroll
        for (int ni = 0; ni < 4; ni++) {
            int lr = m0 + wm*64 + mi*16 + gr;
            int lc = n0 + wn*32 + ni*8 + gc*2;
            const float* a = acc[mi][ni];
            *reinterpret_cast<float2*>(&C[(size_t)lr * ldc + lc]) = make_float2(a[0], a[1]);
            *reinterpret_cast<float2*>(&C[(size_t)(lr+8) * ldc + lc]) = make_float2(a[2], a[3]);
        }
    }
}

// ============ QKV GEMM with scatter epilogue (tf32-rounded outputs) ============
__global__ void __launch_bounds__(256, 2) qkv_tc_kernel(void) {
    extern __shared__ float sm[];
    const int tid = threadIdx.x;
    const int m0 = blockIdx.y * 128;
    const int n0 = blockIdx.x * 128;
    const float* A = g_xt + (size_t)m0 * CDIM;
    const float* B = g_wqkvT + (size_t)n0 * CDIM;
    float acc[4][4][4];
    #pragma unroll
    for (int mi = 0; mi < 4; mi++)
        #pragma unroll
        for (int ni = 0; ni < 4; ni++)
            #pragma unroll
            for (int e = 0; e < 4; e++) acc[mi][ni][e] = 0.f;
    mainloop128x128(A, B, CDIM, CDIM, CDIM/32, sm, tid, acc);
    const int wid = tid >> 5, lane = tid & 31;
    const int gr = lane >> 2, gc = lane & 3;
    const int wm = wid >> 2, wn = wid & 3;
    #pragma unroll
    for (int mi = 0; mi < 4; mi++) {
        int m = m0 + wm*64 + mi*16 + gr;
        int b = m >> 10, i = m & 1023;
        #pragma unroll
        for (int ni = 0; ni < 4; ni++) {
            int n = n0 + wn*32 + ni*8 + gc*2;
            int which = n >> 9;
            int h = (n >> 6) & 7;
            int d = n & 63;
            int bh = b*8 + h;
            float* dst = (which == 0) ? g_q : ((which == 1) ? g_k : g_v);
            float sc = (which == 0) ? 0.125f : 1.0f;
            const float* a = acc[mi][ni];
            float r0 = cvt_tf32(a[0]*sc), r1 = cvt_tf32(a[1]*sc);
            float r2 = cvt_tf32(a[2]*sc), r3 = cvt_tf32(a[3]*sc);
            *reinterpret_cast<float2*>(&dst[((size_t)(bh*NTOK + i))*DH + d]) = make_float2(r0, r1);
            *reinterpret_cast<float2*>(&dst[((size_t)(bh*NTOK + i + 8))*DH + d]) = make_float2(r2, r3);
        }
    }
}

// ============ final GEMM: out = outf @ woutT^T + bias, transposed store (fp32) ============
__global__ void __launch_bounds__(256, 2) final_tc_kernel(
    const float* __restrict__ bias, float* __restrict__ out)
{
    extern __shared__ float sm[];
    const int tid = threadIdx.x;
    const int m0 = blockIdx.y * 128;
    const int n0 = blockIdx.x * 128;
    const float* A = g_outf + (size_t)m0 * CDIM;
    const float* B = g_woutT + (size_t)n0 * CDIM;
    float acc[4][4][4];
    #pragma unroll
    for (int mi = 0; mi < 4; mi++)
        #pragma unroll
        for (int ni = 0; ni < 4; ni++)
            #pragma unroll
            for (int e = 0; e < 4; e++) acc[mi][ni][e] = 0.f;
    mainloop128x128(A, B, CDIM, CDIM, CDIM/32, sm, tid, acc);
    const int wid = tid >> 5, lane = tid & 31;
    const int gr = lane >> 2, gc = lane & 3;
    const int wm = wid >> 2, wn = wid & 3;
    #pragma unroll
    for (int mi = 0; mi < 4; mi++) {
        int m = m0 + wm*64 + mi*16 + gr;
        int b = m >> 10, i = m & 1023;
        #pragma unroll
        for (int ni = 0; ni < 4; ni++) {
            int n = n0 + wn*32 + ni*8 + gc*2;
            const float* a = acc[mi][ni];
            float b0 = bias[n], b1 = bias[n+1];
            out[((size_t)(b*CDIM + n))*NTOK + i]       = a[0] + b0;
            out[((size_t)(b*CDIM + n + 1))*NTOK + i]   = a[1] + b1;
            out[((size_t)(b*CDIM + n))*NTOK + i + 8]   = a[2] + b0;
            out[((size_t)(b*CDIM + n + 1))*NTOK + i + 8] = a[3] + b1;
        }
    }
}

// ============ 128x64 batched GEMM, B row-major [K,64]: C = A @ B ============
__global__ void __launch_bounds__(256, 2) gemm64_rowB_kernel(
    const float* __restrict__ A, const float* __restrict__ B, float* __restrict__ C,
    int lda, int kch, size_t sA, size_t sB, int flatC)
{
    extern __shared__ float sm[];
    const uint32_t sbase = (uint32_t)__cvta_generic_to_shared(sm);
    const uint32_t bbase = sbase + 3*PSTAGE*4;
    const int tid = threadIdx.x;
    const int wid = tid >> 5, lane = tid & 31;
    const int gr = lane >> 2, gc = lane & 3;
    const int wm = wid >> 1, wn = wid & 1;
    const int g = lane >> 3, r8 = lane & 7;
    const uint32_t a_lm = (uint32_t)((wm*32 + (g&1)*8 + r8)*PPITCH + (g>>1)*4)*4;
    const int z = blockIdx.z;
    const int m0 = blockIdx.x * 128;
    A += (size_t)z * sA + (size_t)m0 * lda;
    B += (size_t)z * sB;
    if (flatC) C += (size_t)(z >> 3) * (NTOK*CDIM) + (size_t)(z & 7) * DH;
    else       C += (size_t)z * (ML*DH);

    int arow[4], ac4[4], bk[2], bn4[2];
    #pragma unroll
    for (int e = 0; e < 4; e++) {
        int f4 = e * 256 + tid;
        arow[e] = f4 >> 3;  ac4[e] = (f4 & 7) << 2;
    }
    #pragma unroll
    for (int e = 0; e < 2; e++) {
        int f4 = e * 256 + tid;
        bk[e] = f4 >> 4;  bn4[e] = (f4 & 15) << 2;
    }

    float acc[2][4][4];
    #pragma unroll
    for (int mi = 0; mi < 2; mi++)
        #pragma unroll
        for (int ni = 0; ni < 4; ni++)
            #pragma unroll
            for (int e = 0; e < 4; e++) acc[mi][ni][e] = 0.f;

    #pragma unroll
    for (int p = 0; p < 2; p++) {
        if (p < kch) {
            const int k0 = p * 32;
            #pragma unroll
            for (int e = 0; e < 4; e++)
                cp16(sbase + (uint32_t)(p*PSTAGE + arow[e]*PPITCH + ac4[e])*4,
                     &A[(size_t)arow[e] * lda + k0 + ac4[e]]);
            #pragma unroll
            for (int e = 0; e < 2; e++)
                cp16(bbase + (uint32_t)(p*BRSTG64 + bk[e]*BNP64 + bn4[e])*4,
                     &B[(size_t)(k0 + bk[e]) * DH + bn4[e]]);
        }
        CP_COMMIT();
    }

    for (int c = 0; c < kch; c++) {
        const int st = c % 3;
        if (c + 1 < kch) { CP_WAIT1(); } else { CP_WAIT0(); }
        __syncthreads();
        if (c + 2 < kch) {
            const int nst = (c + 2) % 3;
            const int k0 = (c + 2) * 32;
            #pragma unroll
            for (int e = 0; e < 4; e++)
                cp16(sbase + (uint32_t)(nst*PSTAGE + arow[e]*PPITCH + ac4[e])*4,
                     &A[(size_t)arow[e] * lda + k0 + ac4[e]]);
            #pragma unroll
            for (int e = 0; e < 2; e++)
                cp16(bbase + (uint32_t)(nst*BRSTG64 + bk[e]*BNP64 + bn4[e])*4,
                     &B[(size_t)(k0 + bk[e]) * DH + bn4[e]]);
            CP_COMMIT();
        }
        const uint32_t a_st = sbase + (uint32_t)(st*PSTAGE)*4 + a_lm;
        const float* Bb = sm + 3*PSTAGE + st*BRSTG64;
        #pragma unroll
        for (int ks = 0; ks < 4; ks++) {
            uint32_t af[2][4];
            #pragma unroll
            for (int mi = 0; mi < 2; mi++)
                ldsm_x4(af[mi][0], af[mi][1], af[mi][2], af[mi][3],
                        a_st + (uint32_t)(mi*16*PPITCH + ks*8)*4);
            uint32_t bf[4][2];
            #pragma unroll
            for (int ni = 0; ni < 4; ni++) {
                int n = wn*32 + ni*8 + gr;
                bf[ni][0] = __float_as_uint(Bb[(ks*8 + gc)*BNP64 + n]);
                bf[ni][1] = __float_as_uint(Bb[(ks*8 + gc + 4)*BNP64 + n]);
            }
            #pragma unroll
            for (int mi = 0; mi < 2; mi++)
                #pragma unroll
                for (int ni = 0; ni < 4; ni++)
                    mma_tf32_16x8x8(acc[mi][ni],
                        af[mi][0], af[mi][1], af[mi][2], af[mi][3],
                        bf[ni][0], bf[ni][1]);
        }
    }

    #pragma unroll
    for (int mi = 0; mi < 2; mi++) {
        #pragma unroll
        for (int ni = 0; ni < 4; ni++) {
            int lr = m0 + wm*32 + mi*16 + gr;
            int lc = wn*32 + ni*8 + gc*2;
            const float* a = acc[mi][ni];
            float d0 = cvt_tf32(a[0]), d1 = cvt_tf32(a[1]);
            float d2 = cvt_tf32(a[2]), d3 = cvt_tf32(a[3]);
            int ldc = flatC ? CDIM : DH;
            *reinterpret_cast<float2*>(&C[(size_t)lr * ldc + lc]) = make_float2(d0, d1);
            *reinterpret_cast<float2*>(&C[(size_t)(lr+8) * ldc + lc]) = make_float2(d2, d3);
        }
    }
}

// ---------------- batched 2D transpose (tf32-rounded output) ----------------
__global__ void transpose_kernel(const float* __restrict__ in, float* __restrict__ out,
                                 int R, int C) {
    __shared__ float tile[32][33];
    const int z = blockIdx.z;
    in  += (size_t)z * R * C;
    out += (size_t)z * R * C;
    int c0 = blockIdx.x * 32, r0 = blockIdx.y * 32;
    int tx = threadIdx.x, ty = threadIdx.y;
    #pragma unroll
    for (int j = 0; j < 4; j++)
        tile[ty + j*8][tx] = in[(size_t)(r0 + ty + j*8) * C + c0 + tx];
    __syncthreads();
    #pragma unroll
    for (int j = 0; j < 4; j++)
        out[(size_t)(c0 + ty + j*8) * R + r0 + tx] = cvt_tf32(tile[tx][ty + j*8]);
}

// ================= tf32 pinv batched GEMM: Cn = c1*U + c2*(P @ B), B row-major =================
__global__ void __launch_bounds__(256, 2) pinv_mma_kernel(
    const float* __restrict__ P, const float* __restrict__ B,
    const float* __restrict__ U, float* __restrict__ Cn,
    float c1, float c2)
{
    extern __shared__ float sm[];
    const int tid = threadIdx.x;
    const int wid = tid >> 5, lane = tid & 31;
    const int wm = wid >> 2, wn = wid & 3;
    const int gr = lane >> 2, gc = lane & 3;
    const int tile = blockIdx.x;
    const int batch = tile >> 2;
    const int m0 = ((tile >> 1) & 1) << 7;
    const int n0 = (tile & 1) << 7;
    const size_t boff = (size_t)batch << 16;
    P += boff + (size_t)m0 * ML;
    B += boff + n0;
    if (U) U += boff;
    Cn += boff;

    float acc[4][4][4];
    #pragma unroll
    for (int mi = 0; mi < 4; mi++)
        #pragma unroll
        for (int ni = 0; ni < 4; ni++)
            #pragma unroll
            for (int e = 0; e < 4; e++) acc[mi][ni][e] = 0.f;
    mainloop128x128_rowB(P, B, ML, ML, 8, sm, tid, acc);

    #pragma unroll
    for (int mi = 0; mi < 4; mi++) {
        #pragma unroll
        for (int ni = 0; ni < 4; ni++) {
            int lr = wm*64 + mi*16 + gr;
            int lc = wn*32 + ni*8 + gc*2;
            int grow = m0 + lr, gcol = n0 + lc;
            const float* a = acc[mi][ni];
            float d0, d1, d2, d3;
            if (U) {
                float2 u0 = *reinterpret_cast<const float2*>(&U[(size_t)grow * ML + gcol]);
                float2 u1 = *reinterpret_cast<const float2*>(&U[(size_t)(grow+8) * ML + gcol]);
                d0 = c1*u0.x + c2*a[0]; d1 = c1*u0.y + c2*a[1];
                d2 = c1*u1.x + c2*a[2]; d3 = c1*u1.y + c2*a[3];
            } else {
                d0 = c2*a[0]; d1 = c2*a[1]; d2 = c2*a[2]; d3 = c2*a[3];
            }
            d0 = cvt_tf32(d0); d1 = cvt_tf32(d1); d2 = cvt_tf32(d2); d3 = cvt_tf32(d3);
            *reinterpret_cast<float2*>(&Cn[(size_t)grow * ML + gcol]) = make_float2(d0, d1);
            *reinterpret_cast<float2*>(&Cn[(size_t)(grow+8) * ML + gcol]) = make_float2(d2, d3);
        }
    }
}

// ---------------- landmark means (tf32-rounded) ----------------
__global__ void land_kernel() {
    int idx = blockIdx.x * blockDim.x + threadIdx.x;
    if (idx >= BHN*ML*DH) return;
    int d  = idx & 63;
    int j  = (idx >> 6) & 255;
    int bh = idx >> 14;
    size_t base = ((size_t)bh * NTOK + j*4) * DH + d;
    g_ql[idx] = cvt_tf32(0.25f * (g_q[base] + g_q[base+64] + g_q[base+128] + g_q[base+192]));
    g_kl[idx] = cvt_tf32(0.25f * (g_k[base] + g_k[base+64] + g_k[base+128] + g_k[base+192]));
}

// ---------------- row softmax (tf32-rounded output) ----------------
template<int W>
__global__ void softmax_kernel(float* __restrict__ data) {
    __shared__ float red[256];
    float* row = data + (size_t)blockIdx.x * W;
    int t = threadIdx.x;
    constexpr int PE = W / 256;
    float vals[PE];
    float mx = -1e30f;
    #pragma unroll
    for (int e = 0; e < PE; e++) { vals[e] = row[t + e*256]; mx = fmaxf(mx, vals[e]); }
    red[t] = mx; __syncthreads();
    #pragma unroll
    for (int s = 128; s > 0; s >>= 1) { if (t < s) red[t] = fmaxf(red[t], red[t+s]); __syncthreads(); }
    mx = red[0];
    __syncthreads();
    float sum = 0.f;
    #pragma unroll
    for (int e = 0; e < PE; e++) { vals[e] = expf(vals[e] - mx); sum += vals[e]; }
    red[t] = sum; __syncthreads();
    #pragma unroll
    for (int s = 128; s > 0; s >>= 1) { if (t < s) red[t] += red[t+s]; __syncthreads(); }
    float inv = 1.0f / red[0];
    #pragma unroll
    for (int e = 0; e < PE; e++) row[t + e*256] = cvt_tf32(vals[e] * inv);
}

// ---------------- pinv scale reductions ----------------
__global__ void reset_max_kernel() { if (threadIdx.x == 0) { g_colmax = 0u; g_rowmax = 0u; } }

__global__ void colmax_kernel() {
    int gw = (blockIdx.x * blockDim.x + threadIdx.x) >> 5;
    int lane = threadIdx.x & 31;
    if (gw >= BHN * ML) return;
    const float* row = g_attn2 + (size_t)gw * ML;
    float s = 0.f;
    #pragma unroll
    for (int j = lane; j < ML; j += 32) s += fabsf(row[j]);
    #pragma unroll
    for (int o = 16; o > 0; o >>= 1) s += __shfl_down_sync(0xffffffffu, s, o);
    if (lane == 0) atomicMax(&g_colmax, __float_as_uint(s));
}

__global__ void rowmax_kernel() {
    int idx = blockIdx.x * blockDim.x + threadIdx.x;
    if (idx >= BHN * ML) return;
    int bh = idx >> 8, j = idx & 255;
    const float* base = g_attn2 + (size_t)bh * ML * ML + j;
    float s = 0.f;
    for (int i = 0; i < ML; i++) s += fabsf(base[(size_t)i * ML]);
    atomicMax(&g_rowmax, __float_as_uint(s));
}

// zinit: z0 (bf16, row + transposed) and a2h (bf16 of a2)
__global__ void zinit_kernel() {
    float inv = 1.0f / (__uint_as_float(g_colmax) * __uint_as_float(g_rowmax));
    size_t idx = (size_t)blockIdx.x * 256 + threadIdx.x;
    int j  = idx & 255;
    int i  = (idx >> 8) & 255;
    size_t bh = idx >> 16;
    float a2v  = g_attn2[idx];
    float a2tv = g_attn2[(bh << 16) + ((size_t)j << 8) + i];
    g_zhA[idx]  = __float2bfloat16(a2tv * inv);   // z0 row-major = scaled x^T
    g_zhTA[idx] = __float2bfloat16(a2v * inv);    // z0^T = scaled x
    g_a2h[idx]  = __float2bfloat16(a2v);
}

// ---------------- depthwise 33-tap conv residual (tf32-rounded add) ----------------
__global__ void res_add_kernel(const float* __restrict__ rk) {
    __shared__ float ker[KSZ];
    int blk = blockIdx.x;
    int bh = blk >> 8;
    int ichunk = blk & 255;
    int h = bh & 7, b = bh >> 3;
    if (threadIdx.x < KSZ) ker[threadIdx.x] = rk[h*KSZ + threadIdx.x];
    __syncthreads();
    int d = threadIdx.x & 63;
    int i = ichunk * 4 + (threadIdx.x >> 6);
    const float* vb = g_v + (size_t)bh * NTOK * DH;
    float s = 0.f;
    #pragma unroll
    for (int t = 0; t < KSZ; t++) {
        int ii = i + t - (KSZ/2);
        if (ii >= 0 && ii < NTOK) s += ker[t] * vb[(size_t)ii * DH + d];
    }
    size_t o = ((size_t)(b*NTOK + i)) * CDIM + h*64 + d;
    g_outf[o] = cvt_tf32(g_outf[o] + s);
}

// ---------------- host ----------------
extern "C" void kernel_launch(void* const* d_in, const int* in_sizes, int n_in,
                              void* d_out, int out_size) {
    const float* x     = (const float*)d_in[0];
    const float* w_qkv = (const float*)d_in[1];
    const float* w_out = (const float*)d_in[2];
    const float* b_out = (const float*)d_in[3];
    const float* rk    = (const float*)d_in[4];
    float* out = (float*)d_out;

    float *xt, *wqkvT, *woutT, *q, *k, *v, *ql, *kl, *a1, *a3, *a2;
    float *zA, *zB, *xz, *t1, *t2, *av, *bv, *outf;
    __nv_bfloat16 *a2h, *zhA, *zhB, *zhTA, *zhTB, *xzh, *xzhT, *t1hT, *t2hT;
    cudaGetSymbolAddress((void**)&xt, g_xt);
    cudaGetSymbolAddress((void**)&wqkvT, g_wqkvT);
    cudaGetSymbolAddress((void**)&woutT, g_woutT);
    cudaGetSymbolAddress((void**)&q,  g_q);
    cudaGetSymbolAddress((void**)&k,  g_k);
    cudaGetSymbolAddress((void**)&v,  g_v);
    cudaGetSymbolAddress((void**)&ql, g_ql);
    cudaGetSymbolAddress((void**)&kl, g_kl);
    cudaGetSymbolAddress((void**)&a1, g_attn1);
    cudaGetSymbolAddress((void**)&a3, g_attn3);
    cudaGetSymbolAddress((void**)&a2, g_attn2);
    cudaGetSymbolAddress((void**)&zA, g_zA);
    cudaGetSymbolAddress((void**)&zB, g_zB);
    cudaGetSymbolAddress((void**)&xz, g_xz);
    cudaGetSymbolAddress((void**)&t1, g_t1);
    cudaGetSymbolAddress((void**)&t2, g_t2);
    cudaGetSymbolAddress((void**)&av, g_av);
    cudaGetSymbolAddress((void**)&bv, g_bv);
    cudaGetSymbolAddress((void**)&outf, g_outf);
    cudaGetSymbolAddress((void**)&a2h,  g_a2h);
    cudaGetSymbolAddress((void**)&zhA,  g_zhA);
    cudaGetSymbolAddress((void**)&zhB,  g_zhB);
    cudaGetSymbolAddress((void**)&zhTA, g_zhTA);
    cudaGetSymbolAddress((void**)&zhTB, g_zhTB);
    cudaGetSymbolAddress((void**)&xzh,  g_xzh);
    cudaGetSymbolAddress((void**)&xzhT, g_xzhT);
    cudaGetSymbolAddress((void**)&t1hT, g_t1hT);
    cudaGetSymbolAddress((void**)&t2hT, g_t2hT);

    cudaFuncSetAttribute(pinv_mma_kernel,    cudaFuncAttributeMaxDynamicSharedMemorySize, PB_SMEM3);
    cudaFuncSetAttribute(pinv_bf16_kernel,   cudaFuncAttributeMaxDynamicSharedMemorySize, BH_SMEM3);
    cudaFuncSetAttribute(gemm_tc_kernel,     cudaFuncAttributeMaxDynamicSharedMemorySize, G128_SMEM3);
    cudaFuncSetAttribute(qkv_tc_kernel,      cudaFuncAttributeMaxDynamicSharedMemorySize, G128_SMEM3);
    cudaFuncSetAttribute(final_tc_kernel,    cudaFuncAttributeMaxDynamicSharedMemorySize, G128_SMEM3);
    cudaFuncSetAttribute(gemm64_rowB_kernel, cudaFuncAttributeMaxDynamicSharedMemorySize, G64R_SMEM3);

    // 0) layout prep
    transpose_kernel<<<dim3(NTOK/32, CDIM/32, BATCH), dim3(32,8)>>>(x, xt, CDIM, NTOK);
    transpose_kernel<<<dim3(48, 16, 1), dim3(32,8)>>>(w_qkv, wqkvT, CDIM, 3*CDIM);
    transpose_kernel<<<dim3(16, 16, 1), dim3(32,8)>>>(w_out, woutT, CDIM, CDIM);
    // 1) QKV projection
    qkv_tc_kernel<<<dim3(12, 256), 256, G128_SMEM3>>>();
    // 2) landmarks
    land_kernel<<<(BHN*ML*DH + 255)/256, 256>>>();
    // 3) similarity GEMMs
    gemm_tc_kernel<<<dim3(2, 8, BHN), 256, G128_SMEM3>>>(q,  kl, a1, DH, DH, ML,   2,
        (size_t)NTOK*DH, (size_t)ML*DH, (size_t)NTOK*ML);
    gemm_tc_kernel<<<dim3(2, 2, BHN), 256, G128_SMEM3>>>(ql, kl, a2, DH, DH, ML,   2,
        (size_t)ML*DH,   (size_t)ML*DH, (size_t)ML*ML);
    gemm_tc_kernel<<<dim3(8, 2, BHN), 256, G128_SMEM3>>>(ql, k,  a3, DH, DH, NTOK, 2,
        (size_t)ML*DH,   (size_t)NTOK*DH, (size_t)ML*NTOK);
    // 4) softmaxes
    softmax_kernel<256> <<<BHN*NTOK, 256>>>(a1);
    softmax_kernel<256> <<<BHN*ML,   256>>>(a2);
    softmax_kernel<1024><<<BHN*ML,   256>>>(a3);
    // 5) pinv init (bf16 z0 / z0^T / a2h)
    reset_max_kernel<<<1, 32>>>();
    colmax_kernel<<<(BHN*ML*32)/256, 256>>>();
    rowmax_kernel<<<(BHN*ML)/256, 256>>>();
    zinit_kernel<<<(BHN*ML*ML)/256, 256>>>();
    // 6) Newton–Schulz: iterations 1–5 in bf16 (noise contracted by the Newton map),
    //    final iteration 6 in tf32.
    __nv_bfloat16 *zh_in = zhA, *zh_out = zhB, *zhT_in = zhTA, *zhT_out = zhTB;
    for (int it = 0; it < 5; it++) {
        pinv_bf16_kernel<<<1024, 256, BH_SMEM3>>>(a2h, zhT_in, nullptr, xzh, xzhT, nullptr, 0.0f, 1.0f);
        pinv_bf16_kernel<<<1024, 256, BH_SMEM3>>>(xzh, xzhT, xzh, nullptr, t1hT, nullptr, 7.0f, -1.0f);
        pinv_bf16_kernel<<<1024, 256, BH_SMEM3>>>(xzh, t1hT, xzh, nullptr, t2hT, nullptr, 15.0f, -1.0f);
        if (it < 4) {
            pinv_bf16_kernel<<<1024, 256, BH_SMEM3>>>(zh_in, t2hT, zh_in, zh_out, zhT_out, nullptr, 3.25f, -0.25f);
            __nv_bfloat16* tmp;
            tmp = zh_in;  zh_in  = zh_out;  zh_out  = tmp;
            tmp = zhT_in; zhT_in = zhT_out; zhT_out = tmp;
        } else {
            // hand off to fp32/tf32: z5 written tf32-rounded fp32
            pinv_bf16_kernel<<<1024, 256, BH_SMEM3>>>(zh_in, t2hT, zh_in, nullptr, nullptr, zA, 3.25f, -0.25f);
        }
    }
    // one tf32 Newton–Schulz iteration (iteration 6)
    pinv_mma_kernel<<<1024, 256, PB_SMEM3>>>(a2, zA, nullptr, xz, 0.0f, 1.0f);
    pinv_mma_kernel<<<1024, 256, PB_SMEM3>>>(xz, xz, xz, t1, 7.0f, -1.0f);
    pinv_mma_kernel<<<1024, 256, PB_SMEM3>>>(xz, t1, xz, t2, 15.0f, -1.0f);
    pinv_mma_kernel<<<1024, 256, PB_SMEM3>>>(zA, t2, zA, zB, 3.25f, -0.25f);
    float* zfin = zB;
    // 7) output chain: av = attn3@v ; bv = z@av ; outf = attn1@bv
    gemm64_rowB_kernel<<<dim3(2, 1, BHN), 256, G64R_SMEM3>>>(a3, v, av,
        NTOK, 32, (size_t)ML*NTOK, (size_t)NTOK*DH, 0);
    gemm64_rowB_kernel<<<dim3(2, 1, BHN), 256, G64R_SMEM3>>>(zfin, av, bv,
        ML, 8, (size_t)ML*ML, (size_t)ML*DH, 0);
    gemm64_rowB_kernel<<<dim3(8, 1, BHN), 256, G64R_SMEM3>>>(a1, bv, outf,
        ML, 8, (size_t)NTOK*ML, (size_t)ML*DH, 1);
    // 8) depthwise conv residual
    res_add_kernel<<<BHN*256, 256>>>(rk);
    // 9) output projection + bias + transposed store
    final_tc_kernel<<<dim3(4, 256), 256, G128_SMEM3>>>(b_out, out);
}

// round 12
// speedup vs baseline: 3.9856x; 1.2051x over previous
#include <cuda_runtime.h>
#include <cuda_bf16.h>
#include <cstdint>
#include <cstddef>

#define BATCH 32
#define HEADS 8
#define NTOK 1024
#define DH 64
#define ML 256          // landmarks
#define CDIM 512
#define BHN (BATCH*HEADS)   // 256
#define KSZ 33

// ---------------- device scratch ----------------
__device__ float g_xt[(size_t)BATCH*NTOK*CDIM];     // x transposed: (b, n, c), tf32-rounded
__device__ float g_wqkvT[3*CDIM*CDIM];              // (1536, 512), tf32-rounded
__device__ float g_woutT[CDIM*CDIM];                // (512, 512), tf32-rounded
__device__ float g_q [BHN*NTOK*DH];
__device__ float g_k [BHN*NTOK*DH];
__device__ float g_v [BHN*NTOK*DH];
__device__ float g_ql[BHN*ML*DH];
__device__ float g_kl[BHN*ML*DH];
__device__ float g_attn1[(size_t)BHN*NTOK*ML];      // (bh,1024,256)
__device__ float g_attn3[(size_t)BHN*ML*NTOK];      // (bh,256,1024)
__device__ float g_attn2[BHN*ML*ML];
__device__ float g_zA[BHN*ML*ML];
__device__ float g_zB[BHN*ML*ML];
__device__ float g_xz[BHN*ML*ML];
__device__ float g_t1[BHN*ML*ML];
__device__ float g_t2[BHN*ML*ML];
__device__ float g_av[BHN*ML*DH];
__device__ float g_bv[BHN*ML*DH];
__device__ float g_outf[(size_t)BATCH*NTOK*CDIM];   // (b, n, 512)
__device__ unsigned g_colmax;
__device__ unsigned g_rowmax;
// bf16 pinv buffers
__device__ __nv_bfloat16 g_a2h [BHN*ML*ML];   // bf16(a2), row-major [M][K]
__device__ __nv_bfloat16 g_zhA [BHN*ML*ML];   // z row-major
__device__ __nv_bfloat16 g_zhB [BHN*ML*ML];
__device__ __nv_bfloat16 g_zhTA[BHN*ML*ML];   // z^T (K-major for B operand)
__device__ __nv_bfloat16 g_zhTB[BHN*ML*ML];
__device__ __nv_bfloat16 g_xzh [BHN*ML*ML];
__device__ __nv_bfloat16 g_xzhT[BHN*ML*ML];
__device__ __nv_bfloat16 g_t1hT[BHN*ML*ML];
__device__ __nv_bfloat16 g_t2hT[BHN*ML*ML];

// ================= helpers =================
__device__ __forceinline__ float cvt_tf32(float x) {
    uint32_t u;
    asm("cvt.rna.tf32.f32 %0, %1;" : "=r"(u) : "f"(x));
    return __uint_as_float(u);
}
__device__ __forceinline__ void mma_tf32_16x8x8(float c[4],
    uint32_t a0, uint32_t a1, uint32_t a2, uint32_t a3, uint32_t b0, uint32_t b1) {
    asm volatile(
        "mma.sync.aligned.m16n8k8.row.col.f32.tf32.tf32.f32 "
        "{%0,%1,%2,%3},{%4,%5,%6,%7},{%8,%9},{%0,%1,%2,%3};"
        : "+f"(c[0]), "+f"(c[1]), "+f"(c[2]), "+f"(c[3])
        : "r"(a0), "r"(a1), "r"(a2), "r"(a3), "r"(b0), "r"(b1));
}
__device__ __forceinline__ void mma_bf16_16x8x16(float c[4],
    uint32_t a0, uint32_t a1, uint32_t a2, uint32_t a3, uint32_t b0, uint32_t b1) {
    asm volatile(
        "mma.sync.aligned.m16n8k16.row.col.f32.bf16.bf16.f32 "
        "{%0,%1,%2,%3},{%4,%5,%6,%7},{%8,%9},{%0,%1,%2,%3};"
        : "+f"(c[0]), "+f"(c[1]), "+f"(c[2]), "+f"(c[3])
        : "r"(a0), "r"(a1), "r"(a2), "r"(a3), "r"(b0), "r"(b1));
}
__device__ __forceinline__ void ldsm_x4(uint32_t& r0, uint32_t& r1,
                                        uint32_t& r2, uint32_t& r3, uint32_t saddr) {
    asm volatile("ldmatrix.sync.aligned.m8n8.x4.shared.b16 {%0,%1,%2,%3}, [%4];"
                 : "=r"(r0), "=r"(r1), "=r"(r2), "=r"(r3) : "r"(saddr));
}
__device__ __forceinline__ void cp16(uint32_t dst, const void* src) {
    asm volatile("cp.async.cg.shared.global [%0], [%1], 16;" :: "r"(dst), "l"(src));
}
#define CP_COMMIT() asm volatile("cp.async.commit_group;")
#define CP_WAIT1()  asm volatile("cp.async.wait_group 1;" ::: "memory")
#define CP_WAIT0()  asm volatile("cp.async.wait_group 0;" ::: "memory")

#define PPITCH 36
#define PSTAGE (128*PPITCH)
#define G128_SMEM3 (6*PSTAGE*4)                     // 110592 (A,B both K-major fp32)

#define BNP128 136
#define BRSTG128 (32*BNP128)
#define PB_SMEM3 ((3*PSTAGE + 3*BRSTG128)*4)        // 107520

#define BNP64 72
#define BRSTG64 (32*BNP64)
#define G64R_SMEM3 ((3*PSTAGE + 3*BRSTG64)*4)       // 82944

// bf16 tiles: [128 rows][KPH halves] per chunk (32 halves data, pitch 40)
#define KPH 40
#define HSTG (128*KPH)                               // halves per stage
#define BH_SMEM3 (6*HSTG*2)                          // 61440 bytes

// ============ mainloop A: B stored K-major ([N rows][K]) — sims/qkv/final ============
__device__ __forceinline__ void mainloop128x128(
    const float* __restrict__ A, const float* __restrict__ B,
    int lda, int ldb, int kch, float* sm, int tid, float acc[4][4][4])
{
    const uint32_t sbase = (uint32_t)__cvta_generic_to_shared(sm);
    const uint32_t bbase = sbase + 3*PSTAGE*4;
    const int wid = tid >> 5, lane = tid & 31;
    const int wm = wid >> 2, wn = wid & 3;
    const int g = lane >> 3, r8 = lane & 7;
    const uint32_t a_lm = (uint32_t)((wm*64 + (g&1)*8 + r8)*PPITCH + (g>>1)*4)*4;
    const uint32_t b_lm = (uint32_t)((wn*32 + (g>>1)*8 + r8)*PPITCH + (g&1)*4)*4;
    int rrow[4], rc4[4];
    #pragma unroll
    for (int e = 0; e < 4; e++) {
        int f4 = e * 256 + tid;
        rrow[e] = f4 >> 3;
        rc4[e] = (f4 & 7) << 2;
    }
    #pragma unroll
    for (int p = 0; p < 2; p++) {
        if (p < kch) {
            const int k0 = p * 32;
            #pragma unroll
            for (int e = 0; e < 4; e++) {
                cp16(sbase + (uint32_t)(p*PSTAGE + rrow[e]*PPITCH + rc4[e])*4,
                     &A[(size_t)rrow[e] * lda + k0 + rc4[e]]);
                cp16(bbase + (uint32_t)(p*PSTAGE + rrow[e]*PPITCH + rc4[e])*4,
                     &B[(size_t)rrow[e] * ldb + k0 + rc4[e]]);
            }
        }
        CP_COMMIT();
    }
    for (int c = 0; c < kch; c++) {
        const int st = c % 3;
        if (c + 1 < kch) { CP_WAIT1(); } else { CP_WAIT0(); }
        __syncthreads();
        if (c + 2 < kch) {
            const int nst = (c + 2) % 3;
            const int k0 = (c + 2) * 32;
            #pragma unroll
            for (int e = 0; e < 4; e++) {
                cp16(sbase + (uint32_t)(nst*PSTAGE + rrow[e]*PPITCH + rc4[e])*4,
                     &A[(size_t)rrow[e] * lda + k0 + rc4[e]]);
                cp16(bbase + (uint32_t)(nst*PSTAGE + rrow[e]*PPITCH + rc4[e])*4,
                     &B[(size_t)rrow[e] * ldb + k0 + rc4[e]]);
            }
            CP_COMMIT();
        }
        const uint32_t a_st = sbase + (uint32_t)(st*PSTAGE)*4 + a_lm;
        const uint32_t b_st = bbase + (uint32_t)(st*PSTAGE)*4 + b_lm;
        #pragma unroll
        for (int ks = 0; ks < 4; ks++) {
            uint32_t af[4][4];
            #pragma unroll
            for (int mi = 0; mi < 4; mi++)
                ldsm_x4(af[mi][0], af[mi][1], af[mi][2], af[mi][3],
                        a_st + (uint32_t)(mi*16*PPITCH + ks*8)*4);
            uint32_t bf[4][2];
            #pragma unroll
            for (int p = 0; p < 2; p++)
                ldsm_x4(bf[2*p][0], bf[2*p][1], bf[2*p+1][0], bf[2*p+1][1],
                        b_st + (uint32_t)(p*16*PPITCH + ks*8)*4);
            #pragma unroll
            for (int mi = 0; mi < 4; mi++)
                #pragma unroll
                for (int ni = 0; ni < 4; ni++)
                    mma_tf32_16x8x8(acc[mi][ni],
                        af[mi][0], af[mi][1], af[mi][2], af[mi][3],
                        bf[ni][0], bf[ni][1]);
        }
    }
}

// ============ mainloop B: B stored row-major [K][N] — tf32 pinv/chain ============
__device__ __forceinline__ void mainloop128x128_rowB(
    const float* __restrict__ A, const float* __restrict__ B,
    int lda, int ldb, int kch, float* sm, int tid, float acc[4][4][4])
{
    const uint32_t sbase = (uint32_t)__cvta_generic_to_shared(sm);
    const uint32_t bbase = sbase + 3*PSTAGE*4;
    const int wid = tid >> 5, lane = tid & 31;
    const int gr = lane >> 2, gc = lane & 3;
    const int wm = wid >> 2, wn = wid & 3;
    const int g = lane >> 3, r8 = lane & 7;
    const uint32_t a_lm = (uint32_t)((wm*64 + (g&1)*8 + r8)*PPITCH + (g>>1)*4)*4;
    int arow[4], ac4[4], bk[4], bn4[4];
    #pragma unroll
    for (int e = 0; e < 4; e++) {
        int f4 = e * 256 + tid;
        arow[e] = f4 >> 3;  ac4[e] = (f4 & 7) << 2;
        bk[e]   = f4 >> 5;  bn4[e] = (f4 & 31) << 2;
    }
    #pragma unroll
    for (int p = 0; p < 2; p++) {
        if (p < kch) {
            const int k0 = p * 32;
            #pragma unroll
            for (int e = 0; e < 4; e++) {
                cp16(sbase + (uint32_t)(p*PSTAGE + arow[e]*PPITCH + ac4[e])*4,
                     &A[(size_t)arow[e] * lda + k0 + ac4[e]]);
                cp16(bbase + (uint32_t)(p*BRSTG128 + bk[e]*BNP128 + bn4[e])*4,
                     &B[(size_t)(k0 + bk[e]) * ldb + bn4[e]]);
            }
        }
        CP_COMMIT();
    }
    for (int c = 0; c < kch; c++) {
        const int st = c % 3;
        if (c + 1 < kch) { CP_WAIT1(); } else { CP_WAIT0(); }
        __syncthreads();
        if (c + 2 < kch) {
            const int nst = (c + 2) % 3;
            const int k0 = (c + 2) * 32;
            #pragma unroll
            for (int e = 0; e < 4; e++) {
                cp16(sbase + (uint32_t)(nst*PSTAGE + arow[e]*PPITCH + ac4[e])*4,
                     &A[(size_t)arow[e] * lda + k0 + ac4[e]]);
                cp16(bbase + (uint32_t)(nst*BRSTG128 + bk[e]*BNP128 + bn4[e])*4,
                     &B[(size_t)(k0 + bk[e]) * ldb + bn4[e]]);
            }
            CP_COMMIT();
        }
        const uint32_t a_st = sbase + (uint32_t)(st*PSTAGE)*4 + a_lm;
        const float* Bb = sm + 3*PSTAGE + st*BRSTG128;
        #pragma unroll
        for (int ks = 0; ks < 4; ks++) {
            uint32_t af[4][4];
            #pragma unroll
            for (int mi = 0; mi < 4; mi++)
                ldsm_x4(af[mi][0], af[mi][1], af[mi][2], af[mi][3],
                        a_st + (uint32_t)(mi*16*PPITCH + ks*8)*4);
            uint32_t bf[4][2];
            #pragma unroll
            for (int ni = 0; ni < 4; ni++) {
                int n = wn*32 + ni*8 + gr;
                bf[ni][0] = __float_as_uint(Bb[(ks*8 + gc)*BNP128 + n]);
                bf[ni][1] = __float_as_uint(Bb[(ks*8 + gc + 4)*BNP128 + n]);
            }
            #pragma unroll
            for (int mi = 0; mi < 4; mi++)
                #pragma unroll
                for (int ni = 0; ni < 4; ni++)
                    mma_tf32_16x8x8(acc[mi][ni],
                        af[mi][0], af[mi][1], af[mi][2], af[mi][3],
                        bf[ni][0], bf[ni][1]);
        }
    }
}

// ============ bf16 pinv batched GEMM: D = c1*U + c2*(A @ B^T), both K-major ============
// Outputs (each optional): Cn bf16 [M][N], Ct bf16 [N][M], Cf fp32 tf32-rounded [M][N].
__global__ void __launch_bounds__(256, 2) pinv_bf16_kernel(
    const __nv_bfloat16* __restrict__ A, const __nv_bfloat16* __restrict__ B,
    const __nv_bfloat16* __restrict__ U,
    __nv_bfloat16* __restrict__ Cn, __nv_bfloat16* __restrict__ Ct,
    float* __restrict__ Cf, float c1, float c2)
{
    extern __shared__ __nv_bfloat16 smh[];
    const uint32_t sbase = (uint32_t)__cvta_generic_to_shared(smh);
    const uint32_t bbase = sbase + 3*HSTG*2;
    const int tid = threadIdx.x;
    const int wid = tid >> 5, lane = tid & 31;
    const int wm = wid >> 2, wn = wid & 3;
    const int gr = lane >> 2, gc = lane & 3;
    const int mtx = lane >> 3, mrow = lane & 7;
    const uint32_t a_lm = ((uint32_t)(((mtx&1)*8 + mrow)) * KPH + (uint32_t)((mtx>>1)*8)) * 2;
    const uint32_t b_lm = ((uint32_t)(((mtx>>1)*8 + mrow)) * KPH + (uint32_t)((mtx&1)*8)) * 2;

    const int tile = blockIdx.x;
    const int batch = tile >> 2;
    const int m0 = ((tile >> 1) & 1) << 7;
    const int n0 = (tile & 1) << 7;
    const size_t boff = (size_t)batch << 16;
    A += boff + (size_t)m0 * ML;
    B += boff + (size_t)n0 * ML;
    if (U)  U  += boff;
    if (Cn) Cn += boff;
    if (Ct) Ct += boff;
    if (Cf) Cf += boff;

    int crow[2], cseg[2];
    #pragma unroll
    for (int e = 0; e < 2; e++) {
        int f = e * 256 + tid;
        crow[e] = f >> 2;
        cseg[e] = (f & 3) * 8;
    }

    float acc[4][4][4];
    #pragma unroll
    for (int mi = 0; mi < 4; mi++)
        #pragma unroll
        for (int ni = 0; ni < 4; ni++)
            #pragma unroll
            for (int e = 0; e < 4; e++) acc[mi][ni][e] = 0.f;

    #pragma unroll
    for (int p = 0; p < 2; p++) {
        const int k0 = p * 32;
        #pragma unroll
        for (int e = 0; e < 2; e++) {
            cp16(sbase + (uint32_t)(p*HSTG + crow[e]*KPH + cseg[e])*2,
                 &A[(size_t)crow[e] * ML + k0 + cseg[e]]);
            cp16(bbase + (uint32_t)(p*HSTG + crow[e]*KPH + cseg[e])*2,
                 &B[(size_t)crow[e] * ML + k0 + cseg[e]]);
        }
        CP_COMMIT();
    }
    for (int c = 0; c < 8; c++) {
        const int st = c % 3;
        if (c + 1 < 8) { CP_WAIT1(); } else { CP_WAIT0(); }
        __syncthreads();
        if (c + 2 < 8) {
            const int nst = (c + 2) % 3;
            const int k0 = (c + 2) * 32;
            #pragma unroll
            for (int e = 0; e < 2; e++) {
                cp16(sbase + (uint32_t)(nst*HSTG + crow[e]*KPH + cseg[e])*2,
                     &A[(size_t)crow[e] * ML + k0 + cseg[e]]);
                cp16(bbase + (uint32_t)(nst*HSTG + crow[e]*KPH + cseg[e])*2,
                     &B[(size_t)crow[e] * ML + k0 + cseg[e]]);
            }
            CP_COMMIT();
        }
        const uint32_t a_st = sbase + (uint32_t)(st*HSTG)*2 + a_lm;
        const uint32_t b_st = bbase + (uint32_t)(st*HSTG)*2 + b_lm;
        #pragma unroll
        for (int ks = 0; ks < 2; ks++) {
            uint32_t af[4][4];
            #pragma unroll
            for (int mi = 0; mi < 4; mi++)
                ldsm_x4(af[mi][0], af[mi][1], af[mi][2], af[mi][3],
                        a_st + (uint32_t)((wm*64 + mi*16)*KPH + ks*16)*2);
            uint32_t bf[4][2];
            #pragma unroll
            for (int p = 0; p < 2; p++)
                ldsm_x4(bf[2*p][0], bf[2*p][1], bf[2*p+1][0], bf[2*p+1][1],
                        b_st + (uint32_t)((wn*32 + p*16)*KPH + ks*16)*2);
            #pragma unroll
            for (int mi = 0; mi < 4; mi++)
                #pragma unroll
                for (int ni = 0; ni < 4; ni++)
                    mma_bf16_16x8x16(acc[mi][ni],
                        af[mi][0], af[mi][1], af[mi][2], af[mi][3],
                        bf[ni][0], bf[ni][1]);
        }
    }

    #pragma unroll
    for (int mi = 0; mi < 4; mi++) {
        #pragma unroll
        for (int ni = 0; ni < 4; ni++) {
            int grow = m0 + wm*64 + mi*16 + gr;
            int gcol = n0 + wn*32 + ni*8 + gc*2;
            const float* a = acc[mi][ni];
            float d0, d1, d2, d3;
            if (U) {
                __nv_bfloat162 u0 = *reinterpret_cast<const __nv_bfloat162*>(&U[(size_t)grow * ML + gcol]);
                __nv_bfloat162 u1 = *reinterpret_cast<const __nv_bfloat162*>(&U[(size_t)(grow+8) * ML + gcol]);
                d0 = c1*__bfloat162float(u0.x) + c2*a[0];
                d1 = c1*__bfloat162float(u0.y) + c2*a[1];
                d2 = c1*__bfloat162float(u1.x) + c2*a[2];
                d3 = c1*__bfloat162float(u1.y) + c2*a[3];
            } else {
                d0 = c2*a[0]; d1 = c2*a[1]; d2 = c2*a[2]; d3 = c2*a[3];
            }
            __nv_bfloat16 h0 = __float2bfloat16(d0), h1 = __float2bfloat16(d1);
            __nv_bfloat16 h2 = __float2bfloat16(d2), h3 = __float2bfloat16(d3);
            if (Cn) {
                __nv_bfloat162 p0; p0.x = h0; p0.y = h1;
                __nv_bfloat162 p1; p1.x = h2; p1.y = h3;
                *reinterpret_cast<__nv_bfloat162*>(&Cn[(size_t)grow * ML + gcol]) = p0;
                *reinterpret_cast<__nv_bfloat162*>(&Cn[(size_t)(grow+8) * ML + gcol]) = p1;
            }
            if (Ct) {
                Ct[(size_t)gcol * ML + grow]       = h0;
                Ct[(size_t)(gcol+1) * ML + grow]   = h1;
                Ct[(size_t)gcol * ML + grow+8]     = h2;
                Ct[(size_t)(gcol+1) * ML + grow+8] = h3;
            }
            if (Cf) {
                *reinterpret_cast<float2*>(&Cf[(size_t)grow * ML + gcol]) =
                    make_float2(cvt_tf32(d0), cvt_tf32(d1));
                *reinterpret_cast<float2*>(&Cf[(size_t)(grow+8) * ML + gcol]) =
                    make_float2(cvt_tf32(d2), cvt_tf32(d3));
            }
        }
    }
}

// ============ plain batched GEMM: C[z] = A[z] @ B[z]^T (B K-major; sims) ============
__global__ void __launch_bounds__(256, 2) gemm_tc_kernel(
    const float* __restrict__ A, const float* __restrict__ B, float* __restrict__ C,
    int lda, int ldb, int ldc, int kch,
    size_t sA, size_t sB, size_t sC)
{
    extern __shared__ float sm[];
    const int tid = threadIdx.x;
    const int z = blockIdx.z;
    const int m0 = blockIdx.y * 128, n0 = blockIdx.x * 128;
    A += (size_t)z * sA + (size_t)m0 * lda;
    B += (size_t)z * sB + (size_t)n0 * ldb;
    C += (size_t)z * sC;
    float acc[4][4][4];
    #pragma unroll
    for (int mi = 0; mi < 4; mi++)
        #pragma unroll
        for (int ni = 0; ni < 4; ni++)
            #pragma unroll
            for (int e = 0; e < 4; e++) acc[mi][ni][e] = 0.f;
    mainloop128x128(A, B, lda, ldb, kch, sm, tid, acc);
    const int wid = tid >> 5, lane = tid & 31;
    const int gr = lane >> 2, gc = lane & 3;
    const int wm = wid >> 2, wn = wid & 3;
    #pragma unroll
    for (int mi = 0; mi < 4; mi++) {
        #pragma unroll
        for (int ni = 0; ni < 4; ni++) {
            int lr = m0 + wm*64 + mi*16 + gr;
            int lc = n0 + wn*32 + ni*8 + gc*2;
            const float* a = acc[mi][ni];
            *reinterpret_cast<float2*>(&C[(size_t)lr * ldc + lc]) = make_float2(a[0], a[1]);
            *reinterpret_cast<float2*>(&C[(size_t)(lr+8) * ldc + lc]) = make_float2(a[2], a[3]);
        }
    }
}

// ============ QKV GEMM with scatter epilogue (tf32-rounded outputs) ============
__global__ void __launch_bounds__(256, 2) qkv_tc_kernel(void) {
    extern __shared__ float sm[];
    const int tid = threadIdx.x;
    const int m0 = blockIdx.y * 128;
    const int n0 = blockIdx.x * 128;
    const float* A = g_xt + (size_t)m0 * CDIM;
    const float* B = g_wqkvT + (size_t)n0 * CDIM;
    float acc[4][4][4];
    #pragma unroll
    for (int mi = 0; mi < 4; mi++)
        #pragma unroll
        for (int ni = 0; ni < 4; ni++)
            #pragma unroll
            for (int e = 0; e < 4; e++) acc[mi][ni][e] = 0.f;
    mainloop128x128(A, B, CDIM, CDIM, CDIM/32, sm, tid, acc);
    const int wid = tid >> 5, lane = tid & 31;
    const int gr = lane >> 2, gc = lane & 3;
    const int wm = wid >> 2, wn = wid & 3;
    #pragma unroll
    for (int mi = 0; mi < 4; mi++) {
        int m = m0 + wm*64 + mi*16 + gr;
        int b = m >> 10, i = m & 1023;
        #pragma unroll
        for (int ni = 0; ni < 4; ni++) {
            int n = n0 + wn*32 + ni*8 + gc*2;
            int which = n >> 9;
            int h = (n >> 6) & 7;
            int d = n & 63;
            int bh = b*8 + h;
            float* dst = (which == 0) ? g_q : ((which == 1) ? g_k : g_v);
            float sc = (which == 0) ? 0.125f : 1.0f;
            const float* a = acc[mi][ni];
            float r0 = cvt_tf32(a[0]*sc), r1 = cvt_tf32(a[1]*sc);
            float r2 = cvt_tf32(a[2]*sc), r3 = cvt_tf32(a[3]*sc);
            *reinterpret_cast<float2*>(&dst[((size_t)(bh*NTOK + i))*DH + d]) = make_float2(r0, r1);
            *reinterpret_cast<float2*>(&dst[((size_t)(bh*NTOK + i + 8))*DH + d]) = make_float2(r2, r3);
        }
    }
}

// ============ final GEMM: out = outf @ woutT^T + bias, transposed store (fp32) ============
__global__ void __launch_bounds__(256, 2) final_tc_kernel(
    const float* __restrict__ bias, float* __restrict__ out)
{
    extern __shared__ float sm[];
    const int tid = threadIdx.x;
    const int m0 = blockIdx.y * 128;
    const int n0 = blockIdx.x * 128;
    const float* A = g_outf + (size_t)m0 * CDIM;
    const float* B = g_woutT + (size_t)n0 * CDIM;
    float acc[4][4][4];
    #pragma unroll
    for (int mi = 0; mi < 4; mi++)
        #pragma unroll
        for (int ni = 0; ni < 4; ni++)
            #pragma unroll
            for (int e = 0; e < 4; e++) acc[mi][ni][e] = 0.f;
    mainloop128x128(A, B, CDIM, CDIM, CDIM/32, sm, tid, acc);
    const int wid = tid >> 5, lane = tid & 31;
    const int gr = lane >> 2, gc = lane & 3;
    const int wm = wid >> 2, wn = wid & 3;
    #pragma unroll
    for (int mi = 0; mi < 4; mi++) {
        int m = m0 + wm*64 + mi*16 + gr;
        int b = m >> 10, i = m & 1023;
        #pragma unroll
        for (int ni = 0; ni < 4; ni++) {
            int n = n0 + wn*32 + ni*8 + gc*2;
            const float* a = acc[mi][ni];
            float b0 = bias[n], b1 = bias[n+1];
            out[((size_t)(b*CDIM + n))*NTOK + i]       = a[0] + b0;
            out[((size_t)(b*CDIM + n + 1))*NTOK + i]   = a[1] + b1;
            out[((size_t)(b*CDIM + n))*NTOK + i + 8]   = a[2] + b0;
            out[((size_t)(b*CDIM + n + 1))*NTOK + i + 8] = a[3] + b1;
        }
    }
}

// ============ 128x64 batched GEMM, B row-major [K,64]: C = A @ B ============
__global__ void __launch_bounds__(256, 2) gemm64_rowB_kernel(
    const float* __restrict__ A, const float* __restrict__ B, float* __restrict__ C,
    int lda, int kch, size_t sA, size_t sB, int flatC)
{
    extern __shared__ float sm[];
    const uint32_t sbase = (uint32_t)__cvta_generic_to_shared(sm);
    const uint32_t bbase = sbase + 3*PSTAGE*4;
    const int tid = threadIdx.x;
    const int wid = tid >> 5, lane = tid & 31;
    const int gr = lane >> 2, gc = lane & 3;
    const int wm = wid >> 1, wn = wid & 1;
    const int g = lane >> 3, r8 = lane & 7;
    const uint32_t a_lm = (uint32_t)((wm*32 + (g&1)*8 + r8)*PPITCH + (g>>1)*4)*4;
    const int z = blockIdx.z;
    const int m0 = blockIdx.x * 128;
    A += (size_t)z * sA + (size_t)m0 * lda;
    B += (size_t)z * sB;
    if (flatC) C += (size_t)(z >> 3) * (NTOK*CDIM) + (size_t)(z & 7) * DH;
    else       C += (size_t)z * (ML*DH);

    int arow[4], ac4[4], bk[2], bn4[2];
    #pragma unroll
    for (int e = 0; e < 4; e++) {
        int f4 = e * 256 + tid;
        arow[e] = f4 >> 3;  ac4[e] = (f4 & 7) << 2;
    }
    #pragma unroll
    for (int e = 0; e < 2; e++) {
        int f4 = e * 256 + tid;
        bk[e] = f4 >> 4;  bn4[e] = (f4 & 15) << 2;
    }

    float acc[2][4][4];
    #pragma unroll
    for (int mi = 0; mi < 2; mi++)
        #pragma unroll
        for (int ni = 0; ni < 4; ni++)
            #pragma unroll
            for (int e = 0; e < 4; e++) acc[mi][ni][e] = 0.f;

    #pragma unroll
    for (int p = 0; p < 2; p++) {
        if (p < kch) {
            const int k0 = p * 32;
            #pragma unroll
            for (int e = 0; e < 4; e++)
                cp16(sbase + (uint32_t)(p*PSTAGE + arow[e]*PPITCH + ac4[e])*4,
                     &A[(size_t)arow[e] * lda + k0 + ac4[e]]);
            #pragma unroll
            for (int e = 0; e < 2; e++)
                cp16(bbase + (uint32_t)(p*BRSTG64 + bk[e]*BNP64 + bn4[e])*4,
                     &B[(size_t)(k0 + bk[e]) * DH + bn4[e]]);
        }
        CP_COMMIT();
    }

    for (int c = 0; c < kch; c++) {
        const int st = c % 3;
        if (c + 1 < kch) { CP_WAIT1(); } else { CP_WAIT0(); }
        __syncthreads();
        if (c + 2 < kch) {
            const int nst = (c + 2) % 3;
            const int k0 = (c + 2) * 32;
            #pragma unroll
            for (int e = 0; e < 4; e++)
                cp16(sbase + (uint32_t)(nst*PSTAGE + arow[e]*PPITCH + ac4[e])*4,
                     &A[(size_t)arow[e] * lda + k0 + ac4[e]]);
            #pragma unroll
            for (int e = 0; e < 2; e++)
                cp16(bbase + (uint32_t)(nst*BRSTG64 + bk[e]*BNP64 + bn4[e])*4,
                     &B[(size_t)(k0 + bk[e]) * DH + bn4[e]]);
            CP_COMMIT();
        }
        const uint32_t a_st = sbase + (uint32_t)(st*PSTAGE)*4 + a_lm;
        const float* Bb = sm + 3*PSTAGE + st*BRSTG64;
        #pragma unroll
        for (int ks = 0; ks < 4; ks++) {
            uint32_t af[2][4];
            #pragma unroll
            for (int mi = 0; mi < 2; mi++)
                ldsm_x4(af[mi][0], af[mi][1], af[mi][2], af[mi][3],
                        a_st + (uint32_t)(mi*16*PPITCH + ks*8)*4);
            uint32_t bf[4][2];
            #pragma unroll
            for (int ni = 0; ni < 4; ni++) {
                int n = wn*32 + ni*8 + gr;
                bf[ni][0] = __float_as_uint(Bb[(ks*8 + gc)*BNP64 + n]);
                bf[ni][1] = __float_as_uint(Bb[(ks*8 + gc + 4)*BNP64 + n]);
            }
            #pragma unroll
            for (int mi = 0; mi < 2; mi++)
                #pragma unroll
                for (int ni = 0; ni < 4; ni++)
                    mma_tf32_16x8x8(acc[mi][ni],
                        af[mi][0], af[mi][1], af[mi][2], af[mi][3],
                        bf[ni][0], bf[ni][1]);
        }
    }

    #pragma unroll
    for (int mi = 0; mi < 2; mi++) {
        #pragma unroll
        for (int ni = 0; ni < 4; ni++) {
            int lr = m0 + wm*32 + mi*16 + gr;
            int lc = wn*32 + ni*8 + gc*2;
            const float* a = acc[mi][ni];
            float d0 = cvt_tf32(a[0]), d1 = cvt_tf32(a[1]);
            float d2 = cvt_tf32(a[2]), d3 = cvt_tf32(a[3]);
            int ldc = flatC ? CDIM : DH;
            *reinterpret_cast<float2*>(&C[(size_t)lr * ldc + lc]) = make_float2(d0, d1);
            *reinterpret_cast<float2*>(&C[(size_t)(lr+8) * ldc + lc]) = make_float2(d2, d3);
        }
    }
}

// ---------------- batched 2D transpose (tf32-rounded output) ----------------
__global__ void transpose_kernel(const float* __restrict__ in, float* __restrict__ out,
                                 int R, int C) {
    __shared__ float tile[32][33];
    const int z = blockIdx.z;
    in  += (size_t)z * R * C;
    out += (size_t)z * R * C;
    int c0 = blockIdx.x * 32, r0 = blockIdx.y * 32;
    int tx = threadIdx.x, ty = threadIdx.y;
    #pragma unroll
    for (int j = 0; j < 4; j++)
        tile[ty + j*8][tx] = in[(size_t)(r0 + ty + j*8) * C + c0 + tx];
    __syncthreads();
    #pragma unroll
    for (int j = 0; j < 4; j++)
        out[(size_t)(c0 + ty + j*8) * R + r0 + tx] = cvt_tf32(tile[tx][ty + j*8]);
}

// ================= tf32 pinv batched GEMM: Cn = c1*U + c2*(P @ B), B row-major =================
__global__ void __launch_bounds__(256, 2) pinv_mma_kernel(
    const float* __restrict__ P, const float* __restrict__ B,
    const float* __restrict__ U, float* __restrict__ Cn,
    float c1, float c2)
{
    extern __shared__ float sm[];
    const int tid = threadIdx.x;
    const int wid = tid >> 5, lane = tid & 31;
    const int wm = wid >> 2, wn = wid & 3;
    const int gr = lane >> 2, gc = lane & 3;
    const int tile = blockIdx.x;
    const int batch = tile >> 2;
    const int m0 = ((tile >> 1) & 1) << 7;
    const int n0 = (tile & 1) << 7;
    const size_t boff = (size_t)batch << 16;
    P += boff + (size_t)m0 * ML;
    B += boff + n0;
    if (U) U += boff;
    Cn += boff;

    float acc[4][4][4];
    #pragma unroll
    for (int mi = 0; mi < 4; mi++)
        #pragma unroll
        for (int ni = 0; ni < 4; ni++)
            #pragma unroll
            for (int e = 0; e < 4; e++) acc[mi][ni][e] = 0.f;
    mainloop128x128_rowB(P, B, ML, ML, 8, sm, tid, acc);

    #pragma unroll
    for (int mi = 0; mi < 4; mi++) {
        #pragma unroll
        for (int ni = 0; ni < 4; ni++) {
            int lr = wm*64 + mi*16 + gr;
            int lc = wn*32 + ni*8 + gc*2;
            int grow = m0 + lr, gcol = n0 + lc;
            const float* a = acc[mi][ni];
            float d0, d1, d2, d3;
            if (U) {
                float2 u0 = *reinterpret_cast<const float2*>(&U[(size_t)grow * ML + gcol]);
                float2 u1 = *reinterpret_cast<const float2*>(&U[(size_t)(grow+8) * ML + gcol]);
                d0 = c1*u0.x + c2*a[0]; d1 = c1*u0.y + c2*a[1];
                d2 = c1*u1.x + c2*a[2]; d3 = c1*u1.y + c2*a[3];
            } else {
                d0 = c2*a[0]; d1 = c2*a[1]; d2 = c2*a[2]; d3 = c2*a[3];
            }
            d0 = cvt_tf32(d0); d1 = cvt_tf32(d1); d2 = cvt_tf32(d2); d3 = cvt_tf32(d3);
            *reinterpret_cast<float2*>(&Cn[(size_t)grow * ML + gcol]) = make_float2(d0, d1);
            *reinterpret_cast<float2*>(&Cn[(size_t)(grow+8) * ML + gcol]) = make_float2(d2, d3);
        }
    }
}

// ---------------- landmark means (tf32-rounded) ----------------
__global__ void land_kernel() {
    int idx = blockIdx.x * blockDim.x + threadIdx.x;
    if (idx >= BHN*ML*DH) return;
    int d  = idx & 63;
    int j  = (idx >> 6) & 255;
    int bh = idx >> 14;
    size_t base = ((size_t)bh * NTOK + j*4) * DH + d;
    g_ql[idx] = cvt_tf32(0.25f * (g_q[base] + g_q[base+64] + g_q[base+128] + g_q[base+192]));
    g_kl[idx] = cvt_tf32(0.25f * (g_k[base] + g_k[base+64] + g_k[base+128] + g_k[base+192]));
}

// ---------------- warp-per-row softmax: fast exp, zero block barriers ----------------
// 256 threads = 8 warps, one row per warp. tf32-rounded output.
template<int W>
__global__ void softmax_warp_kernel(float* __restrict__ data) {
    const int lane = threadIdx.x & 31;
    const int row = blockIdx.x * 8 + (threadIdx.x >> 5);
    float* r = data + (size_t)row * W;
    constexpr int PE = W / 32;
    float v[PE];
    float mx = -1e30f;
    #pragma unroll
    for (int e = 0; e < PE; e++) { v[e] = r[lane + e*32]; mx = fmaxf(mx, v[e]); }
    #pragma unroll
    for (int o = 16; o > 0; o >>= 1) mx = fmaxf(mx, __shfl_xor_sync(0xffffffffu, mx, o));
    float s = 0.f;
    #pragma unroll
    for (int e = 0; e < PE; e++) { v[e] = __expf(v[e] - mx); s += v[e]; }
    #pragma unroll
    for (int o = 16; o > 0; o >>= 1) s += __shfl_xor_sync(0xffffffffu, s, o);
    float inv = 1.0f / s;
    #pragma unroll
    for (int e = 0; e < PE; e++) r[lane + e*32] = cvt_tf32(v[e] * inv);
}

// ---------------- pinv scale reductions ----------------
__global__ void reset_max_kernel() { if (threadIdx.x == 0) { g_colmax = 0u; g_rowmax = 0u; } }

__global__ void colmax_kernel() {
    int gw = (blockIdx.x * blockDim.x + threadIdx.x) >> 5;
    int lane = threadIdx.x & 31;
    if (gw >= BHN * ML) return;
    const float* row = g_attn2 + (size_t)gw * ML;
    float s = 0.f;
    #pragma unroll
    for (int j = lane; j < ML; j += 32) s += fabsf(row[j]);
    #pragma unroll
    for (int o = 16; o > 0; o >>= 1) s += __shfl_down_sync(0xffffffffu, s, o);
    if (lane == 0) atomicMax(&g_colmax, __float_as_uint(s));
}

__global__ void rowmax_kernel() {
    int idx = blockIdx.x * blockDim.x + threadIdx.x;
    if (idx >= BHN * ML) return;
    int bh = idx >> 8, j = idx & 255;
    const float* base = g_attn2 + (size_t)bh * ML * ML + j;
    float s = 0.f;
    for (int i = 0; i < ML; i++) s += fabsf(base[(size_t)i * ML]);
    atomicMax(&g_rowmax, __float_as_uint(s));
}

// zinit: z0 (bf16, row + transposed) and a2h (bf16 of a2)
__global__ void zinit_kernel() {
    float inv = 1.0f / (__uint_as_float(g_colmax) * __uint_as_float(g_rowmax));
    size_t idx = (size_t)blockIdx.x * 256 + threadIdx.x;
    int j  = idx & 255;
    int i  = (idx >> 8) & 255;
    size_t bh = idx >> 16;
    float a2v  = g_attn2[idx];
    float a2tv = g_attn2[(bh << 16) + ((size_t)j << 8) + i];
    g_zhA[idx]  = __float2bfloat16(a2tv * inv);   // z0 row-major = scaled x^T
    g_zhTA[idx] = __float2bfloat16(a2v * inv);    // z0^T = scaled x
    g_a2h[idx]  = __float2bfloat16(a2v);
}

// ---------------- depthwise 33-tap conv residual (tf32-rounded add) ----------------
__global__ void res_add_kernel(const float* __restrict__ rk) {
    __shared__ float ker[KSZ];
    int blk = blockIdx.x;
    int bh = blk >> 8;
    int ichunk = blk & 255;
    int h = bh & 7, b = bh >> 3;
    if (threadIdx.x < KSZ) ker[threadIdx.x] = rk[h*KSZ + threadIdx.x];
    __syncthreads();
    int d = threadIdx.x & 63;
    int i = ichunk * 4 + (threadIdx.x >> 6);
    const float* vb = g_v + (size_t)bh * NTOK * DH;
    float s = 0.f;
    #pragma unroll
    for (int t = 0; t < KSZ; t++) {
        int ii = i + t - (KSZ/2);
        if (ii >= 0 && ii < NTOK) s += ker[t] * vb[(size_t)ii * DH + d];
    }
    size_t o = ((size_t)(b*NTOK + i)) * CDIM + h*64 + d;
    g_outf[o] = cvt_tf32(g_outf[o] + s);
}

// ---------------- host ----------------
extern "C" void kernel_launch(void* const* d_in, const int* in_sizes, int n_in,
                              void* d_out, int out_size) {
    const float* x     = (const float*)d_in[0];
    const float* w_qkv = (const float*)d_in[1];
    const float* w_out = (const float*)d_in[2];
    const float* b_out = (const float*)d_in[3];
    const float* rk    = (const float*)d_in[4];
    float* out = (float*)d_out;

    float *xt, *wqkvT, *woutT, *q, *k, *v, *ql, *kl, *a1, *a3, *a2;
    float *zA, *zB, *xz, *t1, *t2, *av, *bv, *outf;
    __nv_bfloat16 *a2h, *zhA, *zhB, *zhTA, *zhTB, *xzh, *xzhT, *t1hT, *t2hT;
    cudaGetSymbolAddress((void**)&xt, g_xt);
    cudaGetSymbolAddress((void**)&wqkvT, g_wqkvT);
    cudaGetSymbolAddress((void**)&woutT, g_woutT);
    cudaGetSymbolAddress((void**)&q,  g_q);
    cudaGetSymbolAddress((void**)&k,  g_k);
    cudaGetSymbolAddress((void**)&v,  g_v);
    cudaGetSymbolAddress((void**)&ql, g_ql);
    cudaGetSymbolAddress((void**)&kl, g_kl);
    cudaGetSymbolAddress((void**)&a1, g_attn1);
    cudaGetSymbolAddress((void**)&a3, g_attn3);
    cudaGetSymbolAddress((void**)&a2, g_attn2);
    cudaGetSymbolAddress((void**)&zA, g_zA);
    cudaGetSymbolAddress((void**)&zB, g_zB);
    cudaGetSymbolAddress((void**)&xz, g_xz);
    cudaGetSymbolAddress((void**)&t1, g_t1);
    cudaGetSymbolAddress((void**)&t2, g_t2);
    cudaGetSymbolAddress((void**)&av, g_av);
    cudaGetSymbolAddress((void**)&bv, g_bv);
    cudaGetSymbolAddress((void**)&outf, g_outf);
    cudaGetSymbolAddress((void**)&a2h,  g_a2h);
    cudaGetSymbolAddress((void**)&zhA,  g_zhA);
    cudaGetSymbolAddress((void**)&zhB,  g_zhB);
    cudaGetSymbolAddress((void**)&zhTA, g_zhTA);
    cudaGetSymbolAddress((void**)&zhTB, g_zhTB);
    cudaGetSymbolAddress((void**)&xzh,  g_xzh);
    cudaGetSymbolAddress((void**)&xzhT, g_xzhT);
    cudaGetSymbolAddress((void**)&t1hT, g_t1hT);
    cudaGetSymbolAddress((void**)&t2hT, g_t2hT);

    cudaFuncSetAttribute(pinv_mma_kernel,    cudaFuncAttributeMaxDynamicSharedMemorySize, PB_SMEM3);
    cudaFuncSetAttribute(pinv_bf16_kernel,   cudaFuncAttributeMaxDynamicSharedMemorySize, BH_SMEM3);
    cudaFuncSetAttribute(gemm_tc_kernel,     cudaFuncAttributeMaxDynamicSharedMemorySize, G128_SMEM3);
    cudaFuncSetAttribute(qkv_tc_kernel,      cudaFuncAttributeMaxDynamicSharedMemorySize, G128_SMEM3);
    cudaFuncSetAttribute(final_tc_kernel,    cudaFuncAttributeMaxDynamicSharedMemorySize, G128_SMEM3);
    cudaFuncSetAttribute(gemm64_rowB_kernel, cudaFuncAttributeMaxDynamicSharedMemorySize, G64R_SMEM3);

    // 0) layout prep
    transpose_kernel<<<dim3(NTOK/32, CDIM/32, BATCH), dim3(32,8)>>>(x, xt, CDIM, NTOK);
    transpose_kernel<<<dim3(48, 16, 1), dim3(32,8)>>>(w_qkv, wqkvT, CDIM, 3*CDIM);
    transpose_kernel<<<dim3(16, 16, 1), dim3(32,8)>>>(w_out, woutT, CDIM, CDIM);
    // 1) QKV projection
    qkv_tc_kernel<<<dim3(12, 256), 256, G128_SMEM3>>>();
    // 2) landmarks
    land_kernel<<<(BHN*ML*DH + 255)/256, 256>>>();
    // 3) similarity GEMMs
    gemm_tc_kernel<<<dim3(2, 8, BHN), 256, G128_SMEM3>>>(q,  kl, a1, DH, DH, ML,   2,
        (size_t)NTOK*DH, (size_t)ML*DH, (size_t)NTOK*ML);
    gemm_tc_kernel<<<dim3(2, 2, BHN), 256, G128_SMEM3>>>(ql, kl, a2, DH, DH, ML,   2,
        (size_t)ML*DH,   (size_t)ML*DH, (size_t)ML*ML);
    gemm_tc_kernel<<<dim3(8, 2, BHN), 256, G128_SMEM3>>>(ql, k,  a3, DH, DH, NTOK, 2,
        (size_t)ML*DH,   (size_t)NTOK*DH, (size_t)ML*NTOK);
    // 4) softmaxes — warp-per-row, fast exp
    softmax_warp_kernel<256> <<<BHN*NTOK/8, 256>>>(a1);
    softmax_warp_kernel<256> <<<BHN*ML/8,   256>>>(a2);
    softmax_warp_kernel<1024><<<BHN*ML/8,   256>>>(a3);
    // 5) pinv init (bf16 z0 / z0^T / a2h)
    reset_max_kernel<<<1, 32>>>();
    colmax_kernel<<<(BHN*ML*32)/256, 256>>>();
    rowmax_kernel<<<(BHN*ML)/256, 256>>>();
    zinit_kernel<<<(BHN*ML*ML)/256, 256>>>();
    // 6) Newton–Schulz: iterations 1–5 in bf16, iteration 6 in tf32
    __nv_bfloat16 *zh_in = zhA, *zh_out = zhB, *zhT_in = zhTA, *zhT_out = zhTB;
    for (int it = 0; it < 5; it++) {
        pinv_bf16_kernel<<<1024, 256, BH_SMEM3>>>(a2h, zhT_in, nullptr, xzh, xzhT, nullptr, 0.0f, 1.0f);
        pinv_bf16_kernel<<<1024, 256, BH_SMEM3>>>(xzh, xzhT, xzh, nullptr, t1hT, nullptr, 7.0f, -1.0f);
        pinv_bf16_kernel<<<1024, 256, BH_SMEM3>>>(xzh, t1hT, xzh, nullptr, t2hT, nullptr, 15.0f, -1.0f);
        if (it < 4) {
            pinv_bf16_kernel<<<1024, 256, BH_SMEM3>>>(zh_in, t2hT, zh_in, zh_out, zhT_out, nullptr, 3.25f, -0.25f);
            __nv_bfloat16* tmp;
            tmp = zh_in;  zh_in  = zh_out;  zh_out  = tmp;
            tmp = zhT_in; zhT_in = zhT_out; zhT_out = tmp;
        } else {
            pinv_bf16_kernel<<<1024, 256, BH_SMEM3>>>(zh_in, t2hT, zh_in, nullptr, nullptr, zA, 3.25f, -0.25f);
        }
    }
    pinv_mma_kernel<<<1024, 256, PB_SMEM3>>>(a2, zA, nullptr, xz, 0.0f, 1.0f);
    pinv_mma_kernel<<<1024, 256, PB_SMEM3>>>(xz, xz, xz, t1, 7.0f, -1.0f);
    pinv_mma_kernel<<<1024, 256, PB_SMEM3>>>(xz, t1, xz, t2, 15.0f, -1.0f);
    pinv_mma_kernel<<<1024, 256, PB_SMEM3>>>(zA, t2, zA, zB, 3.25f, -0.25f);
    float* zfin = zB;
    // 7) output chain: av = attn3@v ; bv = z@av ; outf = attn1@bv
    gemm64_rowB_kernel<<<dim3(2, 1, BHN), 256, G64R_SMEM3>>>(a3, v, av,
        NTOK, 32, (size_t)ML*NTOK, (size_t)NTOK*DH, 0);
    gemm64_rowB_kernel<<<dim3(2, 1, BHN), 256, G64R_SMEM3>>>(zfin, av, bv,
        ML, 8, (size_t)ML*ML, (size_t)ML*DH, 0);
    gemm64_rowB_kernel<<<dim3(8, 1, BHN), 256, G64R_SMEM3>>>(a1, bv, outf,
        ML, 8, (size_t)NTOK*ML, (size_t)ML*DH, 1);
    // 8) depthwise conv residual
    res_add_kernel<<<BHN*256, 256>>>(rk);
    // 9) output projection + bias + transposed store
    final_tc_kernel<<<dim3(4, 256), 256, G128_SMEM3>>>(b_out, out);
}